// round 7
// baseline (speedup 1.0000x reference)
#include <cuda_runtime.h>
#include <cstdint>
#include <cstddef>

#define HH 128
#define WW 128
#define HW 16384
#define BB 4

// ---------------- scratch (static device globals; no allocation) ----------------
__device__ float g_multi[(size_t)BB * 768 * HW];    // qkv (0..383) + ms (384..767)
__device__ float g_att[(size_t)BB * 256 * HW];      // attention output
__device__ float g_attended[(size_t)BB * 128 * HW]; // residual branch point
__device__ float g_h1[(size_t)BB * 768 * HW];       // mb1 output
__device__ float g_h2[(size_t)BB * 768 * HW];       // mb2 output
__device__ float g_kv[(size_t)BB * 32 * 72];        // per-(b,g) 9x8 kv matrices
__device__ float g_wT[768 * 1152];                  // fragment-packed weights (float4 view)

// fragment-region offsets in float4 units
#define FQ 0
#define FK 36864
#define FV 73728
#define FP 110592
#define F1 118784
#define F3 143360

// ---------------- tf32 helpers ----------------
__device__ __forceinline__ float f2tf32f(float f) {
    uint32_t u;
    asm("cvt.rna.tf32.f32 %0, %1;" : "=r"(u) : "f"(f));
    return __uint_as_float(u);
}

__device__ __forceinline__ void mma_tf32(float& d0, float& d1, float& d2, float& d3,
                                         uint32_t a0, uint32_t a1, uint32_t a2, uint32_t a3,
                                         uint32_t b0, uint32_t b1) {
    asm volatile(
        "mma.sync.aligned.m16n8k8.row.col.f32.tf32.tf32.f32 "
        "{%0,%1,%2,%3},{%4,%5,%6,%7},{%8,%9},{%0,%1,%2,%3};"
        : "+f"(d0), "+f"(d1), "+f"(d2), "+f"(d3)
        : "r"(a0), "r"(a1), "r"(a2), "r"(a3), "r"(b0), "r"(b1));
}

__device__ __forceinline__ float hswish_f(float x) {
    return x * fminf(fmaxf(x + 3.f, 0.f), 6.f) * (1.f / 6.f);
}

// ---------------- prep: conv weights -> fragment-packed tf32 float4 ----------------
// out layout: [cb2][c08][rs][w2][mi][lane], one float4 = (a0,a1,a2,a3) of the mma A-fragment.
// w layout: [co][ci][3][3] (co,ci = 128).
__global__ void prep_conv_frag(const float* __restrict__ w, float4* __restrict__ out) {
    int j = blockIdx.x * 256 + threadIdx.x;   // 0..36863
    int lane = j & 31, mi = (j >> 5) & 1, w2 = (j >> 6) & 1;
    int r3 = j >> 7;
    int rs = r3 % 9;
    int tmp = r3 / 9;
    int c08 = tmp & 15;
    int cb2 = tmp >> 4;
    int g = lane >> 2, t = lane & 3;
    int m = cb2 * 64 + w2 * 32 + mi * 16 + g;
    int k = c08 * 8 + t;
    float e0 = w[(size_t)m * 1152 + k * 9 + rs];
    float e1 = w[(size_t)(m + 8) * 1152 + k * 9 + rs];
    float e2 = w[(size_t)m * 1152 + (k + 4) * 9 + rs];
    float e3 = w[(size_t)(m + 8) * 1152 + (k + 4) * 9 + rs];
    out[j] = make_float4(f2tf32f(e0), f2tf32f(e1), f2tf32f(e2), f2tf32f(e3));
}

// ---------------- prep: 1x1 weights -> fragment-packed tf32 float4 ----------------
// out layout: [cb][k016][ks][w2][mi][lane].  w layout: [Cout][Cin].
__global__ void prep_gemm_frag(const float* __restrict__ w, float4* __restrict__ out,
                               int Cin, int Cout) {
    int j = blockIdx.x * 256 + threadIdx.x;
    if (j >= (Cin * Cout) / 4) return;
    int lane = j & 31, mi = (j >> 5) & 1, w2 = (j >> 6) & 1, ks = (j >> 7) & 1;
    int rest = j >> 8;
    int nk = Cin >> 4;
    int k016 = rest % nk;
    int cb = rest / nk;
    int g = lane >> 2, t = lane & 3;
    int co = cb * 64 + w2 * 32 + mi * 16 + g;
    int k = k016 * 16 + ks * 8 + t;
    float e0 = w[(size_t)co * Cin + k];
    float e1 = w[(size_t)(co + 8) * Cin + k];
    float e2 = w[(size_t)co * Cin + k + 4];
    float e3 = w[(size_t)(co + 8) * Cin + k + 4];
    out[j] = make_float4(f2tf32f(e0), f2tf32f(e1), f2tf32f(e2), f2tf32f(e3));
}

// ---------------- fused 3x3 convs (q,k,v) via tf32 tensor cores ----------------
// blockIdx.y in [0,6): cv = y>>1 (0=q on ref, 1=k, 2=v on oth), cb2 = y&1.
__global__ void conv3x3_tc(const float* __restrict__ ref, const float* __restrict__ oth,
                           const float4* __restrict__ wfragAll,
                           const float* __restrict__ bq, const float* __restrict__ bk,
                           const float* __restrict__ bv, float* __restrict__ out) {
    __shared__ float4 Afrag[1152];      // [rs][w2][mi][lane]
    __shared__ float Ish[8][3][136];    // [cin8][row3][col(-1..128)]
    int tid = threadIdx.x;
    int lane = tid & 31, warp = tid >> 5;
    int g = lane >> 2, t = lane & 3;
    int w2 = warp >> 2;                 // 0/1 (wm = w2*32)
    int wn = (warp & 3) * 32;
    int y = blockIdx.x;
    int cv = blockIdx.y >> 1;
    int cb2 = blockIdx.y & 1;
    int cbase = cb2 * 64;
    int b = blockIdx.z;
    const float* in = (cv == 0) ? ref : oth;
    const float4* wf = wfragAll + (size_t)(cv * 2 + cb2) * 16 * 1152;
    const float* bias = (cv == 0) ? bq : (cv == 1) ? bk : bv;
    int outOff = cv * 128;
    const float* inB = in + (size_t)b * 128 * HW;
    float acc[2][4][4] = {};

    for (int c08 = 0; c08 < 16; c08++) {
        int c0 = c08 * 8;
        __syncthreads();
        // weight fragments: coalesced float4 copy, already tf32
        for (int j = tid; j < 1152; j += 256)
            Afrag[j] = wf[c08 * 1152 + j];
        // input patch: warp w handles channel c=w, 3 rows, 130 cols
        {
            const float* inC = inB + (size_t)(c0 + warp) * HW;
#pragma unroll
            for (int r = 0; r < 3; r++) {
                int yy = y - 1 + r;
                for (int col = lane; col < 130; col += 32) {
                    int xx = col - 1;
                    float v = 0.f;
                    if (xx >= 0 && xx < WW && yy >= 0 && yy < HH)
                        v = inC[yy * WW + xx];
                    Ish[warp][r][col] = f2tf32f(v);
                }
            }
        }
        __syncthreads();
#pragma unroll
        for (int r = 0; r < 3; r++) {
#pragma unroll
            for (int s = 0; s < 3; s++) {
                int rs = r * 3 + s;
                uint32_t a[2][4];
#pragma unroll
                for (int mi = 0; mi < 2; mi++) {
                    float4 af = Afrag[((rs * 2 + w2) * 2 + mi) * 32 + lane];
                    a[mi][0] = __float_as_uint(af.x);
                    a[mi][1] = __float_as_uint(af.y);
                    a[mi][2] = __float_as_uint(af.z);
                    a[mi][3] = __float_as_uint(af.w);
                }
#pragma unroll
                for (int ni = 0; ni < 4; ni++) {
                    uint32_t b0 = __float_as_uint(Ish[t][r][wn + ni * 8 + g + s]);
                    uint32_t b1 = __float_as_uint(Ish[t + 4][r][wn + ni * 8 + g + s]);
#pragma unroll
                    for (int mi = 0; mi < 2; mi++)
                        mma_tf32(acc[mi][ni][0], acc[mi][ni][1], acc[mi][ni][2], acc[mi][ni][3],
                                 a[mi][0], a[mi][1], a[mi][2], a[mi][3], b0, b1);
                }
            }
        }
    }
#pragma unroll
    for (int mi = 0; mi < 2; mi++) {
        int co0 = cbase + w2 * 32 + mi * 16 + g;
        int co1 = co0 + 8;
        float bv0 = bias[co0], bv1 = bias[co1];
        float* p0 = out + ((size_t)b * 768 + outOff + co0) * HW + y * WW;
        float* p1 = out + ((size_t)b * 768 + outOff + co1) * HW + y * WW;
#pragma unroll
        for (int ni = 0; ni < 4; ni++) {
            int x0 = wn + ni * 8 + 2 * t;
            *(float2*)&p0[x0] = make_float2(acc[mi][ni][0] + bv0, acc[mi][ni][1] + bv0);
            *(float2*)&p1[x0] = make_float2(acc[mi][ni][2] + bv1, acc[mi][ni][3] + bv1);
        }
    }
}

// ---------------- 1x1 conv (GEMM) via tf32 tensor cores, fragment-packed weights ----------------
template <int MODE>
__global__ void gemm1x1_tc(const float* __restrict__ in, int Cin,
                           const float4* __restrict__ wfrag, int Cout,
                           const float* __restrict__ p0, const float* __restrict__ p1,
                           const float* __restrict__ p2, const float* __restrict__ p3,
                           const float* __restrict__ res, float* __restrict__ out) {
    __shared__ float4 Af[256];          // [ks][w2][mi][lane]
    __shared__ float Ish[16][136];
    int tid = threadIdx.x;
    int lane = tid & 31, warp = tid >> 5;
    int g = lane >> 2, t = lane & 3;
    int w2 = warp >> 2;
    int wn = (warp & 3) * 32;
    int nbase = blockIdx.x * 128;
    int cb = blockIdx.y;
    int b = blockIdx.z;
    int nk = Cin >> 4;
    const float* inB = in + (size_t)b * Cin * HW + nbase;
    float acc[2][4][4] = {};

    for (int k016 = 0; k016 < nk; k016++) {
        int k0 = k016 * 16;
        __syncthreads();
        Af[tid] = wfrag[((size_t)cb * nk + k016) * 256 + tid];
        {
            int k2 = tid >> 5, p2i = tid & 31;
            float4 iv = *(const float4*)&inB[(size_t)(k0 + k2) * HW + p2i * 4];
            iv.x = f2tf32f(iv.x); iv.y = f2tf32f(iv.y);
            iv.z = f2tf32f(iv.z); iv.w = f2tf32f(iv.w);
            *(float4*)&Ish[k2][p2i * 4] = iv;
            float4 iv2 = *(const float4*)&inB[(size_t)(k0 + k2 + 8) * HW + p2i * 4];
            iv2.x = f2tf32f(iv2.x); iv2.y = f2tf32f(iv2.y);
            iv2.z = f2tf32f(iv2.z); iv2.w = f2tf32f(iv2.w);
            *(float4*)&Ish[k2 + 8][p2i * 4] = iv2;
        }
        __syncthreads();
#pragma unroll
        for (int ks = 0; ks < 2; ks++) {
            int kb = ks * 8;
            uint32_t a[2][4];
#pragma unroll
            for (int mi = 0; mi < 2; mi++) {
                float4 af = Af[((ks * 2 + w2) * 2 + mi) * 32 + lane];
                a[mi][0] = __float_as_uint(af.x);
                a[mi][1] = __float_as_uint(af.y);
                a[mi][2] = __float_as_uint(af.z);
                a[mi][3] = __float_as_uint(af.w);
            }
#pragma unroll
            for (int ni = 0; ni < 4; ni++) {
                uint32_t b0 = __float_as_uint(Ish[kb + t][wn + ni * 8 + g]);
                uint32_t b1 = __float_as_uint(Ish[kb + t + 4][wn + ni * 8 + g]);
#pragma unroll
                for (int mi = 0; mi < 2; mi++)
                    mma_tf32(acc[mi][ni][0], acc[mi][ni][1], acc[mi][ni][2], acc[mi][ni][3],
                             a[mi][0], a[mi][1], a[mi][2], a[mi][3], b0, b1);
            }
        }
    }
    // epilogue
#pragma unroll
    for (int mi = 0; mi < 2; mi++) {
        int co0 = cb * 64 + w2 * 32 + mi * 16 + g;
        int co1 = co0 + 8;
        float b0v = 0.f, b1v = 0.f, sc0 = 0.f, sc1 = 0.f, sh0 = 0.f, sh1 = 0.f;
        if (MODE == 0) {
            b0v = p0[co0];
            b1v = p0[co1];
        } else {
            sc0 = p0[co0] * rsqrtf(p3[co0] + 1e-5f);
            sh0 = p1[co0] - p2[co0] * sc0;
            sc1 = p0[co1] * rsqrtf(p3[co1] + 1e-5f);
            sh1 = p1[co1] - p2[co1] * sc1;
        }
        size_t row0 = ((size_t)b * Cout + co0) * HW + nbase;
        size_t row1 = ((size_t)b * Cout + co1) * HW + nbase;
#pragma unroll
        for (int ni = 0; ni < 4; ni++) {
            int x0 = wn + ni * 8 + 2 * t;
            float v00 = acc[mi][ni][0], v01 = acc[mi][ni][1];
            float v10 = acc[mi][ni][2], v11 = acc[mi][ni][3];
            if (MODE == 0) {
                v00 = hswish_f(v00 + b0v);
                v01 = hswish_f(v01 + b0v);
                v10 = hswish_f(v10 + b1v);
                v11 = hswish_f(v11 + b1v);
            } else {
                float2 r0 = *(const float2*)&res[row0 + x0];
                float2 r1 = *(const float2*)&res[row1 + x0];
                v00 = v00 * sc0 + sh0 + r0.x;
                v01 = v01 * sc0 + sh0 + r0.y;
                v10 = v10 * sc1 + sh1 + r1.x;
                v11 = v11 * sc1 + sh1 + r1.y;
            }
            *(float2*)&out[row0 + x0] = make_float2(v00, v01);
            *(float2*)&out[row1 + x0] = make_float2(v10, v11);
        }
    }
}

// ---------------- fused 5x5 depthwise + grouped 1x1 (one group of 8 ch, 4 rows) ----------------
__global__ void dwpw_k(const float* __restrict__ in, const float* __restrict__ dw_w,
                       const float* __restrict__ pw_w, float* __restrict__ out) {
    __shared__ float sh[8][8][136];   // [ch][row y0-2..y0+5][col -2..129]
    __shared__ float wsh[8][25];
    __shared__ float psh[64];
    int tid = threadIdx.x;
    int g = blockIdx.y, b = blockIdx.z;
    int y0 = blockIdx.x * 4;
    int warp = tid >> 5, lane = tid & 31;
    const float* inG = in + ((size_t)b * 768 + g * 8) * HW;

    if (tid < 200) wsh[tid / 25][tid % 25] = dw_w[(g * 8 + tid / 25) * 25 + tid % 25];
    else if (tid >= 224 && tid < 288 - 0) { /* nothing */ }
    if (tid < 64) psh[tid] = pw_w[g * 64 + tid];

    {
        const float* inC = inG + (size_t)warp * HW;
#pragma unroll
        for (int rr = 0; rr < 8; rr++) {
            int yy = y0 - 2 + rr;
            for (int col = lane; col < 132; col += 32) {
                int xx = col - 2;
                float v = 0.f;
                if (yy >= 0 && yy < HH && xx >= 0 && xx < WW) v = inC[yy * WW + xx];
                sh[warp][rr][col] = v;
            }
        }
    }
    __syncthreads();

#pragma unroll
    for (int p = 0; p < 2; p++) {
        int px = tid + p * 256;
        int ry = px >> 7, x = px & 127;
        float d[8];
#pragma unroll
        for (int c = 0; c < 8; c++) {
            float a = 0.f;
#pragma unroll
            for (int r = 0; r < 5; r++)
#pragma unroll
                for (int s = 0; s < 5; s++)
                    a += wsh[c][r * 5 + s] * sh[c][ry + r][x + s];
            d[c] = a;
        }
        float* op = out + ((size_t)b * 768 + 384 + g * 8) * HW + (y0 + ry) * WW + x;
#pragma unroll
        for (int o = 0; o < 8; o++) {
            float a = 0.f;
#pragma unroll
            for (int i = 0; i < 8; i++) a += psh[o * 8 + i] * d[i];
            op[(size_t)o * HW] = a;
        }
    }
}

// ---------------- zero kv accumulators ----------------
__global__ void zero_kv_k(float* __restrict__ kv) {
    int i = blockIdx.x * 256 + threadIdx.x;
    if (i < BB * 32 * 72) kv[i] = 0.f;
}

// ---------------- attention phase 1 ----------------
__global__ void attn_kv_k(const float* __restrict__ multi, float* __restrict__ kv) {
    int b = blockIdx.z, g = blockIdx.y;
    const float* base = multi + ((size_t)b * 768 + g * 24) * HW;
    int n0 = blockIdx.x * 2048;
    float acc[72];
#pragma unroll
    for (int i = 0; i < 72; i++) acc[i] = 0.f;
    for (int n = n0 + threadIdx.x; n < n0 + 2048; n += 256) {
        float kq[8], vv[8];
#pragma unroll
        for (int j = 0; j < 8; j++) kq[j] = fmaxf(base[(size_t)(8 + j) * HW + n], 0.f);
#pragma unroll
        for (int e = 0; e < 8; e++) vv[e] = base[(size_t)(16 + e) * HW + n];
#pragma unroll
        for (int e = 0; e < 8; e++)
#pragma unroll
            for (int j = 0; j < 8; j++) acc[e * 8 + j] += vv[e] * kq[j];
#pragma unroll
        for (int j = 0; j < 8; j++) acc[64 + j] += kq[j];
    }
    __shared__ float red[72][8];
    int lane = threadIdx.x & 31, warp = threadIdx.x >> 5;
#pragma unroll
    for (int i = 0; i < 72; i++) {
        float v = acc[i];
        v += __shfl_down_sync(0xffffffffu, v, 16);
        v += __shfl_down_sync(0xffffffffu, v, 8);
        v += __shfl_down_sync(0xffffffffu, v, 4);
        v += __shfl_down_sync(0xffffffffu, v, 2);
        v += __shfl_down_sync(0xffffffffu, v, 1);
        if (lane == 0) red[i][warp] = v;
    }
    __syncthreads();
    if (threadIdx.x < 72) {
        float s = 0.f;
#pragma unroll
        for (int w = 0; w < 8; w++) s += red[threadIdx.x][w];
        atomicAdd(&kv[((size_t)b * 32 + g) * 72 + threadIdx.x], s);
    }
}

// ---------------- attention phase 2 ----------------
__global__ void attn_apply_k(const float* __restrict__ multi, const float* __restrict__ kv,
                             float* __restrict__ att) {
    int b = blockIdx.z, g = blockIdx.y;
    __shared__ float kvs[72];
    if (threadIdx.x < 72) kvs[threadIdx.x] = kv[((size_t)b * 32 + g) * 72 + threadIdx.x];
    __syncthreads();
    int n = blockIdx.x * 256 + threadIdx.x;
    const float* base = multi + ((size_t)b * 768 + g * 24) * HW + n;
    float q[8];
#pragma unroll
    for (int j = 0; j < 8; j++) q[j] = fmaxf(base[(size_t)j * HW], 0.f);
    float denom = 0.f;
#pragma unroll
    for (int j = 0; j < 8; j++) denom += kvs[64 + j] * q[j];
    float inv = 1.f / (denom + 1e-15f);
    float* op = att + ((size_t)b * 256 + g * 8) * HW + n;
#pragma unroll
    for (int e = 0; e < 8; e++) {
        float s = 0.f;
#pragma unroll
        for (int j = 0; j < 8; j++) s += kvs[e * 8 + j] * q[j];
        op[(size_t)e * HW] = s * inv;
    }
}

// ---------------- 3x3 depthwise + bias + hswish (768 channels, 4 rows/block) ----------------
__global__ void dw3x3_k(const float* __restrict__ in, const float* __restrict__ wgt,
                        const float* __restrict__ bias, float* __restrict__ out) {
    __shared__ float sh[6][136];
    __shared__ float wsm[9];
    int tid = threadIdx.x;
    int y0 = blockIdx.x * 4, c = blockIdx.y, b = blockIdx.z;
    int warp = tid >> 5, lane = tid & 31;
    const float* inC = in + ((size_t)b * 768 + c) * HW;
    if (tid < 9) wsm[tid] = wgt[c * 9 + tid];
    if (warp < 6) {
        int yy = y0 - 1 + warp;
        for (int col = lane; col < 130; col += 32) {
            int xx = col - 1;
            float v = 0.f;
            if (yy >= 0 && yy < HH && xx >= 0 && xx < WW) v = inC[yy * WW + xx];
            sh[warp][col] = v;
        }
    }
    __syncthreads();
    float bv = bias[c];
#pragma unroll
    for (int p = 0; p < 2; p++) {
        int px = tid + p * 256;
        int ry = px >> 7, x = px & 127;
        float a = bv;
#pragma unroll
        for (int r = 0; r < 3; r++)
#pragma unroll
            for (int s = 0; s < 3; s++)
                a += wsm[r * 3 + s] * sh[ry + r][x + s];
        out[((size_t)b * 768 + c) * HW + (y0 + ry) * WW + x] = hswish_f(a);
    }
}

// ---------------- launch ----------------
extern "C" void kernel_launch(void* const* d_in, const int* in_sizes, int n_in,
                              void* d_out, int out_size) {
    const float* ref = (const float*)d_in[0];
    const float* oth = (const float*)d_in[1];
    const float* wq = (const float*)d_in[2];
    const float* bq = (const float*)d_in[3];
    const float* wk = (const float*)d_in[4];
    const float* bk = (const float*)d_in[5];
    const float* wv = (const float*)d_in[6];
    const float* bv = (const float*)d_in[7];
    const float* agg_dw_w = (const float*)d_in[8];
    const float* agg_pw_w = (const float*)d_in[9];
    const float* attn_proj_w = (const float*)d_in[10];
    const float* bn1_g = (const float*)d_in[11];
    const float* bn1_b = (const float*)d_in[12];
    const float* bn1_m = (const float*)d_in[13];
    const float* bn1_v = (const float*)d_in[14];
    const float* mb1_w = (const float*)d_in[15];
    const float* mb1_b = (const float*)d_in[16];
    const float* mb2_w = (const float*)d_in[17];
    const float* mb2_b = (const float*)d_in[18];
    const float* mb3_w = (const float*)d_in[19];
    const float* bn2_g = (const float*)d_in[20];
    const float* bn2_b = (const float*)d_in[21];
    const float* bn2_m = (const float*)d_in[22];
    const float* bn2_v = (const float*)d_in[23];

    float *multi, *att, *attended, *h1, *h2, *kv, *wT;
    cudaGetSymbolAddress((void**)&multi, g_multi);
    cudaGetSymbolAddress((void**)&att, g_att);
    cudaGetSymbolAddress((void**)&attended, g_attended);
    cudaGetSymbolAddress((void**)&h1, g_h1);
    cudaGetSymbolAddress((void**)&h2, g_h2);
    cudaGetSymbolAddress((void**)&kv, g_kv);
    cudaGetSymbolAddress((void**)&wT, g_wT);
    float4* fr4 = (float4*)wT;

    // one-time weight fragment packing (tf32-converted, mma-fragment order)
    prep_conv_frag<<<144, 256>>>(wq, fr4 + FQ);
    prep_conv_frag<<<144, 256>>>(wk, fr4 + FK);
    prep_conv_frag<<<144, 256>>>(wv, fr4 + FV);
    prep_gemm_frag<<<32, 256>>>(attn_proj_w, fr4 + FP, 256, 128);
    prep_gemm_frag<<<96, 256>>>(mb1_w, fr4 + F1, 128, 768);
    prep_gemm_frag<<<96, 256>>>(mb3_w, fr4 + F3, 768, 128);

    // fused q,k,v 3x3 convs -> multi channels 0/128/256
    conv3x3_tc<<<dim3(128, 6, 4), 256>>>(ref, oth, fr4 + FQ, bq, bk, bv, multi);

    // fused 5x5 dw + grouped 1x1 -> multi channels 384..767
    dwpw_k<<<dim3(32, 48, 4), 256>>>(multi, agg_dw_w, agg_pw_w, multi);

    // relu linear attention
    zero_kv_k<<<(BB * 32 * 72 + 255) / 256, 256>>>(kv);
    attn_kv_k<<<dim3(8, 32, 4), 256>>>(multi, kv);
    attn_apply_k<<<dim3(64, 32, 4), 256>>>(multi, kv, att);

    // attn_proj + bn1 + residual -> attended
    gemm1x1_tc<1><<<dim3(128, 2, 4), 256>>>(att, 256, fr4 + FP, 128, bn1_g, bn1_b, bn1_m, bn1_v,
                                            ref, attended);

    // MBConv
    gemm1x1_tc<0><<<dim3(128, 12, 4), 256>>>(attended, 128, fr4 + F1, 768, mb1_b, nullptr,
                                             nullptr, nullptr, nullptr, h1);
    dw3x3_k<<<dim3(32, 768, 4), 256>>>(h1, mb2_w, mb2_b, h2);
    gemm1x1_tc<1><<<dim3(128, 2, 4), 256>>>(h2, 768, fr4 + F3, 128, bn2_g, bn2_b, bn2_m, bn2_v,
                                            attended, (float*)d_out);
}

// round 8
// speedup vs baseline: 1.2757x; 1.2757x over previous
#include <cuda_runtime.h>
#include <cstdint>
#include <cstddef>

#define HH 128
#define WW 128
#define HW 16384
#define BB 4

// ---------------- scratch (static device globals; no allocation) ----------------
__device__ float g_multi[(size_t)BB * 768 * HW];    // qkv (0..383) + ms (384..767)
__device__ float g_msdw[(size_t)BB * 384 * HW];     // depthwise 5x5 output
__device__ float g_att[(size_t)BB * 256 * HW];      // attention output
__device__ float g_attended[(size_t)BB * 128 * HW]; // residual branch point
__device__ float g_h1[(size_t)BB * 768 * HW];       // mb1 output
__device__ float g_h2[(size_t)BB * 768 * HW];       // mb2 output
__device__ float g_kv[(size_t)BB * 32 * 72];        // per-(b,g) 9x8 kv matrices
__device__ float g_wT[768 * 1152];                  // fragment-packed weights (float4 view)

// fragment-region offsets in float4 units
#define FQ 0
#define FK 36864
#define FV 73728
#define FP 110592
#define F1 118784
#define F3 143360

// ---------------- tf32 helpers ----------------
__device__ __forceinline__ float f2tf32f(float f) {
    uint32_t u;
    asm("cvt.rna.tf32.f32 %0, %1;" : "=r"(u) : "f"(f));
    return __uint_as_float(u);
}

__device__ __forceinline__ void mma_tf32(float& d0, float& d1, float& d2, float& d3,
                                         uint32_t a0, uint32_t a1, uint32_t a2, uint32_t a3,
                                         uint32_t b0, uint32_t b1) {
    asm volatile(
        "mma.sync.aligned.m16n8k8.row.col.f32.tf32.tf32.f32 "
        "{%0,%1,%2,%3},{%4,%5,%6,%7},{%8,%9},{%0,%1,%2,%3};"
        : "+f"(d0), "+f"(d1), "+f"(d2), "+f"(d3)
        : "r"(a0), "r"(a1), "r"(a2), "r"(a3), "r"(b0), "r"(b1));
}

__device__ __forceinline__ float hswish_f(float x) {
    return x * fminf(fmaxf(x + 3.f, 0.f), 6.f) * (1.f / 6.f);
}

// ---------------- prep: conv weights -> fragment-packed tf32 float4 ----------------
// out layout: [cb2][c08][rs][w2][mi][lane].  w layout: [co][ci][3][3].
__global__ void prep_conv_frag(const float* __restrict__ w, float4* __restrict__ out) {
    int j = blockIdx.x * 256 + threadIdx.x;   // 0..36863
    int lane = j & 31, mi = (j >> 5) & 1, w2 = (j >> 6) & 1;
    int r3 = j >> 7;
    int rs = r3 % 9;
    int tmp = r3 / 9;
    int c08 = tmp & 15;
    int cb2 = tmp >> 4;
    int g = lane >> 2, t = lane & 3;
    int m = cb2 * 64 + w2 * 32 + mi * 16 + g;
    int k = c08 * 8 + t;
    float e0 = w[(size_t)m * 1152 + k * 9 + rs];
    float e1 = w[(size_t)(m + 8) * 1152 + k * 9 + rs];
    float e2 = w[(size_t)m * 1152 + (k + 4) * 9 + rs];
    float e3 = w[(size_t)(m + 8) * 1152 + (k + 4) * 9 + rs];
    out[j] = make_float4(f2tf32f(e0), f2tf32f(e1), f2tf32f(e2), f2tf32f(e3));
}

// ---------------- prep: 1x1 weights -> fragment-packed tf32 float4 ----------------
// out layout: [cb][k016][ks][w2][mi][lane].  w layout: [Cout][Cin].
__global__ void prep_gemm_frag(const float* __restrict__ w, float4* __restrict__ out,
                               int Cin, int Cout) {
    int j = blockIdx.x * 256 + threadIdx.x;
    if (j >= (Cin * Cout) / 4) return;
    int lane = j & 31, mi = (j >> 5) & 1, w2 = (j >> 6) & 1, ks = (j >> 7) & 1;
    int rest = j >> 8;
    int nk = Cin >> 4;
    int k016 = rest % nk;
    int cb = rest / nk;
    int g = lane >> 2, t = lane & 3;
    int co = cb * 64 + w2 * 32 + mi * 16 + g;
    int k = k016 * 16 + ks * 8 + t;
    float e0 = w[(size_t)co * Cin + k];
    float e1 = w[(size_t)(co + 8) * Cin + k];
    float e2 = w[(size_t)co * Cin + k + 4];
    float e3 = w[(size_t)(co + 8) * Cin + k + 4];
    out[j] = make_float4(f2tf32f(e0), f2tf32f(e1), f2tf32f(e2), f2tf32f(e3));
}

// ---------------- fused 3x3 convs (q,k,v) via tf32 tensor cores ----------------
__global__ void conv3x3_tc(const float* __restrict__ ref, const float* __restrict__ oth,
                           const float4* __restrict__ wfragAll,
                           const float* __restrict__ bq, const float* __restrict__ bk,
                           const float* __restrict__ bv, float* __restrict__ out) {
    __shared__ float4 Afrag[1152];      // [rs][w2][mi][lane]
    __shared__ float Ish[8][3][136];    // [cin8][row3][col(-1..128)]
    int tid = threadIdx.x;
    int lane = tid & 31, warp = tid >> 5;
    int g = lane >> 2, t = lane & 3;
    int w2 = warp >> 2;                 // 0/1 (wm = w2*32)
    int wn = (warp & 3) * 32;
    int y = blockIdx.x;
    int cv = blockIdx.y >> 1;
    int cb2 = blockIdx.y & 1;
    int cbase = cb2 * 64;
    int b = blockIdx.z;
    const float* in = (cv == 0) ? ref : oth;
    const float4* wf = wfragAll + (size_t)(cv * 2 + cb2) * 16 * 1152;
    const float* bias = (cv == 0) ? bq : (cv == 1) ? bk : bv;
    int outOff = cv * 128;
    const float* inB = in + (size_t)b * 128 * HW;
    float acc[2][4][4] = {};

    for (int c08 = 0; c08 < 16; c08++) {
        int c0 = c08 * 8;
        __syncthreads();
        for (int j = tid; j < 1152; j += 256)
            Afrag[j] = wf[c08 * 1152 + j];
        {
            const float* inC = inB + (size_t)(c0 + warp) * HW;
#pragma unroll
            for (int r = 0; r < 3; r++) {
                int yy = y - 1 + r;
                for (int col = lane; col < 130; col += 32) {
                    int xx = col - 1;
                    float v = 0.f;
                    if (xx >= 0 && xx < WW && yy >= 0 && yy < HH)
                        v = inC[yy * WW + xx];
                    Ish[warp][r][col] = f2tf32f(v);
                }
            }
        }
        __syncthreads();
#pragma unroll
        for (int r = 0; r < 3; r++) {
#pragma unroll
            for (int s = 0; s < 3; s++) {
                int rs = r * 3 + s;
                uint32_t a[2][4];
#pragma unroll
                for (int mi = 0; mi < 2; mi++) {
                    float4 af = Afrag[((rs * 2 + w2) * 2 + mi) * 32 + lane];
                    a[mi][0] = __float_as_uint(af.x);
                    a[mi][1] = __float_as_uint(af.y);
                    a[mi][2] = __float_as_uint(af.z);
                    a[mi][3] = __float_as_uint(af.w);
                }
#pragma unroll
                for (int ni = 0; ni < 4; ni++) {
                    uint32_t b0 = __float_as_uint(Ish[t][r][wn + ni * 8 + g + s]);
                    uint32_t b1 = __float_as_uint(Ish[t + 4][r][wn + ni * 8 + g + s]);
#pragma unroll
                    for (int mi = 0; mi < 2; mi++)
                        mma_tf32(acc[mi][ni][0], acc[mi][ni][1], acc[mi][ni][2], acc[mi][ni][3],
                                 a[mi][0], a[mi][1], a[mi][2], a[mi][3], b0, b1);
                }
            }
        }
    }
#pragma unroll
    for (int mi = 0; mi < 2; mi++) {
        int co0 = cbase + w2 * 32 + mi * 16 + g;
        int co1 = co0 + 8;
        float bv0 = bias[co0], bv1 = bias[co1];
        float* p0 = out + ((size_t)b * 768 + outOff + co0) * HW + y * WW;
        float* p1 = out + ((size_t)b * 768 + outOff + co1) * HW + y * WW;
#pragma unroll
        for (int ni = 0; ni < 4; ni++) {
            int x0 = wn + ni * 8 + 2 * t;
            *(float2*)&p0[x0] = make_float2(acc[mi][ni][0] + bv0, acc[mi][ni][1] + bv0);
            *(float2*)&p1[x0] = make_float2(acc[mi][ni][2] + bv1, acc[mi][ni][3] + bv1);
        }
    }
}

// ---------------- 1x1 conv (GEMM) via tf32 tensor cores, fragment-packed weights ----------------
template <int MODE>
__global__ void gemm1x1_tc(const float* __restrict__ in, int Cin,
                           const float4* __restrict__ wfrag, int Cout,
                           const float* __restrict__ p0, const float* __restrict__ p1,
                           const float* __restrict__ p2, const float* __restrict__ p3,
                           const float* __restrict__ res, float* __restrict__ out) {
    __shared__ float4 Af[256];          // [ks][w2][mi][lane]
    __shared__ float Ish[16][136];
    int tid = threadIdx.x;
    int lane = tid & 31, warp = tid >> 5;
    int g = lane >> 2, t = lane & 3;
    int w2 = warp >> 2;
    int wn = (warp & 3) * 32;
    int nbase = blockIdx.x * 128;
    int cb = blockIdx.y;
    int b = blockIdx.z;
    int nk = Cin >> 4;
    const float* inB = in + (size_t)b * Cin * HW + nbase;
    float acc[2][4][4] = {};

    for (int k016 = 0; k016 < nk; k016++) {
        int k0 = k016 * 16;
        __syncthreads();
        Af[tid] = wfrag[((size_t)cb * nk + k016) * 256 + tid];
        {
            int k2 = tid >> 5, p2i = tid & 31;
            float4 iv = *(const float4*)&inB[(size_t)(k0 + k2) * HW + p2i * 4];
            iv.x = f2tf32f(iv.x); iv.y = f2tf32f(iv.y);
            iv.z = f2tf32f(iv.z); iv.w = f2tf32f(iv.w);
            *(float4*)&Ish[k2][p2i * 4] = iv;
            float4 iv2 = *(const float4*)&inB[(size_t)(k0 + k2 + 8) * HW + p2i * 4];
            iv2.x = f2tf32f(iv2.x); iv2.y = f2tf32f(iv2.y);
            iv2.z = f2tf32f(iv2.z); iv2.w = f2tf32f(iv2.w);
            *(float4*)&Ish[k2 + 8][p2i * 4] = iv2;
        }
        __syncthreads();
#pragma unroll
        for (int ks = 0; ks < 2; ks++) {
            int kb = ks * 8;
            uint32_t a[2][4];
#pragma unroll
            for (int mi = 0; mi < 2; mi++) {
                float4 af = Af[((ks * 2 + w2) * 2 + mi) * 32 + lane];
                a[mi][0] = __float_as_uint(af.x);
                a[mi][1] = __float_as_uint(af.y);
                a[mi][2] = __float_as_uint(af.z);
                a[mi][3] = __float_as_uint(af.w);
            }
#pragma unroll
            for (int ni = 0; ni < 4; ni++) {
                uint32_t b0 = __float_as_uint(Ish[kb + t][wn + ni * 8 + g]);
                uint32_t b1 = __float_as_uint(Ish[kb + t + 4][wn + ni * 8 + g]);
#pragma unroll
                for (int mi = 0; mi < 2; mi++)
                    mma_tf32(acc[mi][ni][0], acc[mi][ni][1], acc[mi][ni][2], acc[mi][ni][3],
                             a[mi][0], a[mi][1], a[mi][2], a[mi][3], b0, b1);
            }
        }
    }
    // epilogue
#pragma unroll
    for (int mi = 0; mi < 2; mi++) {
        int co0 = cb * 64 + w2 * 32 + mi * 16 + g;
        int co1 = co0 + 8;
        float b0v = 0.f, b1v = 0.f, sc0 = 0.f, sc1 = 0.f, sh0 = 0.f, sh1 = 0.f;
        if (MODE == 0) {
            b0v = p0[co0];
            b1v = p0[co1];
        } else {
            sc0 = p0[co0] * rsqrtf(p3[co0] + 1e-5f);
            sh0 = p1[co0] - p2[co0] * sc0;
            sc1 = p0[co1] * rsqrtf(p3[co1] + 1e-5f);
            sh1 = p1[co1] - p2[co1] * sc1;
        }
        size_t row0 = ((size_t)b * Cout + co0) * HW + nbase;
        size_t row1 = ((size_t)b * Cout + co1) * HW + nbase;
#pragma unroll
        for (int ni = 0; ni < 4; ni++) {
            int x0 = wn + ni * 8 + 2 * t;
            float v00 = acc[mi][ni][0], v01 = acc[mi][ni][1];
            float v10 = acc[mi][ni][2], v11 = acc[mi][ni][3];
            if (MODE == 0) {
                v00 = hswish_f(v00 + b0v);
                v01 = hswish_f(v01 + b0v);
                v10 = hswish_f(v10 + b1v);
                v11 = hswish_f(v11 + b1v);
            } else {
                float2 r0 = *(const float2*)&res[row0 + x0];
                float2 r1 = *(const float2*)&res[row1 + x0];
                v00 = v00 * sc0 + sh0 + r0.x;
                v01 = v01 * sc0 + sh0 + r0.y;
                v10 = v10 * sc1 + sh1 + r1.x;
                v11 = v11 * sc1 + sh1 + r1.y;
            }
            *(float2*)&out[row0 + x0] = make_float2(v00, v01);
            *(float2*)&out[row1 + x0] = make_float2(v10, v11);
        }
    }
}

// ---------------- 5x5 depthwise on multi channels 0..383 -> msdw  (R5 version) ----------------
__global__ void dw5x5_k(const float* __restrict__ in, const float* __restrict__ wgt,
                        float* __restrict__ out) {
    __shared__ float sh[5][136];
    int x = threadIdx.x;
    int y = blockIdx.x;
    int c = blockIdx.y;
    int b = blockIdx.z;
    const float* inC = in + ((size_t)b * 768 + c) * HW;
    for (int r = 0; r < 5; r++) {
        int yy = y - 2 + r;
        for (int i = x; i < 132; i += 128) {
            int xx = i - 2;
            float v = 0.f;
            if (yy >= 0 && yy < HH && xx >= 0 && xx < WW) v = inC[yy * WW + xx];
            sh[r][i] = v;
        }
    }
    __syncthreads();
    const float* wc = wgt + c * 25;
    float a = 0.f;
#pragma unroll
    for (int r = 0; r < 5; r++)
#pragma unroll
        for (int s = 0; s < 5; s++)
            a += wc[r * 5 + s] * sh[r][x + s];
    out[((size_t)b * 384 + c) * HW + y * WW + x] = a;
}

// ---------------- grouped 1x1, 8->8 per group, 48 groups (R5 version) ----------------
__global__ void pw_group_k(const float* __restrict__ in, const float* __restrict__ wgt,
                           float* __restrict__ out) {
    __shared__ float wsh[64];
    int g = blockIdx.y;
    int b = blockIdx.z;
    if (threadIdx.x < 64) wsh[threadIdx.x] = wgt[g * 64 + threadIdx.x];
    __syncthreads();
    int n = blockIdx.x * 128 + threadIdx.x;
    const float* ip = in + ((size_t)b * 384 + g * 8) * HW + n;
    float xi[8];
#pragma unroll
    for (int i = 0; i < 8; i++) xi[i] = ip[(size_t)i * HW];
    float* op = out + ((size_t)b * 768 + 384 + g * 8) * HW + n;
#pragma unroll
    for (int o = 0; o < 8; o++) {
        float a = 0.f;
#pragma unroll
        for (int i = 0; i < 8; i++) a += wsh[o * 8 + i] * xi[i];
        op[(size_t)o * HW] = a;
    }
}

// ---------------- zero kv accumulators ----------------
__global__ void zero_kv_k(float* __restrict__ kv) {
    int i = blockIdx.x * 256 + threadIdx.x;
    if (i < BB * 32 * 72) kv[i] = 0.f;
}

// ---------------- attention phase 1 ----------------
__global__ void attn_kv_k(const float* __restrict__ multi, float* __restrict__ kv) {
    int b = blockIdx.z, g = blockIdx.y;
    const float* base = multi + ((size_t)b * 768 + g * 24) * HW;
    int n0 = blockIdx.x * 2048;
    float acc[72];
#pragma unroll
    for (int i = 0; i < 72; i++) acc[i] = 0.f;
    for (int n = n0 + threadIdx.x; n < n0 + 2048; n += 256) {
        float kq[8], vv[8];
#pragma unroll
        for (int j = 0; j < 8; j++) kq[j] = fmaxf(base[(size_t)(8 + j) * HW + n], 0.f);
#pragma unroll
        for (int e = 0; e < 8; e++) vv[e] = base[(size_t)(16 + e) * HW + n];
#pragma unroll
        for (int e = 0; e < 8; e++)
#pragma unroll
            for (int j = 0; j < 8; j++) acc[e * 8 + j] += vv[e] * kq[j];
#pragma unroll
        for (int j = 0; j < 8; j++) acc[64 + j] += kq[j];
    }
    __shared__ float red[72][8];
    int lane = threadIdx.x & 31, warp = threadIdx.x >> 5;
#pragma unroll
    for (int i = 0; i < 72; i++) {
        float v = acc[i];
        v += __shfl_down_sync(0xffffffffu, v, 16);
        v += __shfl_down_sync(0xffffffffu, v, 8);
        v += __shfl_down_sync(0xffffffffu, v, 4);
        v += __shfl_down_sync(0xffffffffu, v, 2);
        v += __shfl_down_sync(0xffffffffu, v, 1);
        if (lane == 0) red[i][warp] = v;
    }
    __syncthreads();
    if (threadIdx.x < 72) {
        float s = 0.f;
#pragma unroll
        for (int w = 0; w < 8; w++) s += red[threadIdx.x][w];
        atomicAdd(&kv[((size_t)b * 32 + g) * 72 + threadIdx.x], s);
    }
}

// ---------------- attention phase 2 ----------------
__global__ void attn_apply_k(const float* __restrict__ multi, const float* __restrict__ kv,
                             float* __restrict__ att) {
    int b = blockIdx.z, g = blockIdx.y;
    __shared__ float kvs[72];
    if (threadIdx.x < 72) kvs[threadIdx.x] = kv[((size_t)b * 32 + g) * 72 + threadIdx.x];
    __syncthreads();
    int n = blockIdx.x * 256 + threadIdx.x;
    const float* base = multi + ((size_t)b * 768 + g * 24) * HW + n;
    float q[8];
#pragma unroll
    for (int j = 0; j < 8; j++) q[j] = fmaxf(base[(size_t)j * HW], 0.f);
    float denom = 0.f;
#pragma unroll
    for (int j = 0; j < 8; j++) denom += kvs[64 + j] * q[j];
    float inv = 1.f / (denom + 1e-15f);
    float* op = att + ((size_t)b * 256 + g * 8) * HW + n;
#pragma unroll
    for (int e = 0; e < 8; e++) {
        float s = 0.f;
#pragma unroll
        for (int j = 0; j < 8; j++) s += kvs[e * 8 + j] * q[j];
        op[(size_t)e * HW] = s * inv;
    }
}

// ---------------- 3x3 depthwise + bias + hswish (R5 version) ----------------
__global__ void dw3x3_k(const float* __restrict__ in, const float* __restrict__ wgt,
                        const float* __restrict__ bias, float* __restrict__ out) {
    __shared__ float sh[3][136];
    int x = threadIdx.x, y = blockIdx.x, c = blockIdx.y, b = blockIdx.z;
    const float* inC = in + ((size_t)b * 768 + c) * HW;
    for (int r = 0; r < 3; r++) {
        int yy = y - 1 + r;
        for (int i = x; i < 130; i += 128) {
            int xx = i - 1;
            float v = 0.f;
            if (yy >= 0 && yy < HH && xx >= 0 && xx < WW) v = inC[yy * WW + xx];
            sh[r][i] = v;
        }
    }
    __syncthreads();
    const float* wc = wgt + c * 9;
    float a = bias[c];
#pragma unroll
    for (int r = 0; r < 3; r++)
#pragma unroll
        for (int s = 0; s < 3; s++)
            a += wc[r * 3 + s] * sh[r][x + s];
    out[((size_t)b * 768 + c) * HW + y * WW + x] = hswish_f(a);
}

// ---------------- launch ----------------
extern "C" void kernel_launch(void* const* d_in, const int* in_sizes, int n_in,
                              void* d_out, int out_size) {
    const float* ref = (const float*)d_in[0];
    const float* oth = (const float*)d_in[1];
    const float* wq = (const float*)d_in[2];
    const float* bq = (const float*)d_in[3];
    const float* wk = (const float*)d_in[4];
    const float* bk = (const float*)d_in[5];
    const float* wv = (const float*)d_in[6];
    const float* bv = (const float*)d_in[7];
    const float* agg_dw_w = (const float*)d_in[8];
    const float* agg_pw_w = (const float*)d_in[9];
    const float* attn_proj_w = (const float*)d_in[10];
    const float* bn1_g = (const float*)d_in[11];
    const float* bn1_b = (const float*)d_in[12];
    const float* bn1_m = (const float*)d_in[13];
    const float* bn1_v = (const float*)d_in[14];
    const float* mb1_w = (const float*)d_in[15];
    const float* mb1_b = (const float*)d_in[16];
    const float* mb2_w = (const float*)d_in[17];
    const float* mb2_b = (const float*)d_in[18];
    const float* mb3_w = (const float*)d_in[19];
    const float* bn2_g = (const float*)d_in[20];
    const float* bn2_b = (const float*)d_in[21];
    const float* bn2_m = (const float*)d_in[22];
    const float* bn2_v = (const float*)d_in[23];

    float *multi, *msdw, *att, *attended, *h1, *h2, *kv, *wT;
    cudaGetSymbolAddress((void**)&multi, g_multi);
    cudaGetSymbolAddress((void**)&msdw, g_msdw);
    cudaGetSymbolAddress((void**)&att, g_att);
    cudaGetSymbolAddress((void**)&attended, g_attended);
    cudaGetSymbolAddress((void**)&h1, g_h1);
    cudaGetSymbolAddress((void**)&h2, g_h2);
    cudaGetSymbolAddress((void**)&kv, g_kv);
    cudaGetSymbolAddress((void**)&wT, g_wT);
    float4* fr4 = (float4*)wT;

    // one-time weight fragment packing (tf32-converted, mma-fragment order)
    prep_conv_frag<<<144, 256>>>(wq, fr4 + FQ);
    prep_conv_frag<<<144, 256>>>(wk, fr4 + FK);
    prep_conv_frag<<<144, 256>>>(wv, fr4 + FV);
    prep_gemm_frag<<<32, 256>>>(attn_proj_w, fr4 + FP, 256, 128);
    prep_gemm_frag<<<96, 256>>>(mb1_w, fr4 + F1, 128, 768);
    prep_gemm_frag<<<96, 256>>>(mb3_w, fr4 + F3, 768, 128);

    // fused q,k,v 3x3 convs -> multi channels 0/128/256
    conv3x3_tc<<<dim3(128, 6, 4), 256>>>(ref, oth, fr4 + FQ, bq, bk, bv, multi);

    // aggregation: 5x5 dw then grouped 1x1 -> multi channels 384..767
    dw5x5_k<<<dim3(128, 384, 4), 128>>>(multi, agg_dw_w, msdw);
    pw_group_k<<<dim3(128, 48, 4), 128>>>(msdw, agg_pw_w, multi);

    // relu linear attention
    zero_kv_k<<<(BB * 32 * 72 + 255) / 256, 256>>>(kv);
    attn_kv_k<<<dim3(8, 32, 4), 256>>>(multi, kv);
    attn_apply_k<<<dim3(64, 32, 4), 256>>>(multi, kv, att);

    // attn_proj + bn1 + residual -> attended
    gemm1x1_tc<1><<<dim3(128, 2, 4), 256>>>(att, 256, fr4 + FP, 128, bn1_g, bn1_b, bn1_m, bn1_v,
                                            ref, attended);

    // MBConv
    gemm1x1_tc<0><<<dim3(128, 12, 4), 256>>>(attended, 128, fr4 + F1, 768, mb1_b, nullptr,
                                             nullptr, nullptr, nullptr, h1);
    dw3x3_k<<<dim3(128, 768, 4), 128>>>(h1, mb2_w, mb2_b, h2);
    gemm1x1_tc<1><<<dim3(128, 2, 4), 256>>>(h2, 768, fr4 + F3, 128, bn2_g, bn2_b, bn2_m, bn2_v,
                                            attended, (float*)d_out);
}

// round 9
// speedup vs baseline: 1.6266x; 1.2751x over previous
#include <cuda_runtime.h>
#include <cuda_fp16.h>
#include <cstdint>
#include <cstddef>

#define HH 128
#define WW 128
#define HW 16384
#define BB 4

// ---------------- scratch (static device globals; no allocation) ----------------
__device__ float g_multi[(size_t)BB * 768 * HW];    // qkv (0..383) + ms (384..767)
__device__ float g_msdw[(size_t)BB * 384 * HW];     // depthwise 5x5 output
__device__ float g_att[(size_t)BB * 256 * HW];      // attention output
__device__ float g_attended[(size_t)BB * 128 * HW]; // residual branch point
__device__ float g_h1[(size_t)BB * 768 * HW];       // mb1 output
__device__ float g_h2[(size_t)BB * 768 * HW];       // mb2 output
__device__ float g_kv[(size_t)BB * 32 * 72];        // per-(b,g) 9x8 kv matrices
__device__ float g_wT[768 * 1152];                  // fragment-packed fp16 weights (uint4 view)

// fragment-region offsets in uint4 units
#define FQ 0
#define FK 18432
#define FV 36864
#define FP 55296
#define F1 59392
#define F3 71680

// ---------------- fp16 mma helpers ----------------
__device__ __forceinline__ uint32_t packh2(float a, float b) {
    __half2 h = __floats2half2_rn(a, b);
    return *(uint32_t*)&h;
}

__device__ __forceinline__ void mma_fp16(float& d0, float& d1, float& d2, float& d3,
                                         uint32_t a0, uint32_t a1, uint32_t a2, uint32_t a3,
                                         uint32_t b0, uint32_t b1) {
    asm volatile(
        "mma.sync.aligned.m16n8k16.row.col.f32.f16.f16.f32 "
        "{%0,%1,%2,%3},{%4,%5,%6,%7},{%8,%9},{%0,%1,%2,%3};"
        : "+f"(d0), "+f"(d1), "+f"(d2), "+f"(d3)
        : "r"(a0), "r"(a1), "r"(a2), "r"(a3), "r"(b0), "r"(b1));
}

__device__ __forceinline__ float hswish_f(float x) {
    return x * fminf(fmaxf(x + 3.f, 0.f), 6.f) * (1.f / 6.f);
}

// ---------------- prep: conv weights -> fp16 fragment-packed uint4 ----------------
// j = ((((cb2*8 + c016)*9 + rs)*2 + w2)*2 + mi)*32 + lane.  w layout: [co][ci][3][3].
__global__ void prep_conv_frag_h(const float* __restrict__ w, uint4* __restrict__ out) {
    int j = blockIdx.x * 256 + threadIdx.x;   // 0..18431
    int lane = j & 31, mi = (j >> 5) & 1, w2 = (j >> 6) & 1;
    int r3 = j >> 7;
    int rs = r3 % 9;
    int tmp = r3 / 9;
    int c016 = tmp & 7;
    int cb2 = tmp >> 3;
    int g = lane >> 2, t = lane & 3;
    int m = cb2 * 64 + w2 * 32 + mi * 16 + g;
    int k0 = c016 * 16 + 2 * t;
    uint4 u;
    u.x = packh2(w[((size_t)m * 128 + k0) * 9 + rs],       w[((size_t)m * 128 + k0 + 1) * 9 + rs]);
    u.y = packh2(w[((size_t)(m + 8) * 128 + k0) * 9 + rs], w[((size_t)(m + 8) * 128 + k0 + 1) * 9 + rs]);
    u.z = packh2(w[((size_t)m * 128 + k0 + 8) * 9 + rs],   w[((size_t)m * 128 + k0 + 9) * 9 + rs]);
    u.w = packh2(w[((size_t)(m + 8) * 128 + k0 + 8) * 9 + rs], w[((size_t)(m + 8) * 128 + k0 + 9) * 9 + rs]);
    out[j] = u;
}

// ---------------- prep: 1x1 weights -> fp16 fragment-packed uint4 ----------------
// j = (((cb*nk + k016)*2 + w2)*2 + mi)*32 + lane.  w layout: [Cout][Cin].
__global__ void prep_gemm_frag_h(const float* __restrict__ w, uint4* __restrict__ out,
                                 int Cin, int Cout) {
    int j = blockIdx.x * 256 + threadIdx.x;
    if (j >= (Cin * Cout) / 8) return;
    int lane = j & 31, mi = (j >> 5) & 1, w2 = (j >> 6) & 1;
    int rest = j >> 7;
    int nk = Cin >> 4;
    int k016 = rest % nk;
    int cb = rest / nk;
    int g = lane >> 2, t = lane & 3;
    int m = cb * 64 + w2 * 32 + mi * 16 + g;
    int k0 = k016 * 16 + 2 * t;
    uint4 u;
    u.x = packh2(w[(size_t)m * Cin + k0],       w[(size_t)m * Cin + k0 + 1]);
    u.y = packh2(w[(size_t)(m + 8) * Cin + k0], w[(size_t)(m + 8) * Cin + k0 + 1]);
    u.z = packh2(w[(size_t)m * Cin + k0 + 8],   w[(size_t)m * Cin + k0 + 9]);
    u.w = packh2(w[(size_t)(m + 8) * Cin + k0 + 8], w[(size_t)(m + 8) * Cin + k0 + 9]);
    out[j] = u;
}

// ---------------- fused 3x3 convs (q,k,v) via fp16 tensor cores ----------------
// blockIdx.y in [0,6): cv = y>>1 (0=q on ref, 1=k, 2=v on oth), cb2 = y&1.
__global__ void conv3x3_tc(const float* __restrict__ ref, const float* __restrict__ oth,
                           const uint4* __restrict__ wfragAll,
                           const float* __restrict__ bq, const float* __restrict__ bk,
                           const float* __restrict__ bv, float* __restrict__ out) {
    __shared__ uint4 Afrag[1152];          // [rs][w2][mi][lane]
    __shared__ uint32_t Ish[8][3][136];    // [ch-pair][row3][col(-1..128)] half2
    int tid = threadIdx.x;
    int lane = tid & 31, warp = tid >> 5;
    int g = lane >> 2, t = lane & 3;
    int w2 = warp >> 2;                 // 0/1 (wm = w2*32)
    int wn = (warp & 3) * 32;
    int y = blockIdx.x;
    int cv = blockIdx.y >> 1;
    int cb2 = blockIdx.y & 1;
    int cbase = cb2 * 64;
    int b = blockIdx.z;
    const float* in = (cv == 0) ? ref : oth;
    const uint4* wf = wfragAll + (size_t)cv * 18432 + (size_t)cb2 * 9216;
    const float* bias = (cv == 0) ? bq : (cv == 1) ? bk : bv;
    int outOff = cv * 128;
    const float* inB = in + (size_t)b * 128 * HW;
    float acc[2][4][4] = {};

    for (int c016 = 0; c016 < 8; c016++) {
        int c0 = c016 * 16;
        __syncthreads();
        // weight fragments: straight coalesced uint4 copy
        for (int j = tid; j < 1152; j += 256)
            Afrag[j] = wf[c016 * 1152 + j];
        // input: warp handles channel pair (c0+2*warp, c0+2*warp+1), 3 rows, 130 cols
        {
            const float* inC0 = inB + (size_t)(c0 + 2 * warp) * HW;
            const float* inC1 = inC0 + HW;
#pragma unroll
            for (int r = 0; r < 3; r++) {
                int yy = y - 1 + r;
                for (int col = lane; col < 130; col += 32) {
                    int xx = col - 1;
                    float v0 = 0.f, v1 = 0.f;
                    if (xx >= 0 && xx < WW && yy >= 0 && yy < HH) {
                        v0 = inC0[yy * WW + xx];
                        v1 = inC1[yy * WW + xx];
                    }
                    Ish[warp][r][col] = packh2(v0, v1);
                }
            }
        }
        __syncthreads();
#pragma unroll
        for (int r = 0; r < 3; r++) {
#pragma unroll
            for (int s = 0; s < 3; s++) {
                int rs = r * 3 + s;
                uint4 af[2];
#pragma unroll
                for (int mi = 0; mi < 2; mi++)
                    af[mi] = Afrag[((rs * 2 + w2) * 2 + mi) * 32 + lane];
#pragma unroll
                for (int ni = 0; ni < 4; ni++) {
                    uint32_t b0 = Ish[t][r][wn + ni * 8 + g + s];
                    uint32_t b1 = Ish[t + 4][r][wn + ni * 8 + g + s];
                    mma_fp16(acc[0][ni][0], acc[0][ni][1], acc[0][ni][2], acc[0][ni][3],
                             af[0].x, af[0].y, af[0].z, af[0].w, b0, b1);
                    mma_fp16(acc[1][ni][0], acc[1][ni][1], acc[1][ni][2], acc[1][ni][3],
                             af[1].x, af[1].y, af[1].z, af[1].w, b0, b1);
                }
            }
        }
    }
#pragma unroll
    for (int mi = 0; mi < 2; mi++) {
        int co0 = cbase + w2 * 32 + mi * 16 + g;
        int co1 = co0 + 8;
        float bv0 = bias[co0], bv1 = bias[co1];
        float* p0 = out + ((size_t)b * 768 + outOff + co0) * HW + y * WW;
        float* p1 = out + ((size_t)b * 768 + outOff + co1) * HW + y * WW;
#pragma unroll
        for (int ni = 0; ni < 4; ni++) {
            int x0 = wn + ni * 8 + 2 * t;
            *(float2*)&p0[x0] = make_float2(acc[mi][ni][0] + bv0, acc[mi][ni][1] + bv0);
            *(float2*)&p1[x0] = make_float2(acc[mi][ni][2] + bv1, acc[mi][ni][3] + bv1);
        }
    }
}

// ---------------- 1x1 conv (GEMM) via fp16 tensor cores, fragment-packed weights ----------------
template <int MODE>
__global__ void gemm1x1_tc(const float* __restrict__ in, int Cin,
                           const uint4* __restrict__ wfrag, int Cout,
                           const float* __restrict__ p0, const float* __restrict__ p1,
                           const float* __restrict__ p2, const float* __restrict__ p3,
                           const float* __restrict__ res, float* __restrict__ out) {
    __shared__ uint4 Af[128];              // [w2][mi][lane]
    __shared__ uint32_t Ish[8][136];       // [k-pair][col] half2
    int tid = threadIdx.x;
    int lane = tid & 31, warp = tid >> 5;
    int g = lane >> 2, t = lane & 3;
    int w2 = warp >> 2;
    int wn = (warp & 3) * 32;
    int nbase = blockIdx.x * 128;
    int cb = blockIdx.y;
    int b = blockIdx.z;
    int nk = Cin >> 4;
    const float* inB = in + (size_t)b * Cin * HW + nbase;
    float acc[2][4][4] = {};

    for (int k016 = 0; k016 < nk; k016++) {
        int k0 = k016 * 16;
        __syncthreads();
        if (tid < 128) Af[tid] = wfrag[((size_t)cb * nk + k016) * 128 + tid];
        {
            int k2 = tid >> 5, p2i = tid & 31;
            const float* r0 = inB + (size_t)(k0 + 2 * k2) * HW + p2i * 4;
            float4 v0 = *(const float4*)r0;
            float4 v1 = *(const float4*)(r0 + HW);
            uint4 o;
            o.x = packh2(v0.x, v1.x);
            o.y = packh2(v0.y, v1.y);
            o.z = packh2(v0.z, v1.z);
            o.w = packh2(v0.w, v1.w);
            *(uint4*)&Ish[k2][p2i * 4] = o;
        }
        __syncthreads();
        uint4 af[2];
        af[0] = Af[(w2 * 2 + 0) * 32 + lane];
        af[1] = Af[(w2 * 2 + 1) * 32 + lane];
#pragma unroll
        for (int ni = 0; ni < 4; ni++) {
            uint32_t b0 = Ish[t][wn + ni * 8 + g];
            uint32_t b1 = Ish[t + 4][wn + ni * 8 + g];
            mma_fp16(acc[0][ni][0], acc[0][ni][1], acc[0][ni][2], acc[0][ni][3],
                     af[0].x, af[0].y, af[0].z, af[0].w, b0, b1);
            mma_fp16(acc[1][ni][0], acc[1][ni][1], acc[1][ni][2], acc[1][ni][3],
                     af[1].x, af[1].y, af[1].z, af[1].w, b0, b1);
        }
    }
    // epilogue
#pragma unroll
    for (int mi = 0; mi < 2; mi++) {
        int co0 = cb * 64 + w2 * 32 + mi * 16 + g;
        int co1 = co0 + 8;
        float b0v = 0.f, b1v = 0.f, sc0 = 0.f, sc1 = 0.f, sh0 = 0.f, sh1 = 0.f;
        if (MODE == 0) {
            b0v = p0[co0];
            b1v = p0[co1];
        } else {
            sc0 = p0[co0] * rsqrtf(p3[co0] + 1e-5f);
            sh0 = p1[co0] - p2[co0] * sc0;
            sc1 = p0[co1] * rsqrtf(p3[co1] + 1e-5f);
            sh1 = p1[co1] - p2[co1] * sc1;
        }
        size_t row0 = ((size_t)b * Cout + co0) * HW + nbase;
        size_t row1 = ((size_t)b * Cout + co1) * HW + nbase;
#pragma unroll
        for (int ni = 0; ni < 4; ni++) {
            int x0 = wn + ni * 8 + 2 * t;
            float v00 = acc[mi][ni][0], v01 = acc[mi][ni][1];
            float v10 = acc[mi][ni][2], v11 = acc[mi][ni][3];
            if (MODE == 0) {
                v00 = hswish_f(v00 + b0v);
                v01 = hswish_f(v01 + b0v);
                v10 = hswish_f(v10 + b1v);
                v11 = hswish_f(v11 + b1v);
            } else {
                float2 r0 = *(const float2*)&res[row0 + x0];
                float2 r1 = *(const float2*)&res[row1 + x0];
                v00 = v00 * sc0 + sh0 + r0.x;
                v01 = v01 * sc0 + sh0 + r0.y;
                v10 = v10 * sc1 + sh1 + r1.x;
                v11 = v11 * sc1 + sh1 + r1.y;
            }
            *(float2*)&out[row0 + x0] = make_float2(v00, v01);
            *(float2*)&out[row1 + x0] = make_float2(v10, v11);
        }
    }
}

// ---------------- 5x5 depthwise on multi channels 0..383 -> msdw ----------------
__global__ void dw5x5_k(const float* __restrict__ in, const float* __restrict__ wgt,
                        float* __restrict__ out) {
    __shared__ float sh[5][136];
    int x = threadIdx.x;
    int y = blockIdx.x;
    int c = blockIdx.y;
    int b = blockIdx.z;
    const float* inC = in + ((size_t)b * 768 + c) * HW;
    for (int r = 0; r < 5; r++) {
        int yy = y - 2 + r;
        for (int i = x; i < 132; i += 128) {
            int xx = i - 2;
            float v = 0.f;
            if (yy >= 0 && yy < HH && xx >= 0 && xx < WW) v = inC[yy * WW + xx];
            sh[r][i] = v;
        }
    }
    __syncthreads();
    const float* wc = wgt + c * 25;
    float a = 0.f;
#pragma unroll
    for (int r = 0; r < 5; r++)
#pragma unroll
        for (int s = 0; s < 5; s++)
            a += wc[r * 5 + s] * sh[r][x + s];
    out[((size_t)b * 384 + c) * HW + y * WW + x] = a;
}

// ---------------- grouped 1x1, 8->8 per group, 48 groups ----------------
__global__ void pw_group_k(const float* __restrict__ in, const float* __restrict__ wgt,
                           float* __restrict__ out) {
    __shared__ float wsh[64];
    int g = blockIdx.y;
    int b = blockIdx.z;
    if (threadIdx.x < 64) wsh[threadIdx.x] = wgt[g * 64 + threadIdx.x];
    __syncthreads();
    int n = blockIdx.x * 128 + threadIdx.x;
    const float* ip = in + ((size_t)b * 384 + g * 8) * HW + n;
    float xi[8];
#pragma unroll
    for (int i = 0; i < 8; i++) xi[i] = ip[(size_t)i * HW];
    float* op = out + ((size_t)b * 768 + 384 + g * 8) * HW + n;
#pragma unroll
    for (int o = 0; o < 8; o++) {
        float a = 0.f;
#pragma unroll
        for (int i = 0; i < 8; i++) a += wsh[o * 8 + i] * xi[i];
        op[(size_t)o * HW] = a;
    }
}

// ---------------- zero kv accumulators ----------------
__global__ void zero_kv_k(float* __restrict__ kv) {
    int i = blockIdx.x * 256 + threadIdx.x;
    if (i < BB * 32 * 72) kv[i] = 0.f;
}

// ---------------- attention phase 1 ----------------
__global__ void attn_kv_k(const float* __restrict__ multi, float* __restrict__ kv) {
    int b = blockIdx.z, g = blockIdx.y;
    const float* base = multi + ((size_t)b * 768 + g * 24) * HW;
    int n0 = blockIdx.x * 2048;
    float acc[72];
#pragma unroll
    for (int i = 0; i < 72; i++) acc[i] = 0.f;
    for (int n = n0 + threadIdx.x; n < n0 + 2048; n += 256) {
        float kq[8], vv[8];
#pragma unroll
        for (int j = 0; j < 8; j++) kq[j] = fmaxf(base[(size_t)(8 + j) * HW + n], 0.f);
#pragma unroll
        for (int e = 0; e < 8; e++) vv[e] = base[(size_t)(16 + e) * HW + n];
#pragma unroll
        for (int e = 0; e < 8; e++)
#pragma unroll
            for (int j = 0; j < 8; j++) acc[e * 8 + j] += vv[e] * kq[j];
#pragma unroll
        for (int j = 0; j < 8; j++) acc[64 + j] += kq[j];
    }
    __shared__ float red[72][8];
    int lane = threadIdx.x & 31, warp = threadIdx.x >> 5;
#pragma unroll
    for (int i = 0; i < 72; i++) {
        float v = acc[i];
        v += __shfl_down_sync(0xffffffffu, v, 16);
        v += __shfl_down_sync(0xffffffffu, v, 8);
        v += __shfl_down_sync(0xffffffffu, v, 4);
        v += __shfl_down_sync(0xffffffffu, v, 2);
        v += __shfl_down_sync(0xffffffffu, v, 1);
        if (lane == 0) red[i][warp] = v;
    }
    __syncthreads();
    if (threadIdx.x < 72) {
        float s = 0.f;
#pragma unroll
        for (int w = 0; w < 8; w++) s += red[threadIdx.x][w];
        atomicAdd(&kv[((size_t)b * 32 + g) * 72 + threadIdx.x], s);
    }
}

// ---------------- attention phase 2 ----------------
__global__ void attn_apply_k(const float* __restrict__ multi, const float* __restrict__ kv,
                             float* __restrict__ att) {
    int b = blockIdx.z, g = blockIdx.y;
    __shared__ float kvs[72];
    if (threadIdx.x < 72) kvs[threadIdx.x] = kv[((size_t)b * 32 + g) * 72 + threadIdx.x];
    __syncthreads();
    int n = blockIdx.x * 256 + threadIdx.x;
    const float* base = multi + ((size_t)b * 768 + g * 24) * HW + n;
    float q[8];
#pragma unroll
    for (int j = 0; j < 8; j++) q[j] = fmaxf(base[(size_t)j * HW], 0.f);
    float denom = 0.f;
#pragma unroll
    for (int j = 0; j < 8; j++) denom += kvs[64 + j] * q[j];
    float inv = 1.f / (denom + 1e-15f);
    float* op = att + ((size_t)b * 256 + g * 8) * HW + n;
#pragma unroll
    for (int e = 0; e < 8; e++) {
        float s = 0.f;
#pragma unroll
        for (int j = 0; j < 8; j++) s += kvs[e * 8 + j] * q[j];
        op[(size_t)e * HW] = s * inv;
    }
}

// ---------------- 3x3 depthwise + bias + hswish ----------------
__global__ void dw3x3_k(const float* __restrict__ in, const float* __restrict__ wgt,
                        const float* __restrict__ bias, float* __restrict__ out) {
    __shared__ float sh[3][136];
    int x = threadIdx.x, y = blockIdx.x, c = blockIdx.y, b = blockIdx.z;
    const float* inC = in + ((size_t)b * 768 + c) * HW;
    for (int r = 0; r < 3; r++) {
        int yy = y - 1 + r;
        for (int i = x; i < 130; i += 128) {
            int xx = i - 1;
            float v = 0.f;
            if (yy >= 0 && yy < HH && xx >= 0 && xx < WW) v = inC[yy * WW + xx];
            sh[r][i] = v;
        }
    }
    __syncthreads();
    const float* wc = wgt + c * 9;
    float a = bias[c];
#pragma unroll
    for (int r = 0; r < 3; r++)
#pragma unroll
        for (int s = 0; s < 3; s++)
            a += wc[r * 3 + s] * sh[r][x + s];
    out[((size_t)b * 768 + c) * HW + y * WW + x] = hswish_f(a);
}

// ---------------- launch ----------------
extern "C" void kernel_launch(void* const* d_in, const int* in_sizes, int n_in,
                              void* d_out, int out_size) {
    const float* ref = (const float*)d_in[0];
    const float* oth = (const float*)d_in[1];
    const float* wq = (const float*)d_in[2];
    const float* bq = (const float*)d_in[3];
    const float* wk = (const float*)d_in[4];
    const float* bk = (const float*)d_in[5];
    const float* wv = (const float*)d_in[6];
    const float* bv = (const float*)d_in[7];
    const float* agg_dw_w = (const float*)d_in[8];
    const float* agg_pw_w = (const float*)d_in[9];
    const float* attn_proj_w = (const float*)d_in[10];
    const float* bn1_g = (const float*)d_in[11];
    const float* bn1_b = (const float*)d_in[12];
    const float* bn1_m = (const float*)d_in[13];
    const float* bn1_v = (const float*)d_in[14];
    const float* mb1_w = (const float*)d_in[15];
    const float* mb1_b = (const float*)d_in[16];
    const float* mb2_w = (const float*)d_in[17];
    const float* mb2_b = (const float*)d_in[18];
    const float* mb3_w = (const float*)d_in[19];
    const float* bn2_g = (const float*)d_in[20];
    const float* bn2_b = (const float*)d_in[21];
    const float* bn2_m = (const float*)d_in[22];
    const float* bn2_v = (const float*)d_in[23];

    float *multi, *msdw, *att, *attended, *h1, *h2, *kv, *wT;
    cudaGetSymbolAddress((void**)&multi, g_multi);
    cudaGetSymbolAddress((void**)&msdw, g_msdw);
    cudaGetSymbolAddress((void**)&att, g_att);
    cudaGetSymbolAddress((void**)&attended, g_attended);
    cudaGetSymbolAddress((void**)&h1, g_h1);
    cudaGetSymbolAddress((void**)&h2, g_h2);
    cudaGetSymbolAddress((void**)&kv, g_kv);
    cudaGetSymbolAddress((void**)&wT, g_wT);
    uint4* fr4 = (uint4*)wT;

    // one-time weight fragment packing (fp16, mma m16n8k16 fragment order)
    prep_conv_frag_h<<<72, 256>>>(wq, fr4 + FQ);
    prep_conv_frag_h<<<72, 256>>>(wk, fr4 + FK);
    prep_conv_frag_h<<<72, 256>>>(wv, fr4 + FV);
    prep_gemm_frag_h<<<16, 256>>>(attn_proj_w, fr4 + FP, 256, 128);
    prep_gemm_frag_h<<<48, 256>>>(mb1_w, fr4 + F1, 128, 768);
    prep_gemm_frag_h<<<48, 256>>>(mb3_w, fr4 + F3, 768, 128);

    // fused q,k,v 3x3 convs -> multi channels 0/128/256
    conv3x3_tc<<<dim3(128, 6, 4), 256>>>(ref, oth, fr4 + FQ, bq, bk, bv, multi);

    // aggregation: 5x5 dw then grouped 1x1 -> multi channels 384..767
    dw5x5_k<<<dim3(128, 384, 4), 128>>>(multi, agg_dw_w, msdw);
    pw_group_k<<<dim3(128, 48, 4), 128>>>(msdw, agg_pw_w, multi);

    // relu linear attention
    zero_kv_k<<<(BB * 32 * 72 + 255) / 256, 256>>>(kv);
    attn_kv_k<<<dim3(8, 32, 4), 256>>>(multi, kv);
    attn_apply_k<<<dim3(64, 32, 4), 256>>>(multi, kv, att);

    // attn_proj + bn1 + residual -> attended
    gemm1x1_tc<1><<<dim3(128, 2, 4), 256>>>(att, 256, fr4 + FP, 128, bn1_g, bn1_b, bn1_m, bn1_v,
                                            ref, attended);

    // MBConv
    gemm1x1_tc<0><<<dim3(128, 12, 4), 256>>>(attended, 128, fr4 + F1, 768, mb1_b, nullptr,
                                             nullptr, nullptr, nullptr, h1);
    dw3x3_k<<<dim3(128, 768, 4), 128>>>(h1, mb2_w, mb2_b, h2);
    gemm1x1_tc<1><<<dim3(128, 2, 4), 256>>>(h2, 768, fr4 + F3, 128, bn2_g, bn2_b, bn2_m, bn2_v,
                                            attended, (float*)d_out);
}

// round 10
// speedup vs baseline: 1.7054x; 1.0484x over previous
#include <cuda_runtime.h>
#include <cuda_fp16.h>
#include <cstdint>
#include <cstddef>

#define HH 128
#define WW 128
#define HW 16384
#define BB 4

// ---------------- scratch (static device globals; no allocation) ----------------
__device__ __half g_multi[(size_t)BB * 768 * HW];   // qkv (0..383) + ms (384..767)
__device__ __half g_msdw[(size_t)BB * 384 * HW];    // depthwise 5x5 output
__device__ __half g_att[(size_t)BB * 256 * HW];     // attention output
__device__ float  g_attended[(size_t)BB * 128 * HW];// residual branch point (fp32)
__device__ __half g_h1[(size_t)BB * 768 * HW];      // mb1 output
__device__ __half g_h2[(size_t)BB * 768 * HW];      // mb2 output
__device__ float  g_kv[(size_t)BB * 32 * 72];       // per-(b,g) 9x8 kv matrices
__device__ float  g_wT[768 * 1152];                 // fragment-packed fp16 weights (uint4 view)

// fragment-region offsets in uint4 units
#define FQ 0
#define FK 18432
#define FV 36864
#define FP 55296
#define F1 59392
#define F3 71680

// ---------------- fp16 mma helpers ----------------
__device__ __forceinline__ uint32_t packh2(float a, float b) {
    __half2 h = __floats2half2_rn(a, b);
    return *(uint32_t*)&h;
}

__device__ __forceinline__ void mma_fp16(float& d0, float& d1, float& d2, float& d3,
                                         uint32_t a0, uint32_t a1, uint32_t a2, uint32_t a3,
                                         uint32_t b0, uint32_t b1) {
    asm volatile(
        "mma.sync.aligned.m16n8k16.row.col.f32.f16.f16.f32 "
        "{%0,%1,%2,%3},{%4,%5,%6,%7},{%8,%9},{%0,%1,%2,%3};"
        : "+f"(d0), "+f"(d1), "+f"(d2), "+f"(d3)
        : "r"(a0), "r"(a1), "r"(a2), "r"(a3), "r"(b0), "r"(b1));
}

__device__ __forceinline__ float hswish_f(float x) {
    return x * fminf(fmaxf(x + 3.f, 0.f), 6.f) * (1.f / 6.f);
}

// ---------------- prep: conv weights -> fp16 fragment-packed uint4 ----------------
__global__ void prep_conv_frag_h(const float* __restrict__ w, uint4* __restrict__ out) {
    int j = blockIdx.x * 256 + threadIdx.x;   // 0..18431
    int lane = j & 31, mi = (j >> 5) & 1, w2 = (j >> 6) & 1;
    int r3 = j >> 7;
    int rs = r3 % 9;
    int tmp = r3 / 9;
    int c016 = tmp & 7;
    int cb2 = tmp >> 3;
    int g = lane >> 2, t = lane & 3;
    int m = cb2 * 64 + w2 * 32 + mi * 16 + g;
    int k0 = c016 * 16 + 2 * t;
    uint4 u;
    u.x = packh2(w[((size_t)m * 128 + k0) * 9 + rs],       w[((size_t)m * 128 + k0 + 1) * 9 + rs]);
    u.y = packh2(w[((size_t)(m + 8) * 128 + k0) * 9 + rs], w[((size_t)(m + 8) * 128 + k0 + 1) * 9 + rs]);
    u.z = packh2(w[((size_t)m * 128 + k0 + 8) * 9 + rs],   w[((size_t)m * 128 + k0 + 9) * 9 + rs]);
    u.w = packh2(w[((size_t)(m + 8) * 128 + k0 + 8) * 9 + rs], w[((size_t)(m + 8) * 128 + k0 + 9) * 9 + rs]);
    out[j] = u;
}

// ---------------- prep: 1x1 weights -> fp16 fragment-packed uint4 ----------------
__global__ void prep_gemm_frag_h(const float* __restrict__ w, uint4* __restrict__ out,
                                 int Cin, int Cout) {
    int j = blockIdx.x * 256 + threadIdx.x;
    if (j >= (Cin * Cout) / 8) return;
    int lane = j & 31, mi = (j >> 5) & 1, w2 = (j >> 6) & 1;
    int rest = j >> 7;
    int nk = Cin >> 4;
    int k016 = rest % nk;
    int cb = rest / nk;
    int g = lane >> 2, t = lane & 3;
    int m = cb * 64 + w2 * 32 + mi * 16 + g;
    int k0 = k016 * 16 + 2 * t;
    uint4 u;
    u.x = packh2(w[(size_t)m * Cin + k0],       w[(size_t)m * Cin + k0 + 1]);
    u.y = packh2(w[(size_t)(m + 8) * Cin + k0], w[(size_t)(m + 8) * Cin + k0 + 1]);
    u.z = packh2(w[(size_t)m * Cin + k0 + 8],   w[(size_t)m * Cin + k0 + 9]);
    u.w = packh2(w[(size_t)(m + 8) * Cin + k0 + 8], w[(size_t)(m + 8) * Cin + k0 + 9]);
    out[j] = u;
}

// ---------------- fused 3x3 convs (q,k,v) via fp16 tensor cores ----------------
__global__ void conv3x3_tc(const float* __restrict__ ref, const float* __restrict__ oth,
                           const uint4* __restrict__ wfragAll,
                           const float* __restrict__ bq, const float* __restrict__ bk,
                           const float* __restrict__ bv, __half* __restrict__ out) {
    __shared__ uint4 Afrag[1152];          // [rs][w2][mi][lane]
    __shared__ uint32_t Ish[8][3][136];    // [ch-pair][row3][col(-1..128)] half2
    int tid = threadIdx.x;
    int lane = tid & 31, warp = tid >> 5;
    int g = lane >> 2, t = lane & 3;
    int w2 = warp >> 2;
    int wn = (warp & 3) * 32;
    int y = blockIdx.x;
    int cv = blockIdx.y >> 1;
    int cb2 = blockIdx.y & 1;
    int cbase = cb2 * 64;
    int b = blockIdx.z;
    const float* in = (cv == 0) ? ref : oth;
    const uint4* wf = wfragAll + (size_t)cv * 18432 + (size_t)cb2 * 9216;
    const float* bias = (cv == 0) ? bq : (cv == 1) ? bk : bv;
    int outOff = cv * 128;
    const float* inB = in + (size_t)b * 128 * HW;
    float acc[2][4][4] = {};

    for (int c016 = 0; c016 < 8; c016++) {
        int c0 = c016 * 16;
        __syncthreads();
        for (int j = tid; j < 1152; j += 256)
            Afrag[j] = wf[c016 * 1152 + j];
        {
            const float* inC0 = inB + (size_t)(c0 + 2 * warp) * HW;
            const float* inC1 = inC0 + HW;
#pragma unroll
            for (int r = 0; r < 3; r++) {
                int yy = y - 1 + r;
                for (int col = lane; col < 130; col += 32) {
                    int xx = col - 1;
                    float v0 = 0.f, v1 = 0.f;
                    if (xx >= 0 && xx < WW && yy >= 0 && yy < HH) {
                        v0 = inC0[yy * WW + xx];
                        v1 = inC1[yy * WW + xx];
                    }
                    Ish[warp][r][col] = packh2(v0, v1);
                }
            }
        }
        __syncthreads();
#pragma unroll
        for (int r = 0; r < 3; r++) {
#pragma unroll
            for (int s = 0; s < 3; s++) {
                int rs = r * 3 + s;
                uint4 af[2];
#pragma unroll
                for (int mi = 0; mi < 2; mi++)
                    af[mi] = Afrag[((rs * 2 + w2) * 2 + mi) * 32 + lane];
#pragma unroll
                for (int ni = 0; ni < 4; ni++) {
                    uint32_t b0 = Ish[t][r][wn + ni * 8 + g + s];
                    uint32_t b1 = Ish[t + 4][r][wn + ni * 8 + g + s];
                    mma_fp16(acc[0][ni][0], acc[0][ni][1], acc[0][ni][2], acc[0][ni][3],
                             af[0].x, af[0].y, af[0].z, af[0].w, b0, b1);
                    mma_fp16(acc[1][ni][0], acc[1][ni][1], acc[1][ni][2], acc[1][ni][3],
                             af[1].x, af[1].y, af[1].z, af[1].w, b0, b1);
                }
            }
        }
    }
#pragma unroll
    for (int mi = 0; mi < 2; mi++) {
        int co0 = cbase + w2 * 32 + mi * 16 + g;
        int co1 = co0 + 8;
        float bv0 = bias[co0], bv1 = bias[co1];
        __half* p0 = out + ((size_t)b * 768 + outOff + co0) * HW + y * WW;
        __half* p1 = out + ((size_t)b * 768 + outOff + co1) * HW + y * WW;
#pragma unroll
        for (int ni = 0; ni < 4; ni++) {
            int x0 = wn + ni * 8 + 2 * t;
            *(__half2*)&p0[x0] = __floats2half2_rn(acc[mi][ni][0] + bv0, acc[mi][ni][1] + bv0);
            *(__half2*)&p1[x0] = __floats2half2_rn(acc[mi][ni][2] + bv1, acc[mi][ni][3] + bv1);
        }
    }
}

// ---------------- 1x1 conv (GEMM) via fp16 tensor cores ----------------
// TI: float or __half input.  TO: float or __half output.
// MODE 0: hswish(acc+bias). MODE 1: res(fp32) + bn(acc).
template <int MODE, typename TI, typename TO>
__global__ void gemm1x1_tc(const TI* __restrict__ in, int Cin,
                           const uint4* __restrict__ wfrag, int Cout,
                           const float* __restrict__ p0, const float* __restrict__ p1,
                           const float* __restrict__ p2, const float* __restrict__ p3,
                           const float* __restrict__ res, TO* __restrict__ out) {
    __shared__ uint4 Af[128];              // [w2][mi][lane]
    __shared__ uint32_t Ish[8][136];       // [k-pair][col] half2
    int tid = threadIdx.x;
    int lane = tid & 31, warp = tid >> 5;
    int g = lane >> 2, t = lane & 3;
    int w2 = warp >> 2;
    int wn = (warp & 3) * 32;
    int nbase = blockIdx.x * 128;
    int cb = blockIdx.y;
    int b = blockIdx.z;
    int nk = Cin >> 4;
    const TI* inB = in + (size_t)b * Cin * HW + nbase;
    float acc[2][4][4] = {};

    for (int k016 = 0; k016 < nk; k016++) {
        int k0 = k016 * 16;
        __syncthreads();
        if (tid < 128) Af[tid] = wfrag[((size_t)cb * nk + k016) * 128 + tid];
        {
            int k2 = tid >> 5, p2i = tid & 31;
            if constexpr (sizeof(TI) == 4) {
                const float* r0 = (const float*)inB + (size_t)(k0 + 2 * k2) * HW + p2i * 4;
                float4 v0 = *(const float4*)r0;
                float4 v1 = *(const float4*)(r0 + HW);
                uint4 o;
                o.x = packh2(v0.x, v1.x);
                o.y = packh2(v0.y, v1.y);
                o.z = packh2(v0.z, v1.z);
                o.w = packh2(v0.w, v1.w);
                *(uint4*)&Ish[k2][p2i * 4] = o;
            } else {
                const __half* r0 = (const __half*)inB + (size_t)(k0 + 2 * k2) * HW + p2i * 4;
                uint2 a = *(const uint2*)r0;
                uint2 c = *(const uint2*)(r0 + HW);
                __half2 a0 = *(__half2*)&a.x, a1 = *(__half2*)&a.y;
                __half2 c0 = *(__half2*)&c.x, c1 = *(__half2*)&c.y;
                __half2 t0 = __lows2half2(a0, c0);
                __half2 t1 = __highs2half2(a0, c0);
                __half2 t2 = __lows2half2(a1, c1);
                __half2 t3 = __highs2half2(a1, c1);
                uint4 o;
                o.x = *(uint32_t*)&t0;
                o.y = *(uint32_t*)&t1;
                o.z = *(uint32_t*)&t2;
                o.w = *(uint32_t*)&t3;
                *(uint4*)&Ish[k2][p2i * 4] = o;
            }
        }
        __syncthreads();
        uint4 af[2];
        af[0] = Af[(w2 * 2 + 0) * 32 + lane];
        af[1] = Af[(w2 * 2 + 1) * 32 + lane];
#pragma unroll
        for (int ni = 0; ni < 4; ni++) {
            uint32_t b0 = Ish[t][wn + ni * 8 + g];
            uint32_t b1 = Ish[t + 4][wn + ni * 8 + g];
            mma_fp16(acc[0][ni][0], acc[0][ni][1], acc[0][ni][2], acc[0][ni][3],
                     af[0].x, af[0].y, af[0].z, af[0].w, b0, b1);
            mma_fp16(acc[1][ni][0], acc[1][ni][1], acc[1][ni][2], acc[1][ni][3],
                     af[1].x, af[1].y, af[1].z, af[1].w, b0, b1);
        }
    }
    // epilogue
#pragma unroll
    for (int mi = 0; mi < 2; mi++) {
        int co0 = cb * 64 + w2 * 32 + mi * 16 + g;
        int co1 = co0 + 8;
        float b0v = 0.f, b1v = 0.f, sc0 = 0.f, sc1 = 0.f, sh0 = 0.f, sh1 = 0.f;
        if (MODE == 0) {
            b0v = p0[co0];
            b1v = p0[co1];
        } else {
            sc0 = p0[co0] * rsqrtf(p3[co0] + 1e-5f);
            sh0 = p1[co0] - p2[co0] * sc0;
            sc1 = p0[co1] * rsqrtf(p3[co1] + 1e-5f);
            sh1 = p1[co1] - p2[co1] * sc1;
        }
        size_t row0 = ((size_t)b * Cout + co0) * HW + nbase;
        size_t row1 = ((size_t)b * Cout + co1) * HW + nbase;
#pragma unroll
        for (int ni = 0; ni < 4; ni++) {
            int x0 = wn + ni * 8 + 2 * t;
            float v00 = acc[mi][ni][0], v01 = acc[mi][ni][1];
            float v10 = acc[mi][ni][2], v11 = acc[mi][ni][3];
            if (MODE == 0) {
                v00 = hswish_f(v00 + b0v);
                v01 = hswish_f(v01 + b0v);
                v10 = hswish_f(v10 + b1v);
                v11 = hswish_f(v11 + b1v);
            } else {
                float2 r0 = *(const float2*)&res[row0 + x0];
                float2 r1 = *(const float2*)&res[row1 + x0];
                v00 = v00 * sc0 + sh0 + r0.x;
                v01 = v01 * sc0 + sh0 + r0.y;
                v10 = v10 * sc1 + sh1 + r1.x;
                v11 = v11 * sc1 + sh1 + r1.y;
            }
            if constexpr (sizeof(TO) == 4) {
                *(float2*)&((float*)out)[row0 + x0] = make_float2(v00, v01);
                *(float2*)&((float*)out)[row1 + x0] = make_float2(v10, v11);
            } else {
                *(__half2*)&((__half*)out)[row0 + x0] = __floats2half2_rn(v00, v01);
                *(__half2*)&((__half*)out)[row1 + x0] = __floats2half2_rn(v10, v11);
            }
        }
    }
}

// ---------------- 5x5 depthwise on multi channels 0..383 -> msdw (fp16 io) ----------------
__global__ void dw5x5_k(const __half* __restrict__ in, const float* __restrict__ wgt,
                        __half* __restrict__ out) {
    __shared__ float sh[5][136];
    int x = threadIdx.x;
    int y = blockIdx.x;
    int c = blockIdx.y;
    int b = blockIdx.z;
    const __half* inC = in + ((size_t)b * 768 + c) * HW;
    for (int r = 0; r < 5; r++) {
        int yy = y - 2 + r;
        for (int i = x; i < 132; i += 128) {
            int xx = i - 2;
            float v = 0.f;
            if (yy >= 0 && yy < HH && xx >= 0 && xx < WW) v = __half2float(inC[yy * WW + xx]);
            sh[r][i] = v;
        }
    }
    __syncthreads();
    const float* wc = wgt + c * 25;
    float a = 0.f;
#pragma unroll
    for (int r = 0; r < 5; r++)
#pragma unroll
        for (int s = 0; s < 5; s++)
            a += wc[r * 5 + s] * sh[r][x + s];
    out[((size_t)b * 384 + c) * HW + y * WW + x] = __float2half(a);
}

// ---------------- grouped 1x1, 8->8 per group, 48 groups (fp16 io) ----------------
__global__ void pw_group_k(const __half* __restrict__ in, const float* __restrict__ wgt,
                           __half* __restrict__ out) {
    __shared__ float wsh[64];
    int g = blockIdx.y;
    int b = blockIdx.z;
    if (threadIdx.x < 64) wsh[threadIdx.x] = wgt[g * 64 + threadIdx.x];
    __syncthreads();
    int n = blockIdx.x * 128 + threadIdx.x;
    const __half* ip = in + ((size_t)b * 384 + g * 8) * HW + n;
    float xi[8];
#pragma unroll
    for (int i = 0; i < 8; i++) xi[i] = __half2float(ip[(size_t)i * HW]);
    __half* op = out + ((size_t)b * 768 + 384 + g * 8) * HW + n;
#pragma unroll
    for (int o = 0; o < 8; o++) {
        float a = 0.f;
#pragma unroll
        for (int i = 0; i < 8; i++) a += wsh[o * 8 + i] * xi[i];
        op[(size_t)o * HW] = __float2half(a);
    }
}

// ---------------- zero kv accumulators ----------------
__global__ void zero_kv_k(float* __restrict__ kv) {
    int i = blockIdx.x * 256 + threadIdx.x;
    if (i < BB * 32 * 72) kv[i] = 0.f;
}

// ---------------- attention phase 1 (fp16 in) ----------------
__global__ void attn_kv_k(const __half* __restrict__ multi, float* __restrict__ kv) {
    int b = blockIdx.z, g = blockIdx.y;
    const __half* base = multi + ((size_t)b * 768 + g * 24) * HW;
    int n0 = blockIdx.x * 2048;
    float acc[72];
#pragma unroll
    for (int i = 0; i < 72; i++) acc[i] = 0.f;
    for (int n = n0 + threadIdx.x; n < n0 + 2048; n += 256) {
        float kq[8], vv[8];
#pragma unroll
        for (int j = 0; j < 8; j++) kq[j] = fmaxf(__half2float(base[(size_t)(8 + j) * HW + n]), 0.f);
#pragma unroll
        for (int e = 0; e < 8; e++) vv[e] = __half2float(base[(size_t)(16 + e) * HW + n]);
#pragma unroll
        for (int e = 0; e < 8; e++)
#pragma unroll
            for (int j = 0; j < 8; j++) acc[e * 8 + j] += vv[e] * kq[j];
#pragma unroll
        for (int j = 0; j < 8; j++) acc[64 + j] += kq[j];
    }
    __shared__ float red[72][8];
    int lane = threadIdx.x & 31, warp = threadIdx.x >> 5;
#pragma unroll
    for (int i = 0; i < 72; i++) {
        float v = acc[i];
        v += __shfl_down_sync(0xffffffffu, v, 16);
        v += __shfl_down_sync(0xffffffffu, v, 8);
        v += __shfl_down_sync(0xffffffffu, v, 4);
        v += __shfl_down_sync(0xffffffffu, v, 2);
        v += __shfl_down_sync(0xffffffffu, v, 1);
        if (lane == 0) red[i][warp] = v;
    }
    __syncthreads();
    if (threadIdx.x < 72) {
        float s = 0.f;
#pragma unroll
        for (int w = 0; w < 8; w++) s += red[threadIdx.x][w];
        atomicAdd(&kv[((size_t)b * 32 + g) * 72 + threadIdx.x], s);
    }
}

// ---------------- attention phase 2 (fp16 io) ----------------
__global__ void attn_apply_k(const __half* __restrict__ multi, const float* __restrict__ kv,
                             __half* __restrict__ att) {
    int b = blockIdx.z, g = blockIdx.y;
    __shared__ float kvs[72];
    if (threadIdx.x < 72) kvs[threadIdx.x] = kv[((size_t)b * 32 + g) * 72 + threadIdx.x];
    __syncthreads();
    int n = blockIdx.x * 256 + threadIdx.x;
    const __half* base = multi + ((size_t)b * 768 + g * 24) * HW + n;
    float q[8];
#pragma unroll
    for (int j = 0; j < 8; j++) q[j] = fmaxf(__half2float(base[(size_t)j * HW]), 0.f);
    float denom = 0.f;
#pragma unroll
    for (int j = 0; j < 8; j++) denom += kvs[64 + j] * q[j];
    float inv = 1.f / (denom + 1e-15f);
    __half* op = att + ((size_t)b * 256 + g * 8) * HW + n;
#pragma unroll
    for (int e = 0; e < 8; e++) {
        float s = 0.f;
#pragma unroll
        for (int j = 0; j < 8; j++) s += kvs[e * 8 + j] * q[j];
        op[(size_t)e * HW] = __float2half(s * inv);
    }
}

// ---------------- 3x3 depthwise + bias + hswish (fp16 io) ----------------
__global__ void dw3x3_k(const __half* __restrict__ in, const float* __restrict__ wgt,
                        const float* __restrict__ bias, __half* __restrict__ out) {
    __shared__ float sh[3][136];
    int x = threadIdx.x, y = blockIdx.x, c = blockIdx.y, b = blockIdx.z;
    const __half* inC = in + ((size_t)b * 768 + c) * HW;
    for (int r = 0; r < 3; r++) {
        int yy = y - 1 + r;
        for (int i = x; i < 130; i += 128) {
            int xx = i - 1;
            float v = 0.f;
            if (yy >= 0 && yy < HH && xx >= 0 && xx < WW) v = __half2float(inC[yy * WW + xx]);
            sh[r][i] = v;
        }
    }
    __syncthreads();
    const float* wc = wgt + c * 9;
    float a = bias[c];
#pragma unroll
    for (int r = 0; r < 3; r++)
#pragma unroll
        for (int s = 0; s < 3; s++)
            a += wc[r * 3 + s] * sh[r][x + s];
    out[((size_t)b * 768 + c) * HW + y * WW + x] = __float2half(hswish_f(a));
}

// ---------------- launch ----------------
extern "C" void kernel_launch(void* const* d_in, const int* in_sizes, int n_in,
                              void* d_out, int out_size) {
    const float* ref = (const float*)d_in[0];
    const float* oth = (const float*)d_in[1];
    const float* wq = (const float*)d_in[2];
    const float* bq = (const float*)d_in[3];
    const float* wk = (const float*)d_in[4];
    const float* bk = (const float*)d_in[5];
    const float* wv = (const float*)d_in[6];
    const float* bv = (const float*)d_in[7];
    const float* agg_dw_w = (const float*)d_in[8];
    const float* agg_pw_w = (const float*)d_in[9];
    const float* attn_proj_w = (const float*)d_in[10];
    const float* bn1_g = (const float*)d_in[11];
    const float* bn1_b = (const float*)d_in[12];
    const float* bn1_m = (const float*)d_in[13];
    const float* bn1_v = (const float*)d_in[14];
    const float* mb1_w = (const float*)d_in[15];
    const float* mb1_b = (const float*)d_in[16];
    const float* mb2_w = (const float*)d_in[17];
    const float* mb2_b = (const float*)d_in[18];
    const float* mb3_w = (const float*)d_in[19];
    const float* bn2_g = (const float*)d_in[20];
    const float* bn2_b = (const float*)d_in[21];
    const float* bn2_m = (const float*)d_in[22];
    const float* bn2_v = (const float*)d_in[23];

    __half *multi, *msdw, *att, *h1, *h2;
    float *attended, *kv, *wT;
    cudaGetSymbolAddress((void**)&multi, g_multi);
    cudaGetSymbolAddress((void**)&msdw, g_msdw);
    cudaGetSymbolAddress((void**)&att, g_att);
    cudaGetSymbolAddress((void**)&attended, g_attended);
    cudaGetSymbolAddress((void**)&h1, g_h1);
    cudaGetSymbolAddress((void**)&h2, g_h2);
    cudaGetSymbolAddress((void**)&kv, g_kv);
    cudaGetSymbolAddress((void**)&wT, g_wT);
    uint4* fr4 = (uint4*)wT;

    // one-time weight fragment packing (fp16, mma m16n8k16 fragment order)
    prep_conv_frag_h<<<72, 256>>>(wq, fr4 + FQ);
    prep_conv_frag_h<<<72, 256>>>(wk, fr4 + FK);
    prep_conv_frag_h<<<72, 256>>>(wv, fr4 + FV);
    prep_gemm_frag_h<<<16, 256>>>(attn_proj_w, fr4 + FP, 256, 128);
    prep_gemm_frag_h<<<48, 256>>>(mb1_w, fr4 + F1, 128, 768);
    prep_gemm_frag_h<<<48, 256>>>(mb3_w, fr4 + F3, 768, 128);

    // fused q,k,v 3x3 convs -> multi channels 0/128/256 (fp16)
    conv3x3_tc<<<dim3(128, 6, 4), 256>>>(ref, oth, fr4 + FQ, bq, bk, bv, multi);

    // aggregation: 5x5 dw then grouped 1x1 -> multi channels 384..767 (fp16)
    dw5x5_k<<<dim3(128, 384, 4), 128>>>(multi, agg_dw_w, msdw);
    pw_group_k<<<dim3(128, 48, 4), 128>>>(msdw, agg_pw_w, multi);

    // relu linear attention (fp16 io, fp32 accum)
    zero_kv_k<<<(BB * 32 * 72 + 255) / 256, 256>>>(kv);
    attn_kv_k<<<dim3(8, 32, 4), 256>>>(multi, kv);
    attn_apply_k<<<dim3(64, 32, 4), 256>>>(multi, kv, att);

    // attn_proj + bn1 + residual(ref fp32) -> attended (fp32)
    gemm1x1_tc<1, __half, float><<<dim3(128, 2, 4), 256>>>(
        att, 256, fr4 + FP, 128, bn1_g, bn1_b, bn1_m, bn1_v, ref, attended);

    // MBConv
    gemm1x1_tc<0, float, __half><<<dim3(128, 12, 4), 256>>>(
        attended, 128, fr4 + F1, 768, mb1_b, nullptr, nullptr, nullptr, nullptr, h1);
    dw3x3_k<<<dim3(128, 768, 4), 128>>>(h1, mb2_w, mb2_b, h2);
    gemm1x1_tc<1, __half, float><<<dim3(128, 2, 4), 256>>>(
        h2, 768, fr4 + F3, 128, bn2_g, bn2_b, bn2_m, bn2_v, attended, (float*)d_out);
}

// round 11
// speedup vs baseline: 1.7495x; 1.0259x over previous
#include <cuda_runtime.h>
#include <cuda_fp16.h>
#include <cstdint>
#include <cstddef>

#define HH 128
#define WW 128
#define HW 16384
#define BB 4

// ---------------- scratch (static device globals; no allocation) ----------------
__device__ __half g_multi[(size_t)BB * 768 * HW];   // qkv (0..383) + ms (384..767)
__device__ __half g_msdw[(size_t)BB * 384 * HW];    // depthwise 5x5 output
__device__ __half g_att[(size_t)BB * 256 * HW];     // attention output
__device__ float  g_attended[(size_t)BB * 128 * HW];// residual branch point (fp32)
__device__ __half g_h1[(size_t)BB * 768 * HW];      // mb1 output
__device__ __half g_h2[(size_t)BB * 768 * HW];      // mb2 output
__device__ float  g_kv[(size_t)BB * 32 * 72];       // per-(b,g) 9x8 kv matrices
__device__ float  g_wT[768 * 1152];                 // fragment-packed fp16 weights (uint4 view)

// fragment-region offsets in uint4 units
#define FQ 0
#define FK 18432
#define FV 36864
#define FP 55296
#define F1 59392
#define F3 71680

// ---------------- fp16 mma helpers ----------------
__device__ __forceinline__ uint32_t packh2(float a, float b) {
    __half2 h = __floats2half2_rn(a, b);
    return *(uint32_t*)&h;
}

__device__ __forceinline__ void mma_fp16(float& d0, float& d1, float& d2, float& d3,
                                         uint32_t a0, uint32_t a1, uint32_t a2, uint32_t a3,
                                         uint32_t b0, uint32_t b1) {
    asm volatile(
        "mma.sync.aligned.m16n8k16.row.col.f32.f16.f16.f32 "
        "{%0,%1,%2,%3},{%4,%5,%6,%7},{%8,%9},{%0,%1,%2,%3};"
        : "+f"(d0), "+f"(d1), "+f"(d2), "+f"(d3)
        : "r"(a0), "r"(a1), "r"(a2), "r"(a3), "r"(b0), "r"(b1));
}

__device__ __forceinline__ float hswish_f(float x) {
    return x * fminf(fmaxf(x + 3.f, 0.f), 6.f) * (1.f / 6.f);
}

// ---------------- prep: conv weights -> fp16 fragment-packed uint4 ----------------
__global__ void prep_conv_frag_h(const float* __restrict__ w, uint4* __restrict__ out) {
    int j = blockIdx.x * 256 + threadIdx.x;   // 0..18431
    int lane = j & 31, mi = (j >> 5) & 1, w2 = (j >> 6) & 1;
    int r3 = j >> 7;
    int rs = r3 % 9;
    int tmp = r3 / 9;
    int c016 = tmp & 7;
    int cb2 = tmp >> 3;
    int g = lane >> 2, t = lane & 3;
    int m = cb2 * 64 + w2 * 32 + mi * 16 + g;
    int k0 = c016 * 16 + 2 * t;
    uint4 u;
    u.x = packh2(w[((size_t)m * 128 + k0) * 9 + rs],       w[((size_t)m * 128 + k0 + 1) * 9 + rs]);
    u.y = packh2(w[((size_t)(m + 8) * 128 + k0) * 9 + rs], w[((size_t)(m + 8) * 128 + k0 + 1) * 9 + rs]);
    u.z = packh2(w[((size_t)m * 128 + k0 + 8) * 9 + rs],   w[((size_t)m * 128 + k0 + 9) * 9 + rs]);
    u.w = packh2(w[((size_t)(m + 8) * 128 + k0 + 8) * 9 + rs], w[((size_t)(m + 8) * 128 + k0 + 9) * 9 + rs]);
    out[j] = u;
}

// ---------------- prep: 1x1 weights -> fp16 fragment-packed uint4 ----------------
__global__ void prep_gemm_frag_h(const float* __restrict__ w, uint4* __restrict__ out,
                                 int Cin, int Cout) {
    int j = blockIdx.x * 256 + threadIdx.x;
    if (j >= (Cin * Cout) / 8) return;
    int lane = j & 31, mi = (j >> 5) & 1, w2 = (j >> 6) & 1;
    int rest = j >> 7;
    int nk = Cin >> 4;
    int k016 = rest % nk;
    int cb = rest / nk;
    int g = lane >> 2, t = lane & 3;
    int m = cb * 64 + w2 * 32 + mi * 16 + g;
    int k0 = k016 * 16 + 2 * t;
    uint4 u;
    u.x = packh2(w[(size_t)m * Cin + k0],       w[(size_t)m * Cin + k0 + 1]);
    u.y = packh2(w[(size_t)(m + 8) * Cin + k0], w[(size_t)(m + 8) * Cin + k0 + 1]);
    u.z = packh2(w[(size_t)m * Cin + k0 + 8],   w[(size_t)m * Cin + k0 + 9]);
    u.w = packh2(w[(size_t)(m + 8) * Cin + k0 + 8], w[(size_t)(m + 8) * Cin + k0 + 9]);
    out[j] = u;
}

// ---------------- fused 3x3 convs (q,k,v), M=128 couts per block ----------------
// blockIdx.y = cv (0=q on ref, 1=k, 2=v on oth). Each block computes all 128 couts.
__global__ void __launch_bounds__(256, 2)
conv3x3_tc(const float* __restrict__ ref, const float* __restrict__ oth,
           const uint4* __restrict__ wfragAll,
           const float* __restrict__ bq, const float* __restrict__ bk,
           const float* __restrict__ bv, __half* __restrict__ out) {
    __shared__ uint4 Afrag[2304];          // [cb2][rs][w2][mi][lane]
    __shared__ uint32_t Ish[8][3][136];    // [ch-pair][row3][col(-1..128)] half2
    int tid = threadIdx.x;
    int lane = tid & 31, warp = tid >> 5;
    int g = lane >> 2, t = lane & 3;
    int w2 = warp >> 2;
    int wn = (warp & 3) * 32;
    int y = blockIdx.x;
    int cv = blockIdx.y;
    int b = blockIdx.z;
    const float* in = (cv == 0) ? ref : oth;
    const uint4* wf = wfragAll + (size_t)cv * 18432;
    const float* bias = (cv == 0) ? bq : (cv == 1) ? bk : bv;
    int outOff = cv * 128;
    const float* inB = in + (size_t)b * 128 * HW;
    float acc[4][4][4] = {};

    for (int c016 = 0; c016 < 8; c016++) {
        int c0 = c016 * 16;
        __syncthreads();
        for (int j = tid; j < 1152; j += 256) {
            Afrag[j] = wf[c016 * 1152 + j];
            Afrag[j + 1152] = wf[9216 + c016 * 1152 + j];
        }
        {
            const float* inC0 = inB + (size_t)(c0 + 2 * warp) * HW;
            const float* inC1 = inC0 + HW;
#pragma unroll
            for (int r = 0; r < 3; r++) {
                int yy = y - 1 + r;
                for (int col = lane; col < 130; col += 32) {
                    int xx = col - 1;
                    float v0 = 0.f, v1 = 0.f;
                    if (xx >= 0 && xx < WW && yy >= 0 && yy < HH) {
                        v0 = inC0[yy * WW + xx];
                        v1 = inC1[yy * WW + xx];
                    }
                    Ish[warp][r][col] = packh2(v0, v1);
                }
            }
        }
        __syncthreads();
#pragma unroll
        for (int r = 0; r < 3; r++) {
#pragma unroll
            for (int s = 0; s < 3; s++) {
                int rs = r * 3 + s;
                uint4 af[4];
#pragma unroll
                for (int mi2 = 0; mi2 < 4; mi2++)
                    af[mi2] = Afrag[(mi2 >> 1) * 1152 +
                                    ((rs * 2 + w2) * 2 + (mi2 & 1)) * 32 + lane];
#pragma unroll
                for (int ni = 0; ni < 4; ni++) {
                    uint32_t b0 = Ish[t][r][wn + ni * 8 + g + s];
                    uint32_t b1 = Ish[t + 4][r][wn + ni * 8 + g + s];
#pragma unroll
                    for (int mi2 = 0; mi2 < 4; mi2++)
                        mma_fp16(acc[mi2][ni][0], acc[mi2][ni][1],
                                 acc[mi2][ni][2], acc[mi2][ni][3],
                                 af[mi2].x, af[mi2].y, af[mi2].z, af[mi2].w, b0, b1);
                }
            }
        }
    }
#pragma unroll
    for (int mi2 = 0; mi2 < 4; mi2++) {
        int co0 = (mi2 >> 1) * 64 + w2 * 32 + (mi2 & 1) * 16 + g;
        int co1 = co0 + 8;
        float bv0 = bias[co0], bv1 = bias[co1];
        __half* p0 = out + ((size_t)b * 768 + outOff + co0) * HW + y * WW;
        __half* p1 = out + ((size_t)b * 768 + outOff + co1) * HW + y * WW;
#pragma unroll
        for (int ni = 0; ni < 4; ni++) {
            int x0 = wn + ni * 8 + 2 * t;
            *(__half2*)&p0[x0] = __floats2half2_rn(acc[mi2][ni][0] + bv0, acc[mi2][ni][1] + bv0);
            *(__half2*)&p1[x0] = __floats2half2_rn(acc[mi2][ni][2] + bv1, acc[mi2][ni][3] + bv1);
        }
    }
}

// ---------------- 1x1 conv (GEMM), M=128 couts per block ----------------
// TI/TO: float or __half. MODE 0: hswish(acc+bias). MODE 1: res(fp32) + bn(acc).
template <int MODE, typename TI, typename TO>
__global__ void __launch_bounds__(256, 2)
gemm1x1_tc(const TI* __restrict__ in, int Cin,
           const uint4* __restrict__ wfrag, int Cout,
           const float* __restrict__ p0, const float* __restrict__ p1,
           const float* __restrict__ p2, const float* __restrict__ p3,
           const float* __restrict__ res, TO* __restrict__ out) {
    __shared__ uint4 Af[256];              // [cbHalf][w2][mi][lane]
    __shared__ uint32_t Ish[8][136];       // [k-pair][col] half2
    int tid = threadIdx.x;
    int lane = tid & 31, warp = tid >> 5;
    int g = lane >> 2, t = lane & 3;
    int w2 = warp >> 2;
    int wn = (warp & 3) * 32;
    int nbase = blockIdx.x * 128;
    int cbBase = blockIdx.y * 2;
    int b = blockIdx.z;
    int nk = Cin >> 4;
    const TI* inB = in + (size_t)b * Cin * HW + nbase;
    float acc[4][4][4] = {};

    for (int k016 = 0; k016 < nk; k016++) {
        int k0 = k016 * 16;
        __syncthreads();
        {
            int half = tid >> 7;           // 0/1 -> cbBase / cbBase+1
            int idx = tid & 127;
            Af[tid] = wfrag[((size_t)(cbBase + half) * nk + k016) * 128 + idx];
        }
        {
            int k2 = tid >> 5, p2i = tid & 31;
            if constexpr (sizeof(TI) == 4) {
                const float* r0 = (const float*)inB + (size_t)(k0 + 2 * k2) * HW + p2i * 4;
                float4 v0 = *(const float4*)r0;
                float4 v1 = *(const float4*)(r0 + HW);
                uint4 o;
                o.x = packh2(v0.x, v1.x);
                o.y = packh2(v0.y, v1.y);
                o.z = packh2(v0.z, v1.z);
                o.w = packh2(v0.w, v1.w);
                *(uint4*)&Ish[k2][p2i * 4] = o;
            } else {
                const __half* r0 = (const __half*)inB + (size_t)(k0 + 2 * k2) * HW + p2i * 4;
                uint2 a = *(const uint2*)r0;
                uint2 c = *(const uint2*)(r0 + HW);
                __half2 a0 = *(__half2*)&a.x, a1 = *(__half2*)&a.y;
                __half2 c0 = *(__half2*)&c.x, c1 = *(__half2*)&c.y;
                __half2 t0 = __lows2half2(a0, c0);
                __half2 t1 = __highs2half2(a0, c0);
                __half2 t2 = __lows2half2(a1, c1);
                __half2 t3 = __highs2half2(a1, c1);
                uint4 o;
                o.x = *(uint32_t*)&t0;
                o.y = *(uint32_t*)&t1;
                o.z = *(uint32_t*)&t2;
                o.w = *(uint32_t*)&t3;
                *(uint4*)&Ish[k2][p2i * 4] = o;
            }
        }
        __syncthreads();
        uint4 af[4];
#pragma unroll
        for (int mi2 = 0; mi2 < 4; mi2++)
            af[mi2] = Af[(mi2 >> 1) * 128 + (w2 * 2 + (mi2 & 1)) * 32 + lane];
#pragma unroll
        for (int ni = 0; ni < 4; ni++) {
            uint32_t b0 = Ish[t][wn + ni * 8 + g];
            uint32_t b1 = Ish[t + 4][wn + ni * 8 + g];
#pragma unroll
            for (int mi2 = 0; mi2 < 4; mi2++)
                mma_fp16(acc[mi2][ni][0], acc[mi2][ni][1], acc[mi2][ni][2], acc[mi2][ni][3],
                         af[mi2].x, af[mi2].y, af[mi2].z, af[mi2].w, b0, b1);
        }
    }
    // epilogue
#pragma unroll
    for (int mi2 = 0; mi2 < 4; mi2++) {
        int co0 = (cbBase + (mi2 >> 1)) * 64 + w2 * 32 + (mi2 & 1) * 16 + g;
        int co1 = co0 + 8;
        float b0v = 0.f, b1v = 0.f, sc0 = 0.f, sc1 = 0.f, sh0 = 0.f, sh1 = 0.f;
        if (MODE == 0) {
            b0v = p0[co0];
            b1v = p0[co1];
        } else {
            sc0 = p0[co0] * rsqrtf(p3[co0] + 1e-5f);
            sh0 = p1[co0] - p2[co0] * sc0;
            sc1 = p0[co1] * rsqrtf(p3[co1] + 1e-5f);
            sh1 = p1[co1] - p2[co1] * sc1;
        }
        size_t row0 = ((size_t)b * Cout + co0) * HW + nbase;
        size_t row1 = ((size_t)b * Cout + co1) * HW + nbase;
#pragma unroll
        for (int ni = 0; ni < 4; ni++) {
            int x0 = wn + ni * 8 + 2 * t;
            float v00 = acc[mi2][ni][0], v01 = acc[mi2][ni][1];
            float v10 = acc[mi2][ni][2], v11 = acc[mi2][ni][3];
            if (MODE == 0) {
                v00 = hswish_f(v00 + b0v);
                v01 = hswish_f(v01 + b0v);
                v10 = hswish_f(v10 + b1v);
                v11 = hswish_f(v11 + b1v);
            } else {
                float2 r0 = *(const float2*)&res[row0 + x0];
                float2 r1 = *(const float2*)&res[row1 + x0];
                v00 = v00 * sc0 + sh0 + r0.x;
                v01 = v01 * sc0 + sh0 + r0.y;
                v10 = v10 * sc1 + sh1 + r1.x;
                v11 = v11 * sc1 + sh1 + r1.y;
            }
            if constexpr (sizeof(TO) == 4) {
                *(float2*)&((float*)out)[row0 + x0] = make_float2(v00, v01);
                *(float2*)&((float*)out)[row1 + x0] = make_float2(v10, v11);
            } else {
                *(__half2*)&((__half*)out)[row0 + x0] = __floats2half2_rn(v00, v01);
                *(__half2*)&((__half*)out)[row1 + x0] = __floats2half2_rn(v10, v11);
            }
        }
    }
}

// ---------------- 5x5 depthwise on multi channels 0..383 -> msdw (fp16 io) ----------------
__global__ void dw5x5_k(const __half* __restrict__ in, const float* __restrict__ wgt,
                        __half* __restrict__ out) {
    __shared__ float sh[5][136];
    int x = threadIdx.x;
    int y = blockIdx.x;
    int c = blockIdx.y;
    int b = blockIdx.z;
    const __half* inC = in + ((size_t)b * 768 + c) * HW;
    for (int r = 0; r < 5; r++) {
        int yy = y - 2 + r;
        for (int i = x; i < 132; i += 128) {
            int xx = i - 2;
            float v = 0.f;
            if (yy >= 0 && yy < HH && xx >= 0 && xx < WW) v = __half2float(inC[yy * WW + xx]);
            sh[r][i] = v;
        }
    }
    __syncthreads();
    const float* wc = wgt + c * 25;
    float a = 0.f;
#pragma unroll
    for (int r = 0; r < 5; r++)
#pragma unroll
        for (int s = 0; s < 5; s++)
            a += wc[r * 5 + s] * sh[r][x + s];
    out[((size_t)b * 384 + c) * HW + y * WW + x] = __float2half(a);
}

// ---------------- grouped 1x1, 8->8 per group, 48 groups (fp16 io) ----------------
__global__ void pw_group_k(const __half* __restrict__ in, const float* __restrict__ wgt,
                           __half* __restrict__ out) {
    __shared__ float wsh[64];
    int g = blockIdx.y;
    int b = blockIdx.z;
    if (threadIdx.x < 64) wsh[threadIdx.x] = wgt[g * 64 + threadIdx.x];
    __syncthreads();
    int n = blockIdx.x * 128 + threadIdx.x;
    const __half* ip = in + ((size_t)b * 384 + g * 8) * HW + n;
    float xi[8];
#pragma unroll
    for (int i = 0; i < 8; i++) xi[i] = __half2float(ip[(size_t)i * HW]);
    __half* op = out + ((size_t)b * 768 + 384 + g * 8) * HW + n;
#pragma unroll
    for (int o = 0; o < 8; o++) {
        float a = 0.f;
#pragma unroll
        for (int i = 0; i < 8; i++) a += wsh[o * 8 + i] * xi[i];
        op[(size_t)o * HW] = __float2half(a);
    }
}

// ---------------- zero kv accumulators ----------------
__global__ void zero_kv_k(float* __restrict__ kv) {
    int i = blockIdx.x * 256 + threadIdx.x;
    if (i < BB * 32 * 72) kv[i] = 0.f;
}

// ---------------- attention phase 1 (fp16 in) ----------------
__global__ void attn_kv_k(const __half* __restrict__ multi, float* __restrict__ kv) {
    int b = blockIdx.z, g = blockIdx.y;
    const __half* base = multi + ((size_t)b * 768 + g * 24) * HW;
    int n0 = blockIdx.x * 2048;
    float acc[72];
#pragma unroll
    for (int i = 0; i < 72; i++) acc[i] = 0.f;
    for (int n = n0 + threadIdx.x; n < n0 + 2048; n += 256) {
        float kq[8], vv[8];
#pragma unroll
        for (int j = 0; j < 8; j++) kq[j] = fmaxf(__half2float(base[(size_t)(8 + j) * HW + n]), 0.f);
#pragma unroll
        for (int e = 0; e < 8; e++) vv[e] = __half2float(base[(size_t)(16 + e) * HW + n]);
#pragma unroll
        for (int e = 0; e < 8; e++)
#pragma unroll
            for (int j = 0; j < 8; j++) acc[e * 8 + j] += vv[e] * kq[j];
#pragma unroll
        for (int j = 0; j < 8; j++) acc[64 + j] += kq[j];
    }
    __shared__ float red[72][8];
    int lane = threadIdx.x & 31, warp = threadIdx.x >> 5;
#pragma unroll
    for (int i = 0; i < 72; i++) {
        float v = acc[i];
        v += __shfl_down_sync(0xffffffffu, v, 16);
        v += __shfl_down_sync(0xffffffffu, v, 8);
        v += __shfl_down_sync(0xffffffffu, v, 4);
        v += __shfl_down_sync(0xffffffffu, v, 2);
        v += __shfl_down_sync(0xffffffffu, v, 1);
        if (lane == 0) red[i][warp] = v;
    }
    __syncthreads();
    if (threadIdx.x < 72) {
        float s = 0.f;
#pragma unroll
        for (int w = 0; w < 8; w++) s += red[threadIdx.x][w];
        atomicAdd(&kv[((size_t)b * 32 + g) * 72 + threadIdx.x], s);
    }
}

// ---------------- attention phase 2 (fp16 io) ----------------
__global__ void attn_apply_k(const __half* __restrict__ multi, const float* __restrict__ kv,
                             __half* __restrict__ att) {
    int b = blockIdx.z, g = blockIdx.y;
    __shared__ float kvs[72];
    if (threadIdx.x < 72) kvs[threadIdx.x] = kv[((size_t)b * 32 + g) * 72 + threadIdx.x];
    __syncthreads();
    int n = blockIdx.x * 256 + threadIdx.x;
    const __half* base = multi + ((size_t)b * 768 + g * 24) * HW + n;
    float q[8];
#pragma unroll
    for (int j = 0; j < 8; j++) q[j] = fmaxf(__half2float(base[(size_t)j * HW]), 0.f);
    float denom = 0.f;
#pragma unroll
    for (int j = 0; j < 8; j++) denom += kvs[64 + j] * q[j];
    float inv = 1.f / (denom + 1e-15f);
    __half* op = att + ((size_t)b * 256 + g * 8) * HW + n;
#pragma unroll
    for (int e = 0; e < 8; e++) {
        float s = 0.f;
#pragma unroll
        for (int j = 0; j < 8; j++) s += kvs[e * 8 + j] * q[j];
        op[(size_t)e * HW] = __float2half(s * inv);
    }
}

// ---------------- 3x3 depthwise + bias + hswish (fp16 io) ----------------
__global__ void dw3x3_k(const __half* __restrict__ in, const float* __restrict__ wgt,
                        const float* __restrict__ bias, __half* __restrict__ out) {
    __shared__ float sh[3][136];
    int x = threadIdx.x, y = blockIdx.x, c = blockIdx.y, b = blockIdx.z;
    const __half* inC = in + ((size_t)b * 768 + c) * HW;
    for (int r = 0; r < 3; r++) {
        int yy = y - 1 + r;
        for (int i = x; i < 130; i += 128) {
            int xx = i - 1;
            float v = 0.f;
            if (yy >= 0 && yy < HH && xx >= 0 && xx < WW) v = __half2float(inC[yy * WW + xx]);
            sh[r][i] = v;
        }
    }
    __syncthreads();
    const float* wc = wgt + c * 9;
    float a = bias[c];
#pragma unroll
    for (int r = 0; r < 3; r++)
#pragma unroll
        for (int s = 0; s < 3; s++)
            a += wc[r * 3 + s] * sh[r][x + s];
    out[((size_t)b * 768 + c) * HW + y * WW + x] = __float2half(hswish_f(a));
}

// ---------------- launch ----------------
extern "C" void kernel_launch(void* const* d_in, const int* in_sizes, int n_in,
                              void* d_out, int out_size) {
    const float* ref = (const float*)d_in[0];
    const float* oth = (const float*)d_in[1];
    const float* wq = (const float*)d_in[2];
    const float* bq = (const float*)d_in[3];
    const float* wk = (const float*)d_in[4];
    const float* bk = (const float*)d_in[5];
    const float* wv = (const float*)d_in[6];
    const float* bv = (const float*)d_in[7];
    const float* agg_dw_w = (const float*)d_in[8];
    const float* agg_pw_w = (const float*)d_in[9];
    const float* attn_proj_w = (const float*)d_in[10];
    const float* bn1_g = (const float*)d_in[11];
    const float* bn1_b = (const float*)d_in[12];
    const float* bn1_m = (const float*)d_in[13];
    const float* bn1_v = (const float*)d_in[14];
    const float* mb1_w = (const float*)d_in[15];
    const float* mb1_b = (const float*)d_in[16];
    const float* mb2_w = (const float*)d_in[17];
    const float* mb2_b = (const float*)d_in[18];
    const float* mb3_w = (const float*)d_in[19];
    const float* bn2_g = (const float*)d_in[20];
    const float* bn2_b = (const float*)d_in[21];
    const float* bn2_m = (const float*)d_in[22];
    const float* bn2_v = (const float*)d_in[23];

    __half *multi, *msdw, *att, *h1, *h2;
    float *attended, *kv, *wT;
    cudaGetSymbolAddress((void**)&multi, g_multi);
    cudaGetSymbolAddress((void**)&msdw, g_msdw);
    cudaGetSymbolAddress((void**)&att, g_att);
    cudaGetSymbolAddress((void**)&attended, g_attended);
    cudaGetSymbolAddress((void**)&h1, g_h1);
    cudaGetSymbolAddress((void**)&h2, g_h2);
    cudaGetSymbolAddress((void**)&kv, g_kv);
    cudaGetSymbolAddress((void**)&wT, g_wT);
    uint4* fr4 = (uint4*)wT;

    // one-time weight fragment packing (fp16, mma m16n8k16 fragment order)
    prep_conv_frag_h<<<72, 256>>>(wq, fr4 + FQ);
    prep_conv_frag_h<<<72, 256>>>(wk, fr4 + FK);
    prep_conv_frag_h<<<72, 256>>>(wv, fr4 + FV);
    prep_gemm_frag_h<<<16, 256>>>(attn_proj_w, fr4 + FP, 256, 128);
    prep_gemm_frag_h<<<48, 256>>>(mb1_w, fr4 + F1, 128, 768);
    prep_gemm_frag_h<<<48, 256>>>(mb3_w, fr4 + F3, 768, 128);

    // fused q,k,v 3x3 convs (M=128/block) -> multi channels 0/128/256 (fp16)
    conv3x3_tc<<<dim3(128, 3, 4), 256>>>(ref, oth, fr4 + FQ, bq, bk, bv, multi);

    // aggregation: 5x5 dw then grouped 1x1 -> multi channels 384..767 (fp16)
    dw5x5_k<<<dim3(128, 384, 4), 128>>>(multi, agg_dw_w, msdw);
    pw_group_k<<<dim3(128, 48, 4), 128>>>(msdw, agg_pw_w, multi);

    // relu linear attention (fp16 io, fp32 accum)
    zero_kv_k<<<(BB * 32 * 72 + 255) / 256, 256>>>(kv);
    attn_kv_k<<<dim3(8, 32, 4), 256>>>(multi, kv);
    attn_apply_k<<<dim3(64, 32, 4), 256>>>(multi, kv, att);

    // attn_proj + bn1 + residual(ref fp32) -> attended (fp32)
    gemm1x1_tc<1, __half, float><<<dim3(128, 1, 4), 256>>>(
        att, 256, fr4 + FP, 128, bn1_g, bn1_b, bn1_m, bn1_v, ref, attended);

    // MBConv
    gemm1x1_tc<0, float, __half><<<dim3(128, 6, 4), 256>>>(
        attended, 128, fr4 + F1, 768, mb1_b, nullptr, nullptr, nullptr, nullptr, h1);
    dw3x3_k<<<dim3(128, 768, 4), 128>>>(h1, mb2_w, mb2_b, h2);
    gemm1x1_tc<1, __half, float><<<dim3(128, 1, 4), 256>>>(
        h2, 768, fr4 + F3, 128, bn2_g, bn2_b, bn2_m, bn2_v, attended, (float*)d_out);
}

// round 12
// speedup vs baseline: 2.1248x; 1.2145x over previous
#include <cuda_runtime.h>
#include <cuda_fp16.h>
#include <cstdint>
#include <cstddef>

#define HH 128
#define WW 128
#define HW 16384
#define BB 4

// ---------------- scratch (static device globals; no allocation) ----------------
__device__ __half g_multi[(size_t)BB * 768 * HW];   // qkv (0..383) + ms (384..767)
__device__ __half g_msdw[(size_t)BB * 384 * HW];    // depthwise 5x5 output
__device__ __half g_att[(size_t)BB * 256 * HW];     // attention output
__device__ float  g_attended[(size_t)BB * 128 * HW];// residual branch point (fp32)
__device__ __half g_h1[(size_t)BB * 768 * HW];      // mb1 output
__device__ __half g_h2[(size_t)BB * 768 * HW];      // mb2 output
__device__ float  g_kv[(size_t)BB * 32 * 72];       // per-(b,g) 9x8 kv matrices
__device__ float  g_wT[768 * 1152];                 // fragment-packed fp16 weights (uint4 view)

// fragment-region offsets in uint4 units
#define FQ 0
#define FK 18432
#define FV 36864
#define FP 55296
#define F1 59392
#define F3 71680

// ---------------- fp16 mma helpers ----------------
__device__ __forceinline__ uint32_t packh2(float a, float b) {
    __half2 h = __floats2half2_rn(a, b);
    return *(uint32_t*)&h;
}

__device__ __forceinline__ void mma_fp16(float& d0, float& d1, float& d2, float& d3,
                                         uint32_t a0, uint32_t a1, uint32_t a2, uint32_t a3,
                                         uint32_t b0, uint32_t b1) {
    asm volatile(
        "mma.sync.aligned.m16n8k16.row.col.f32.f16.f16.f32 "
        "{%0,%1,%2,%3},{%4,%5,%6,%7},{%8,%9},{%0,%1,%2,%3};"
        : "+f"(d0), "+f"(d1), "+f"(d2), "+f"(d3)
        : "r"(a0), "r"(a1), "r"(a2), "r"(a3), "r"(b0), "r"(b1));
}

__device__ __forceinline__ float hswish_f(float x) {
    return x * fminf(fmaxf(x + 3.f, 0.f), 6.f) * (1.f / 6.f);
}

// ---------------- prep: conv weights -> fp16 fragment-packed uint4 ----------------
__global__ void prep_conv_frag_h(const float* __restrict__ w, uint4* __restrict__ out) {
    int j = blockIdx.x * 256 + threadIdx.x;   // 0..18431
    int lane = j & 31, mi = (j >> 5) & 1, w2 = (j >> 6) & 1;
    int r3 = j >> 7;
    int rs = r3 % 9;
    int tmp = r3 / 9;
    int c016 = tmp & 7;
    int cb2 = tmp >> 3;
    int g = lane >> 2, t = lane & 3;
    int m = cb2 * 64 + w2 * 32 + mi * 16 + g;
    int k0 = c016 * 16 + 2 * t;
    uint4 u;
    u.x = packh2(w[((size_t)m * 128 + k0) * 9 + rs],       w[((size_t)m * 128 + k0 + 1) * 9 + rs]);
    u.y = packh2(w[((size_t)(m + 8) * 128 + k0) * 9 + rs], w[((size_t)(m + 8) * 128 + k0 + 1) * 9 + rs]);
    u.z = packh2(w[((size_t)m * 128 + k0 + 8) * 9 + rs],   w[((size_t)m * 128 + k0 + 9) * 9 + rs]);
    u.w = packh2(w[((size_t)(m + 8) * 128 + k0 + 8) * 9 + rs], w[((size_t)(m + 8) * 128 + k0 + 9) * 9 + rs]);
    out[j] = u;
}

// ---------------- prep: 1x1 weights -> fp16 fragment-packed uint4 ----------------
__global__ void prep_gemm_frag_h(const float* __restrict__ w, uint4* __restrict__ out,
                                 int Cin, int Cout) {
    int j = blockIdx.x * 256 + threadIdx.x;
    if (j >= (Cin * Cout) / 8) return;
    int lane = j & 31, mi = (j >> 5) & 1, w2 = (j >> 6) & 1;
    int rest = j >> 7;
    int nk = Cin >> 4;
    int k016 = rest % nk;
    int cb = rest / nk;
    int g = lane >> 2, t = lane & 3;
    int m = cb * 64 + w2 * 32 + mi * 16 + g;
    int k0 = k016 * 16 + 2 * t;
    uint4 u;
    u.x = packh2(w[(size_t)m * Cin + k0],       w[(size_t)m * Cin + k0 + 1]);
    u.y = packh2(w[(size_t)(m + 8) * Cin + k0], w[(size_t)(m + 8) * Cin + k0 + 1]);
    u.z = packh2(w[(size_t)m * Cin + k0 + 8],   w[(size_t)m * Cin + k0 + 9]);
    u.w = packh2(w[(size_t)(m + 8) * Cin + k0 + 8], w[(size_t)(m + 8) * Cin + k0 + 9]);
    out[j] = u;
}

// ---------------- fused 3x3 convs (q,k,v), M=128 couts per block ----------------
__global__ void __launch_bounds__(256, 2)
conv3x3_tc(const float* __restrict__ ref, const float* __restrict__ oth,
           const uint4* __restrict__ wfragAll,
           const float* __restrict__ bq, const float* __restrict__ bk,
           const float* __restrict__ bv, __half* __restrict__ out) {
    __shared__ uint4 Afrag[2304];          // [cb2][rs][w2][mi][lane]
    __shared__ uint32_t Ish[8][3][136];    // [ch-pair][row3][col(-1..128)] half2
    int tid = threadIdx.x;
    int lane = tid & 31, warp = tid >> 5;
    int g = lane >> 2, t = lane & 3;
    int w2 = warp >> 2;
    int wn = (warp & 3) * 32;
    int y = blockIdx.x;
    int cv = blockIdx.y;
    int b = blockIdx.z;
    const float* in = (cv == 0) ? ref : oth;
    const uint4* wf = wfragAll + (size_t)cv * 18432;
    const float* bias = (cv == 0) ? bq : (cv == 1) ? bk : bv;
    int outOff = cv * 128;
    const float* inB = in + (size_t)b * 128 * HW;
    float acc[4][4][4] = {};

    for (int c016 = 0; c016 < 8; c016++) {
        int c0 = c016 * 16;
        __syncthreads();
        for (int j = tid; j < 1152; j += 256) {
            Afrag[j] = wf[c016 * 1152 + j];
            Afrag[j + 1152] = wf[9216 + c016 * 1152 + j];
        }
        {
            const float* inC0 = inB + (size_t)(c0 + 2 * warp) * HW;
            const float* inC1 = inC0 + HW;
#pragma unroll
            for (int r = 0; r < 3; r++) {
                int yy = y - 1 + r;
                for (int col = lane; col < 130; col += 32) {
                    int xx = col - 1;
                    float v0 = 0.f, v1 = 0.f;
                    if (xx >= 0 && xx < WW && yy >= 0 && yy < HH) {
                        v0 = inC0[yy * WW + xx];
                        v1 = inC1[yy * WW + xx];
                    }
                    Ish[warp][r][col] = packh2(v0, v1);
                }
            }
        }
        __syncthreads();
#pragma unroll
        for (int r = 0; r < 3; r++) {
#pragma unroll
            for (int s = 0; s < 3; s++) {
                int rs = r * 3 + s;
                uint4 af[4];
#pragma unroll
                for (int mi2 = 0; mi2 < 4; mi2++)
                    af[mi2] = Afrag[(mi2 >> 1) * 1152 +
                                    ((rs * 2 + w2) * 2 + (mi2 & 1)) * 32 + lane];
#pragma unroll
                for (int ni = 0; ni < 4; ni++) {
                    uint32_t b0 = Ish[t][r][wn + ni * 8 + g + s];
                    uint32_t b1 = Ish[t + 4][r][wn + ni * 8 + g + s];
#pragma unroll
                    for (int mi2 = 0; mi2 < 4; mi2++)
                        mma_fp16(acc[mi2][ni][0], acc[mi2][ni][1],
                                 acc[mi2][ni][2], acc[mi2][ni][3],
                                 af[mi2].x, af[mi2].y, af[mi2].z, af[mi2].w, b0, b1);
                }
            }
        }
    }
#pragma unroll
    for (int mi2 = 0; mi2 < 4; mi2++) {
        int co0 = (mi2 >> 1) * 64 + w2 * 32 + (mi2 & 1) * 16 + g;
        int co1 = co0 + 8;
        float bv0 = bias[co0], bv1 = bias[co1];
        __half* p0 = out + ((size_t)b * 768 + outOff + co0) * HW + y * WW;
        __half* p1 = out + ((size_t)b * 768 + outOff + co1) * HW + y * WW;
#pragma unroll
        for (int ni = 0; ni < 4; ni++) {
            int x0 = wn + ni * 8 + 2 * t;
            *(__half2*)&p0[x0] = __floats2half2_rn(acc[mi2][ni][0] + bv0, acc[mi2][ni][1] + bv0);
            *(__half2*)&p1[x0] = __floats2half2_rn(acc[mi2][ni][2] + bv1, acc[mi2][ni][3] + bv1);
        }
    }
}

// ---------------- 1x1 conv (GEMM), M=128 couts per block ----------------
template <int MODE, typename TI, typename TO>
__global__ void __launch_bounds__(256, 2)
gemm1x1_tc(const TI* __restrict__ in, int Cin,
           const uint4* __restrict__ wfrag, int Cout,
           const float* __restrict__ p0, const float* __restrict__ p1,
           const float* __restrict__ p2, const float* __restrict__ p3,
           const float* __restrict__ res, TO* __restrict__ out) {
    __shared__ uint4 Af[256];              // [cbHalf][w2][mi][lane]
    __shared__ uint32_t Ish[8][136];       // [k-pair][col] half2
    int tid = threadIdx.x;
    int lane = tid & 31, warp = tid >> 5;
    int g = lane >> 2, t = lane & 3;
    int w2 = warp >> 2;
    int wn = (warp & 3) * 32;
    int nbase = blockIdx.x * 128;
    int cbBase = blockIdx.y * 2;
    int b = blockIdx.z;
    int nk = Cin >> 4;
    const TI* inB = in + (size_t)b * Cin * HW + nbase;
    float acc[4][4][4] = {};

    for (int k016 = 0; k016 < nk; k016++) {
        int k0 = k016 * 16;
        __syncthreads();
        {
            int half = tid >> 7;
            int idx = tid & 127;
            Af[tid] = wfrag[((size_t)(cbBase + half) * nk + k016) * 128 + idx];
        }
        {
            int k2 = tid >> 5, p2i = tid & 31;
            if constexpr (sizeof(TI) == 4) {
                const float* r0 = (const float*)inB + (size_t)(k0 + 2 * k2) * HW + p2i * 4;
                float4 v0 = *(const float4*)r0;
                float4 v1 = *(const float4*)(r0 + HW);
                uint4 o;
                o.x = packh2(v0.x, v1.x);
                o.y = packh2(v0.y, v1.y);
                o.z = packh2(v0.z, v1.z);
                o.w = packh2(v0.w, v1.w);
                *(uint4*)&Ish[k2][p2i * 4] = o;
            } else {
                const __half* r0 = (const __half*)inB + (size_t)(k0 + 2 * k2) * HW + p2i * 4;
                uint2 a = *(const uint2*)r0;
                uint2 c = *(const uint2*)(r0 + HW);
                __half2 a0 = *(__half2*)&a.x, a1 = *(__half2*)&a.y;
                __half2 c0 = *(__half2*)&c.x, c1 = *(__half2*)&c.y;
                __half2 t0 = __lows2half2(a0, c0);
                __half2 t1 = __highs2half2(a0, c0);
                __half2 t2 = __lows2half2(a1, c1);
                __half2 t3 = __highs2half2(a1, c1);
                uint4 o;
                o.x = *(uint32_t*)&t0;
                o.y = *(uint32_t*)&t1;
                o.z = *(uint32_t*)&t2;
                o.w = *(uint32_t*)&t3;
                *(uint4*)&Ish[k2][p2i * 4] = o;
            }
        }
        __syncthreads();
        uint4 af[4];
#pragma unroll
        for (int mi2 = 0; mi2 < 4; mi2++)
            af[mi2] = Af[(mi2 >> 1) * 128 + (w2 * 2 + (mi2 & 1)) * 32 + lane];
#pragma unroll
        for (int ni = 0; ni < 4; ni++) {
            uint32_t b0 = Ish[t][wn + ni * 8 + g];
            uint32_t b1 = Ish[t + 4][wn + ni * 8 + g];
#pragma unroll
            for (int mi2 = 0; mi2 < 4; mi2++)
                mma_fp16(acc[mi2][ni][0], acc[mi2][ni][1], acc[mi2][ni][2], acc[mi2][ni][3],
                         af[mi2].x, af[mi2].y, af[mi2].z, af[mi2].w, b0, b1);
        }
    }
    // epilogue
#pragma unroll
    for (int mi2 = 0; mi2 < 4; mi2++) {
        int co0 = (cbBase + (mi2 >> 1)) * 64 + w2 * 32 + (mi2 & 1) * 16 + g;
        int co1 = co0 + 8;
        float b0v = 0.f, b1v = 0.f, sc0 = 0.f, sc1 = 0.f, sh0 = 0.f, sh1 = 0.f;
        if (MODE == 0) {
            b0v = p0[co0];
            b1v = p0[co1];
        } else {
            sc0 = p0[co0] * rsqrtf(p3[co0] + 1e-5f);
            sh0 = p1[co0] - p2[co0] * sc0;
            sc1 = p0[co1] * rsqrtf(p3[co1] + 1e-5f);
            sh1 = p1[co1] - p2[co1] * sc1;
        }
        size_t row0 = ((size_t)b * Cout + co0) * HW + nbase;
        size_t row1 = ((size_t)b * Cout + co1) * HW + nbase;
#pragma unroll
        for (int ni = 0; ni < 4; ni++) {
            int x0 = wn + ni * 8 + 2 * t;
            float v00 = acc[mi2][ni][0], v01 = acc[mi2][ni][1];
            float v10 = acc[mi2][ni][2], v11 = acc[mi2][ni][3];
            if (MODE == 0) {
                v00 = hswish_f(v00 + b0v);
                v01 = hswish_f(v01 + b0v);
                v10 = hswish_f(v10 + b1v);
                v11 = hswish_f(v11 + b1v);
            } else {
                float2 r0 = *(const float2*)&res[row0 + x0];
                float2 r1 = *(const float2*)&res[row1 + x0];
                v00 = v00 * sc0 + sh0 + r0.x;
                v01 = v01 * sc0 + sh0 + r0.y;
                v10 = v10 * sc1 + sh1 + r1.x;
                v11 = v11 * sc1 + sh1 + r1.y;
            }
            if constexpr (sizeof(TO) == 4) {
                *(float2*)&((float*)out)[row0 + x0] = make_float2(v00, v01);
                *(float2*)&((float*)out)[row1 + x0] = make_float2(v10, v11);
            } else {
                *(__half2*)&((__half*)out)[row0 + x0] = __floats2half2_rn(v00, v01);
                *(__half2*)&((__half*)out)[row1 + x0] = __floats2half2_rn(v10, v11);
            }
        }
    }
}

// ---------------- 5x5 depthwise, 8 rows per block (fp16 io) ----------------
__global__ void dw5x5_k(const __half* __restrict__ in, const float* __restrict__ wgt,
                        __half* __restrict__ out) {
    __shared__ float sh[12][136];
    int tid = threadIdx.x;
    int warp = tid >> 5, lane = tid & 31;
    int y0 = blockIdx.x * 8;
    int c = blockIdx.y;
    int b = blockIdx.z;
    const __half* inC = in + ((size_t)b * 768 + c) * HW;
    for (int rr = warp; rr < 12; rr += 8) {
        int yy = y0 - 2 + rr;
        for (int col = lane; col < 132; col += 32) {
            int xx = col - 2;
            float v = 0.f;
            if (yy >= 0 && yy < HH && xx >= 0 && xx < WW) v = __half2float(inC[yy * WW + xx]);
            sh[rr][col] = v;
        }
    }
    __syncthreads();
    float wreg[25];
#pragma unroll
    for (int i = 0; i < 25; i++) wreg[i] = wgt[c * 25 + i];
    __half* oC = out + ((size_t)b * 384 + c) * HW;
#pragma unroll
    for (int p = 0; p < 4; p++) {
        int px = tid + p * 256;
        int ry = px >> 7, x = px & 127;
        float a = 0.f;
#pragma unroll
        for (int r = 0; r < 5; r++)
#pragma unroll
            for (int s = 0; s < 5; s++)
                a += wreg[r * 5 + s] * sh[ry + r][x + s];
        oC[(y0 + ry) * WW + x] = __float2half(a);
    }
}

// ---------------- grouped 1x1, 8->8 per group, 48 groups (fp16 io) ----------------
__global__ void pw_group_k(const __half* __restrict__ in, const float* __restrict__ wgt,
                           __half* __restrict__ out) {
    __shared__ float wsh[64];
    int g = blockIdx.y;
    int b = blockIdx.z;
    if (threadIdx.x < 64) wsh[threadIdx.x] = wgt[g * 64 + threadIdx.x];
    __syncthreads();
    int n = blockIdx.x * 128 + threadIdx.x;
    const __half* ip = in + ((size_t)b * 384 + g * 8) * HW + n;
    float xi[8];
#pragma unroll
    for (int i = 0; i < 8; i++) xi[i] = __half2float(ip[(size_t)i * HW]);
    __half* op = out + ((size_t)b * 768 + 384 + g * 8) * HW + n;
#pragma unroll
    for (int o = 0; o < 8; o++) {
        float a = 0.f;
#pragma unroll
        for (int i = 0; i < 8; i++) a += wsh[o * 8 + i] * xi[i];
        op[(size_t)o * HW] = __float2half(a);
    }
}

// ---------------- zero kv accumulators ----------------
__global__ void zero_kv_k(float* __restrict__ kv) {
    int i = blockIdx.x * 256 + threadIdx.x;
    if (i < BB * 32 * 72) kv[i] = 0.f;
}

// ---------------- attention phase 1 (fp16 in) ----------------
__global__ void attn_kv_k(const __half* __restrict__ multi, float* __restrict__ kv) {
    int b = blockIdx.z, g = blockIdx.y;
    const __half* base = multi + ((size_t)b * 768 + g * 24) * HW;
    int n0 = blockIdx.x * 2048;
    float acc[72];
#pragma unroll
    for (int i = 0; i < 72; i++) acc[i] = 0.f;
    for (int n = n0 + threadIdx.x; n < n0 + 2048; n += 256) {
        float kq[8], vv[8];
#pragma unroll
        for (int j = 0; j < 8; j++) kq[j] = fmaxf(__half2float(base[(size_t)(8 + j) * HW + n]), 0.f);
#pragma unroll
        for (int e = 0; e < 8; e++) vv[e] = __half2float(base[(size_t)(16 + e) * HW + n]);
#pragma unroll
        for (int e = 0; e < 8; e++)
#pragma unroll
            for (int j = 0; j < 8; j++) acc[e * 8 + j] += vv[e] * kq[j];
#pragma unroll
        for (int j = 0; j < 8; j++) acc[64 + j] += kq[j];
    }
    __shared__ float red[72][8];
    int lane = threadIdx.x & 31, warp = threadIdx.x >> 5;
#pragma unroll
    for (int i = 0; i < 72; i++) {
        float v = acc[i];
        v += __shfl_down_sync(0xffffffffu, v, 16);
        v += __shfl_down_sync(0xffffffffu, v, 8);
        v += __shfl_down_sync(0xffffffffu, v, 4);
        v += __shfl_down_sync(0xffffffffu, v, 2);
        v += __shfl_down_sync(0xffffffffu, v, 1);
        if (lane == 0) red[i][warp] = v;
    }
    __syncthreads();
    if (threadIdx.x < 72) {
        float s = 0.f;
#pragma unroll
        for (int w = 0; w < 8; w++) s += red[threadIdx.x][w];
        atomicAdd(&kv[((size_t)b * 32 + g) * 72 + threadIdx.x], s);
    }
}

// ---------------- attention phase 2 (fp16 io) ----------------
__global__ void attn_apply_k(const __half* __restrict__ multi, const float* __restrict__ kv,
                             __half* __restrict__ att) {
    int b = blockIdx.z, g = blockIdx.y;
    __shared__ float kvs[72];
    if (threadIdx.x < 72) kvs[threadIdx.x] = kv[((size_t)b * 32 + g) * 72 + threadIdx.x];
    __syncthreads();
    int n = blockIdx.x * 256 + threadIdx.x;
    const __half* base = multi + ((size_t)b * 768 + g * 24) * HW + n;
    float q[8];
#pragma unroll
    for (int j = 0; j < 8; j++) q[j] = fmaxf(__half2float(base[(size_t)j * HW]), 0.f);
    float denom = 0.f;
#pragma unroll
    for (int j = 0; j < 8; j++) denom += kvs[64 + j] * q[j];
    float inv = 1.f / (denom + 1e-15f);
    __half* op = att + ((size_t)b * 256 + g * 8) * HW + n;
#pragma unroll
    for (int e = 0; e < 8; e++) {
        float s = 0.f;
#pragma unroll
        for (int j = 0; j < 8; j++) s += kvs[e * 8 + j] * q[j];
        op[(size_t)e * HW] = __float2half(s * inv);
    }
}

// ---------------- 3x3 depthwise + bias + hswish, 8 rows per block (fp16 io) ----------------
__global__ void dw3x3_k(const __half* __restrict__ in, const float* __restrict__ wgt,
                        const float* __restrict__ bias, __half* __restrict__ out) {
    __shared__ float sh[10][136];
    int tid = threadIdx.x;
    int warp = tid >> 5, lane = tid & 31;
    int y0 = blockIdx.x * 8;
    int c = blockIdx.y;
    int b = blockIdx.z;
    const __half* inC = in + ((size_t)b * 768 + c) * HW;
    for (int rr = warp; rr < 10; rr += 8) {
        int yy = y0 - 1 + rr;
        for (int col = lane; col < 130; col += 32) {
            int xx = col - 1;
            float v = 0.f;
            if (yy >= 0 && yy < HH && xx >= 0 && xx < WW) v = __half2float(inC[yy * WW + xx]);
            sh[rr][col] = v;
        }
    }
    __syncthreads();
    float wreg[9];
#pragma unroll
    for (int i = 0; i < 9; i++) wreg[i] = wgt[c * 9 + i];
    float bv = bias[c];
    __half* oC = out + ((size_t)b * 768 + c) * HW;
#pragma unroll
    for (int p = 0; p < 4; p++) {
        int px = tid + p * 256;
        int ry = px >> 7, x = px & 127;
        float a = bv;
#pragma unroll
        for (int r = 0; r < 3; r++)
#pragma unroll
            for (int s = 0; s < 3; s++)
                a += wreg[r * 3 + s] * sh[ry + r][x + s];
        oC[(y0 + ry) * WW + x] = __float2half(hswish_f(a));
    }
}

// ---------------- launch ----------------
extern "C" void kernel_launch(void* const* d_in, const int* in_sizes, int n_in,
                              void* d_out, int out_size) {
    const float* ref = (const float*)d_in[0];
    const float* oth = (const float*)d_in[1];
    const float* wq = (const float*)d_in[2];
    const float* bq = (const float*)d_in[3];
    const float* wk = (const float*)d_in[4];
    const float* bk = (const float*)d_in[5];
    const float* wv = (const float*)d_in[6];
    const float* bv = (const float*)d_in[7];
    const float* agg_dw_w = (const float*)d_in[8];
    const float* agg_pw_w = (const float*)d_in[9];
    const float* attn_proj_w = (const float*)d_in[10];
    const float* bn1_g = (const float*)d_in[11];
    const float* bn1_b = (const float*)d_in[12];
    const float* bn1_m = (const float*)d_in[13];
    const float* bn1_v = (const float*)d_in[14];
    const float* mb1_w = (const float*)d_in[15];
    const float* mb1_b = (const float*)d_in[16];
    const float* mb2_w = (const float*)d_in[17];
    const float* mb2_b = (const float*)d_in[18];
    const float* mb3_w = (const float*)d_in[19];
    const float* bn2_g = (const float*)d_in[20];
    const float* bn2_b = (const float*)d_in[21];
    const float* bn2_m = (const float*)d_in[22];
    const float* bn2_v = (const float*)d_in[23];

    __half *multi, *msdw, *att, *h1, *h2;
    float *attended, *kv, *wT;
    cudaGetSymbolAddress((void**)&multi, g_multi);
    cudaGetSymbolAddress((void**)&msdw, g_msdw);
    cudaGetSymbolAddress((void**)&att, g_att);
    cudaGetSymbolAddress((void**)&attended, g_attended);
    cudaGetSymbolAddress((void**)&h1, g_h1);
    cudaGetSymbolAddress((void**)&h2, g_h2);
    cudaGetSymbolAddress((void**)&kv, g_kv);
    cudaGetSymbolAddress((void**)&wT, g_wT);
    uint4* fr4 = (uint4*)wT;

    // one-time weight fragment packing (fp16, mma m16n8k16 fragment order)
    prep_conv_frag_h<<<72, 256>>>(wq, fr4 + FQ);
    prep_conv_frag_h<<<72, 256>>>(wk, fr4 + FK);
    prep_conv_frag_h<<<72, 256>>>(wv, fr4 + FV);
    prep_gemm_frag_h<<<16, 256>>>(attn_proj_w, fr4 + FP, 256, 128);
    prep_gemm_frag_h<<<48, 256>>>(mb1_w, fr4 + F1, 128, 768);
    prep_gemm_frag_h<<<48, 256>>>(mb3_w, fr4 + F3, 768, 128);

    // fused q,k,v 3x3 convs (M=128/block) -> multi channels 0/128/256 (fp16)
    conv3x3_tc<<<dim3(128, 3, 4), 256>>>(ref, oth, fr4 + FQ, bq, bk, bv, multi);

    // aggregation: 5x5 dw (8 rows/block) then grouped 1x1 -> multi channels 384..767
    dw5x5_k<<<dim3(16, 384, 4), 256>>>(multi, agg_dw_w, msdw);
    pw_group_k<<<dim3(128, 48, 4), 128>>>(msdw, agg_pw_w, multi);

    // relu linear attention (fp16 io, fp32 accum)
    zero_kv_k<<<(BB * 32 * 72 + 255) / 256, 256>>>(kv);
    attn_kv_k<<<dim3(8, 32, 4), 256>>>(multi, kv);
    attn_apply_k<<<dim3(64, 32, 4), 256>>>(multi, kv, att);

    // attn_proj + bn1 + residual(ref fp32) -> attended (fp32)
    gemm1x1_tc<1, __half, float><<<dim3(128, 1, 4), 256>>>(
        att, 256, fr4 + FP, 128, bn1_g, bn1_b, bn1_m, bn1_v, ref, attended);

    // MBConv
    gemm1x1_tc<0, float, __half><<<dim3(128, 6, 4), 256>>>(
        attended, 128, fr4 + F1, 768, mb1_b, nullptr, nullptr, nullptr, nullptr, h1);
    dw3x3_k<<<dim3(16, 768, 4), 256>>>(h1, mb2_w, mb2_b, h2);
    gemm1x1_tc<1, __half, float><<<dim3(128, 1, 4), 256>>>(
        h2, 768, fr4 + F3, 128, bn2_g, bn2_b, bn2_m, bn2_v, attended, (float*)d_out);
}

// round 13
// speedup vs baseline: 2.1942x; 1.0326x over previous
#include <cuda_runtime.h>
#include <cuda_fp16.h>
#include <cstdint>
#include <cstddef>

#define HH 128
#define WW 128
#define HW 16384
#define BB 4

// ---------------- scratch (static device globals; no allocation) ----------------
__device__ __half g_multi[(size_t)BB * 768 * HW];   // qkv (0..383) + ms (384..767)
__device__ __half g_msdw[(size_t)BB * 384 * HW];    // depthwise 5x5 output
__device__ __half g_att[(size_t)BB * 256 * HW];     // attention output
__device__ float  g_attended[(size_t)BB * 128 * HW];// residual branch point (fp32)
__device__ __half g_h1[(size_t)BB * 768 * HW];      // mb1 output
__device__ __half g_h2[(size_t)BB * 768 * HW];      // mb2 output
__device__ float  g_kv[(size_t)BB * 32 * 72];       // per-(b,g) 9x8 kv matrices
__device__ float  g_wT[768 * 1152];                 // fragment-packed fp16 weights (uint4 view)

// fragment-region offsets in uint4 units
#define FQ 0
#define FK 18432
#define FV 36864
#define FP 55296
#define F1 59392
#define F3 71680

// conv dynamic smem: Afrag [2][2304] uint4 + Ish [2][8*3*136] uint32
#define CONV_SMEM (2 * 2304 * 16 + 2 * 3264 * 4)

// ---------------- fp16 mma helpers ----------------
__device__ __forceinline__ uint32_t packh2(float a, float b) {
    __half2 h = __floats2half2_rn(a, b);
    return *(uint32_t*)&h;
}

__device__ __forceinline__ void mma_fp16(float& d0, float& d1, float& d2, float& d3,
                                         uint32_t a0, uint32_t a1, uint32_t a2, uint32_t a3,
                                         uint32_t b0, uint32_t b1) {
    asm volatile(
        "mma.sync.aligned.m16n8k16.row.col.f32.f16.f16.f32 "
        "{%0,%1,%2,%3},{%4,%5,%6,%7},{%8,%9},{%0,%1,%2,%3};"
        : "+f"(d0), "+f"(d1), "+f"(d2), "+f"(d3)
        : "r"(a0), "r"(a1), "r"(a2), "r"(a3), "r"(b0), "r"(b1));
}

__device__ __forceinline__ float hswish_f(float x) {
    return x * fminf(fmaxf(x + 3.f, 0.f), 6.f) * (1.f / 6.f);
}

// ---------------- prep: 3 conv weight sets -> fp16 fragment-packed uint4 ----------------
__global__ void prep_conv_frag_h3(const float* __restrict__ wq, const float* __restrict__ wk,
                                  const float* __restrict__ wv, uint4* __restrict__ out) {
    int which = blockIdx.y;
    const float* w = (which == 0) ? wq : (which == 1) ? wk : wv;
    uint4* o = out + (size_t)which * 18432;
    int j = blockIdx.x * 256 + threadIdx.x;   // 0..18431
    int lane = j & 31, mi = (j >> 5) & 1, w2 = (j >> 6) & 1;
    int r3 = j >> 7;
    int rs = r3 % 9;
    int tmp = r3 / 9;
    int c016 = tmp & 7;
    int cb2 = tmp >> 3;
    int g = lane >> 2, t = lane & 3;
    int m = cb2 * 64 + w2 * 32 + mi * 16 + g;
    int k0 = c016 * 16 + 2 * t;
    uint4 u;
    u.x = packh2(w[((size_t)m * 128 + k0) * 9 + rs],       w[((size_t)m * 128 + k0 + 1) * 9 + rs]);
    u.y = packh2(w[((size_t)(m + 8) * 128 + k0) * 9 + rs], w[((size_t)(m + 8) * 128 + k0 + 1) * 9 + rs]);
    u.z = packh2(w[((size_t)m * 128 + k0 + 8) * 9 + rs],   w[((size_t)m * 128 + k0 + 9) * 9 + rs]);
    u.w = packh2(w[((size_t)(m + 8) * 128 + k0 + 8) * 9 + rs], w[((size_t)(m + 8) * 128 + k0 + 9) * 9 + rs]);
    o[j] = u;
}

// ---------------- prep: 1x1 weights -> fp16 fragment-packed uint4 ----------------
__global__ void prep_gemm_frag_h(const float* __restrict__ w, uint4* __restrict__ out,
                                 int Cin, int Cout) {
    int j = blockIdx.x * 256 + threadIdx.x;
    if (j >= (Cin * Cout) / 8) return;
    int lane = j & 31, mi = (j >> 5) & 1, w2 = (j >> 6) & 1;
    int rest = j >> 7;
    int nk = Cin >> 4;
    int k016 = rest % nk;
    int cb = rest / nk;
    int g = lane >> 2, t = lane & 3;
    int m = cb * 64 + w2 * 32 + mi * 16 + g;
    int k0 = k016 * 16 + 2 * t;
    uint4 u;
    u.x = packh2(w[(size_t)m * Cin + k0],       w[(size_t)m * Cin + k0 + 1]);
    u.y = packh2(w[(size_t)(m + 8) * Cin + k0], w[(size_t)(m + 8) * Cin + k0 + 1]);
    u.z = packh2(w[(size_t)m * Cin + k0 + 8],   w[(size_t)m * Cin + k0 + 9]);
    u.w = packh2(w[(size_t)(m + 8) * Cin + k0 + 8], w[(size_t)(m + 8) * Cin + k0 + 9]);
    out[j] = u;
}

// ---------------- fused 3x3 convs (q,k,v), M=128/block, 2-stage pipeline ----------------
__global__ void __launch_bounds__(256, 2)
conv3x3_tc(const float* __restrict__ ref, const float* __restrict__ oth,
           const uint4* __restrict__ wfragAll,
           const float* __restrict__ bq, const float* __restrict__ bk,
           const float* __restrict__ bv, __half* __restrict__ out) {
    extern __shared__ char smem_raw[];
    uint4* AfragB = (uint4*)smem_raw;                        // [2][2304]
    uint32_t* IshB = (uint32_t*)(smem_raw + 2 * 2304 * 16);  // [2][8*3*136]
    int tid = threadIdx.x;
    int lane = tid & 31, warp = tid >> 5;
    int g = lane >> 2, t = lane & 3;
    int w2 = warp >> 2;
    int wn = (warp & 3) * 32;
    int y = blockIdx.x;
    int cv = blockIdx.y;
    int b = blockIdx.z;
    const float* in = (cv == 0) ? ref : oth;
    const uint4* wf = wfragAll + (size_t)cv * 18432;
    const float* bias = (cv == 0) ? bq : (cv == 1) ? bk : bv;
    int outOff = cv * 128;
    const float* inB = in + (size_t)b * 128 * HW;
    float acc[4][4][4] = {};

    auto loadStage = [&](int c016, int buf) {
        uint4* A = AfragB + buf * 2304;
        uint32_t* I = IshB + buf * 3264;
        for (int j = tid; j < 1152; j += 256) {
            A[j] = wf[c016 * 1152 + j];
            A[j + 1152] = wf[9216 + c016 * 1152 + j];
        }
        const float* inC0 = inB + (size_t)(c016 * 16 + 2 * warp) * HW;
        const float* inC1 = inC0 + HW;
#pragma unroll
        for (int r = 0; r < 3; r++) {
            int yy = y - 1 + r;
            for (int col = lane; col < 130; col += 32) {
                int xx = col - 1;
                float v0 = 0.f, v1 = 0.f;
                if (xx >= 0 && xx < WW && yy >= 0 && yy < HH) {
                    v0 = inC0[yy * WW + xx];
                    v1 = inC1[yy * WW + xx];
                }
                I[(warp * 3 + r) * 136 + col] = packh2(v0, v1);
            }
        }
    };

    loadStage(0, 0);
    for (int c016 = 0; c016 < 8; c016++) {
        __syncthreads();
        if (c016 < 7) loadStage(c016 + 1, (c016 + 1) & 1);
        const uint4* A = AfragB + (c016 & 1) * 2304;
        const uint32_t* I = IshB + (c016 & 1) * 3264;
#pragma unroll
        for (int r = 0; r < 3; r++) {
#pragma unroll
            for (int s = 0; s < 3; s++) {
                int rs = r * 3 + s;
                uint4 af[4];
#pragma unroll
                for (int mi2 = 0; mi2 < 4; mi2++)
                    af[mi2] = A[(mi2 >> 1) * 1152 +
                                ((rs * 2 + w2) * 2 + (mi2 & 1)) * 32 + lane];
#pragma unroll
                for (int ni = 0; ni < 4; ni++) {
                    uint32_t b0 = I[(t * 3 + r) * 136 + wn + ni * 8 + g + s];
                    uint32_t b1 = I[((t + 4) * 3 + r) * 136 + wn + ni * 8 + g + s];
#pragma unroll
                    for (int mi2 = 0; mi2 < 4; mi2++)
                        mma_fp16(acc[mi2][ni][0], acc[mi2][ni][1],
                                 acc[mi2][ni][2], acc[mi2][ni][3],
                                 af[mi2].x, af[mi2].y, af[mi2].z, af[mi2].w, b0, b1);
                }
            }
        }
    }
#pragma unroll
    for (int mi2 = 0; mi2 < 4; mi2++) {
        int co0 = (mi2 >> 1) * 64 + w2 * 32 + (mi2 & 1) * 16 + g;
        int co1 = co0 + 8;
        float bv0 = bias[co0], bv1 = bias[co1];
        __half* p0 = out + ((size_t)b * 768 + outOff + co0) * HW + y * WW;
        __half* p1 = out + ((size_t)b * 768 + outOff + co1) * HW + y * WW;
#pragma unroll
        for (int ni = 0; ni < 4; ni++) {
            int x0 = wn + ni * 8 + 2 * t;
            *(__half2*)&p0[x0] = __floats2half2_rn(acc[mi2][ni][0] + bv0, acc[mi2][ni][1] + bv0);
            *(__half2*)&p1[x0] = __floats2half2_rn(acc[mi2][ni][2] + bv1, acc[mi2][ni][3] + bv1);
        }
    }
}

// ---------------- 1x1 conv (GEMM), M=128/block, 2-stage pipeline ----------------
template <int MODE, typename TI, typename TO>
__global__ void __launch_bounds__(256, 2)
gemm1x1_tc(const TI* __restrict__ in, int Cin,
           const uint4* __restrict__ wfrag, int Cout,
           const float* __restrict__ p0, const float* __restrict__ p1,
           const float* __restrict__ p2, const float* __restrict__ p3,
           const float* __restrict__ res, TO* __restrict__ out) {
    __shared__ uint4 Af[2][256];           // [stage][cbHalf][w2][mi][lane]
    __shared__ uint32_t Ish[2][8][136];    // [stage][k-pair][col] half2
    int tid = threadIdx.x;
    int lane = tid & 31, warp = tid >> 5;
    int g = lane >> 2, t = lane & 3;
    int w2 = warp >> 2;
    int wn = (warp & 3) * 32;
    int nbase = blockIdx.x * 128;
    int cbBase = blockIdx.y * 2;
    int b = blockIdx.z;
    int nk = Cin >> 4;
    const TI* inB = in + (size_t)b * Cin * HW + nbase;
    float acc[4][4][4] = {};

    auto loadStage = [&](int k016, int buf) {
        int half = tid >> 7;
        int idx = tid & 127;
        Af[buf][tid] = wfrag[((size_t)(cbBase + half) * nk + k016) * 128 + idx];
        int k0 = k016 * 16;
        int k2 = tid >> 5, p2i = tid & 31;
        if constexpr (sizeof(TI) == 4) {
            const float* r0 = (const float*)inB + (size_t)(k0 + 2 * k2) * HW + p2i * 4;
            float4 v0 = *(const float4*)r0;
            float4 v1 = *(const float4*)(r0 + HW);
            uint4 o;
            o.x = packh2(v0.x, v1.x);
            o.y = packh2(v0.y, v1.y);
            o.z = packh2(v0.z, v1.z);
            o.w = packh2(v0.w, v1.w);
            *(uint4*)&Ish[buf][k2][p2i * 4] = o;
        } else {
            const __half* r0 = (const __half*)inB + (size_t)(k0 + 2 * k2) * HW + p2i * 4;
            uint2 a = *(const uint2*)r0;
            uint2 c = *(const uint2*)(r0 + HW);
            __half2 a0 = *(__half2*)&a.x, a1 = *(__half2*)&a.y;
            __half2 c0 = *(__half2*)&c.x, c1 = *(__half2*)&c.y;
            __half2 t0 = __lows2half2(a0, c0);
            __half2 t1 = __highs2half2(a0, c0);
            __half2 t2 = __lows2half2(a1, c1);
            __half2 t3 = __highs2half2(a1, c1);
            uint4 o;
            o.x = *(uint32_t*)&t0;
            o.y = *(uint32_t*)&t1;
            o.z = *(uint32_t*)&t2;
            o.w = *(uint32_t*)&t3;
            *(uint4*)&Ish[buf][k2][p2i * 4] = o;
        }
    };

    loadStage(0, 0);
    for (int k016 = 0; k016 < nk; k016++) {
        __syncthreads();
        if (k016 + 1 < nk) loadStage(k016 + 1, (k016 + 1) & 1);
        int buf = k016 & 1;
        uint4 af[4];
#pragma unroll
        for (int mi2 = 0; mi2 < 4; mi2++)
            af[mi2] = Af[buf][(mi2 >> 1) * 128 + (w2 * 2 + (mi2 & 1)) * 32 + lane];
#pragma unroll
        for (int ni = 0; ni < 4; ni++) {
            uint32_t b0 = Ish[buf][t][wn + ni * 8 + g];
            uint32_t b1 = Ish[buf][t + 4][wn + ni * 8 + g];
#pragma unroll
            for (int mi2 = 0; mi2 < 4; mi2++)
                mma_fp16(acc[mi2][ni][0], acc[mi2][ni][1], acc[mi2][ni][2], acc[mi2][ni][3],
                         af[mi2].x, af[mi2].y, af[mi2].z, af[mi2].w, b0, b1);
        }
    }
    // epilogue
#pragma unroll
    for (int mi2 = 0; mi2 < 4; mi2++) {
        int co0 = (cbBase + (mi2 >> 1)) * 64 + w2 * 32 + (mi2 & 1) * 16 + g;
        int co1 = co0 + 8;
        float b0v = 0.f, b1v = 0.f, sc0 = 0.f, sc1 = 0.f, sh0 = 0.f, sh1 = 0.f;
        if (MODE == 0) {
            b0v = p0[co0];
            b1v = p0[co1];
        } else {
            sc0 = p0[co0] * rsqrtf(p3[co0] + 1e-5f);
            sh0 = p1[co0] - p2[co0] * sc0;
            sc1 = p0[co1] * rsqrtf(p3[co1] + 1e-5f);
            sh1 = p1[co1] - p2[co1] * sc1;
        }
        size_t row0 = ((size_t)b * Cout + co0) * HW + nbase;
        size_t row1 = ((size_t)b * Cout + co1) * HW + nbase;
#pragma unroll
        for (int ni = 0; ni < 4; ni++) {
            int x0 = wn + ni * 8 + 2 * t;
            float v00 = acc[mi2][ni][0], v01 = acc[mi2][ni][1];
            float v10 = acc[mi2][ni][2], v11 = acc[mi2][ni][3];
            if (MODE == 0) {
                v00 = hswish_f(v00 + b0v);
                v01 = hswish_f(v01 + b0v);
                v10 = hswish_f(v10 + b1v);
                v11 = hswish_f(v11 + b1v);
            } else {
                float2 r0 = *(const float2*)&res[row0 + x0];
                float2 r1 = *(const float2*)&res[row1 + x0];
                v00 = v00 * sc0 + sh0 + r0.x;
                v01 = v01 * sc0 + sh0 + r0.y;
                v10 = v10 * sc1 + sh1 + r1.x;
                v11 = v11 * sc1 + sh1 + r1.y;
            }
            if constexpr (sizeof(TO) == 4) {
                *(float2*)&((float*)out)[row0 + x0] = make_float2(v00, v01);
                *(float2*)&((float*)out)[row1 + x0] = make_float2(v10, v11);
            } else {
                *(__half2*)&((__half*)out)[row0 + x0] = __floats2half2_rn(v00, v01);
                *(__half2*)&((__half*)out)[row1 + x0] = __floats2half2_rn(v10, v11);
            }
        }
    }
}

// ---------------- 5x5 depthwise, 8 rows per block (fp16 io) ----------------
__global__ void dw5x5_k(const __half* __restrict__ in, const float* __restrict__ wgt,
                        __half* __restrict__ out) {
    __shared__ float sh[12][136];
    int tid = threadIdx.x;
    int warp = tid >> 5, lane = tid & 31;
    int y0 = blockIdx.x * 8;
    int c = blockIdx.y;
    int b = blockIdx.z;
    const __half* inC = in + ((size_t)b * 768 + c) * HW;
    for (int rr = warp; rr < 12; rr += 8) {
        int yy = y0 - 2 + rr;
        for (int col = lane; col < 132; col += 32) {
            int xx = col - 2;
            float v = 0.f;
            if (yy >= 0 && yy < HH && xx >= 0 && xx < WW) v = __half2float(inC[yy * WW + xx]);
            sh[rr][col] = v;
        }
    }
    __syncthreads();
    float wreg[25];
#pragma unroll
    for (int i = 0; i < 25; i++) wreg[i] = wgt[c * 25 + i];
    __half* oC = out + ((size_t)b * 384 + c) * HW;
#pragma unroll
    for (int p = 0; p < 4; p++) {
        int px = tid + p * 256;
        int ry = px >> 7, x = px & 127;
        float a = 0.f;
#pragma unroll
        for (int r = 0; r < 5; r++)
#pragma unroll
            for (int s = 0; s < 5; s++)
                a += wreg[r * 5 + s] * sh[ry + r][x + s];
        oC[(y0 + ry) * WW + x] = __float2half(a);
    }
}

// ---------------- grouped 1x1, 8->8 per group, 48 groups (fp16 io) ----------------
__global__ void pw_group_k(const __half* __restrict__ in, const float* __restrict__ wgt,
                           __half* __restrict__ out) {
    __shared__ float wsh[64];
    int g = blockIdx.y;
    int b = blockIdx.z;
    if (threadIdx.x < 64) wsh[threadIdx.x] = wgt[g * 64 + threadIdx.x];
    __syncthreads();
    int n = blockIdx.x * 128 + threadIdx.x;
    const __half* ip = in + ((size_t)b * 384 + g * 8) * HW + n;
    float xi[8];
#pragma unroll
    for (int i = 0; i < 8; i++) xi[i] = __half2float(ip[(size_t)i * HW]);
    __half* op = out + ((size_t)b * 768 + 384 + g * 8) * HW + n;
#pragma unroll
    for (int o = 0; o < 8; o++) {
        float a = 0.f;
#pragma unroll
        for (int i = 0; i < 8; i++) a += wsh[o * 8 + i] * xi[i];
        op[(size_t)o * HW] = __float2half(a);
    }
}

// ---------------- zero kv accumulators ----------------
__global__ void zero_kv_k(float* __restrict__ kv) {
    int i = blockIdx.x * 256 + threadIdx.x;
    if (i < BB * 32 * 72) kv[i] = 0.f;
}

// ---------------- attention phase 1 (fp16 in) ----------------
__global__ void attn_kv_k(const __half* __restrict__ multi, float* __restrict__ kv) {
    int b = blockIdx.z, g = blockIdx.y;
    const __half* base = multi + ((size_t)b * 768 + g * 24) * HW;
    int n0 = blockIdx.x * 2048;
    float acc[72];
#pragma unroll
    for (int i = 0; i < 72; i++) acc[i] = 0.f;
    for (int n = n0 + threadIdx.x; n < n0 + 2048; n += 256) {
        float kq[8], vv[8];
#pragma unroll
        for (int j = 0; j < 8; j++) kq[j] = fmaxf(__half2float(base[(size_t)(8 + j) * HW + n]), 0.f);
#pragma unroll
        for (int e = 0; e < 8; e++) vv[e] = __half2float(base[(size_t)(16 + e) * HW + n]);
#pragma unroll
        for (int e = 0; e < 8; e++)
#pragma unroll
            for (int j = 0; j < 8; j++) acc[e * 8 + j] += vv[e] * kq[j];
#pragma unroll
        for (int j = 0; j < 8; j++) acc[64 + j] += kq[j];
    }
    __shared__ float red[72][8];
    int lane = threadIdx.x & 31, warp = threadIdx.x >> 5;
#pragma unroll
    for (int i = 0; i < 72; i++) {
        float v = acc[i];
        v += __shfl_down_sync(0xffffffffu, v, 16);
        v += __shfl_down_sync(0xffffffffu, v, 8);
        v += __shfl_down_sync(0xffffffffu, v, 4);
        v += __shfl_down_sync(0xffffffffu, v, 2);
        v += __shfl_down_sync(0xffffffffu, v, 1);
        if (lane == 0) red[i][warp] = v;
    }
    __syncthreads();
    if (threadIdx.x < 72) {
        float s = 0.f;
#pragma unroll
        for (int w = 0; w < 8; w++) s += red[threadIdx.x][w];
        atomicAdd(&kv[((size_t)b * 32 + g) * 72 + threadIdx.x], s);
    }
}

// ---------------- attention phase 2 (fp16 io) ----------------
__global__ void attn_apply_k(const __half* __restrict__ multi, const float* __restrict__ kv,
                             __half* __restrict__ att) {
    int b = blockIdx.z, g = blockIdx.y;
    __shared__ float kvs[72];
    if (threadIdx.x < 72) kvs[threadIdx.x] = kv[((size_t)b * 32 + g) * 72 + threadIdx.x];
    __syncthreads();
    int n = blockIdx.x * 256 + threadIdx.x;
    const __half* base = multi + ((size_t)b * 768 + g * 24) * HW + n;
    float q[8];
#pragma unroll
    for (int j = 0; j < 8; j++) q[j] = fmaxf(__half2float(base[(size_t)j * HW]), 0.f);
    float denom = 0.f;
#pragma unroll
    for (int j = 0; j < 8; j++) denom += kvs[64 + j] * q[j];
    float inv = 1.f / (denom + 1e-15f);
    __half* op = att + ((size_t)b * 256 + g * 8) * HW + n;
#pragma unroll
    for (int e = 0; e < 8; e++) {
        float s = 0.f;
#pragma unroll
        for (int j = 0; j < 8; j++) s += kvs[e * 8 + j] * q[j];
        op[(size_t)e * HW] = __float2half(s * inv);
    }
}

// ---------------- 3x3 depthwise + bias + hswish, 8 rows per block (fp16 io) ----------------
__global__ void dw3x3_k(const __half* __restrict__ in, const float* __restrict__ wgt,
                        const float* __restrict__ bias, __half* __restrict__ out) {
    __shared__ float sh[10][136];
    int tid = threadIdx.x;
    int warp = tid >> 5, lane = tid & 31;
    int y0 = blockIdx.x * 8;
    int c = blockIdx.y;
    int b = blockIdx.z;
    const __half* inC = in + ((size_t)b * 768 + c) * HW;
    for (int rr = warp; rr < 10; rr += 8) {
        int yy = y0 - 1 + rr;
        for (int col = lane; col < 130; col += 32) {
            int xx = col - 1;
            float v = 0.f;
            if (yy >= 0 && yy < HH && xx >= 0 && xx < WW) v = __half2float(inC[yy * WW + xx]);
            sh[rr][col] = v;
        }
    }
    __syncthreads();
    float wreg[9];
#pragma unroll
    for (int i = 0; i < 9; i++) wreg[i] = wgt[c * 9 + i];
    float bv = bias[c];
    __half* oC = out + ((size_t)b * 768 + c) * HW;
#pragma unroll
    for (int p = 0; p < 4; p++) {
        int px = tid + p * 256;
        int ry = px >> 7, x = px & 127;
        float a = bv;
#pragma unroll
        for (int r = 0; r < 3; r++)
#pragma unroll
            for (int s = 0; s < 3; s++)
                a += wreg[r * 3 + s] * sh[ry + r][x + s];
        oC[(y0 + ry) * WW + x] = __float2half(hswish_f(a));
    }
}

// ---------------- launch ----------------
extern "C" void kernel_launch(void* const* d_in, const int* in_sizes, int n_in,
                              void* d_out, int out_size) {
    const float* ref = (const float*)d_in[0];
    const float* oth = (const float*)d_in[1];
    const float* wq = (const float*)d_in[2];
    const float* bq = (const float*)d_in[3];
    const float* wk = (const float*)d_in[4];
    const float* bk = (const float*)d_in[5];
    const float* wv = (const float*)d_in[6];
    const float* bv = (const float*)d_in[7];
    const float* agg_dw_w = (const float*)d_in[8];
    const float* agg_pw_w = (const float*)d_in[9];
    const float* attn_proj_w = (const float*)d_in[10];
    const float* bn1_g = (const float*)d_in[11];
    const float* bn1_b = (const float*)d_in[12];
    const float* bn1_m = (const float*)d_in[13];
    const float* bn1_v = (const float*)d_in[14];
    const float* mb1_w = (const float*)d_in[15];
    const float* mb1_b = (const float*)d_in[16];
    const float* mb2_w = (const float*)d_in[17];
    const float* mb2_b = (const float*)d_in[18];
    const float* mb3_w = (const float*)d_in[19];
    const float* bn2_g = (const float*)d_in[20];
    const float* bn2_b = (const float*)d_in[21];
    const float* bn2_m = (const float*)d_in[22];
    const float* bn2_v = (const float*)d_in[23];

    __half *multi, *msdw, *att, *h1, *h2;
    float *attended, *kv, *wT;
    cudaGetSymbolAddress((void**)&multi, g_multi);
    cudaGetSymbolAddress((void**)&msdw, g_msdw);
    cudaGetSymbolAddress((void**)&att, g_att);
    cudaGetSymbolAddress((void**)&attended, g_attended);
    cudaGetSymbolAddress((void**)&h1, g_h1);
    cudaGetSymbolAddress((void**)&h2, g_h2);
    cudaGetSymbolAddress((void**)&kv, g_kv);
    cudaGetSymbolAddress((void**)&wT, g_wT);
    uint4* fr4 = (uint4*)wT;

    static bool attr_set = false;
    if (!attr_set) {
        cudaFuncSetAttribute(conv3x3_tc, cudaFuncAttributeMaxDynamicSharedMemorySize,
                             CONV_SMEM);
        attr_set = true;
    }

    // one-time weight fragment packing (fp16, mma m16n8k16 fragment order)
    prep_conv_frag_h3<<<dim3(72, 3), 256>>>(wq, wk, wv, fr4 + FQ);
    prep_gemm_frag_h<<<16, 256>>>(attn_proj_w, fr4 + FP, 256, 128);
    prep_gemm_frag_h<<<48, 256>>>(mb1_w, fr4 + F1, 128, 768);
    prep_gemm_frag_h<<<48, 256>>>(mb3_w, fr4 + F3, 768, 128);

    // fused q,k,v 3x3 convs (M=128/block, pipelined) -> multi channels 0/128/256
    conv3x3_tc<<<dim3(128, 3, 4), 256, CONV_SMEM>>>(ref, oth, fr4 + FQ, bq, bk, bv, multi);

    // aggregation: 5x5 dw (8 rows/block) then grouped 1x1 -> multi channels 384..767
    dw5x5_k<<<dim3(16, 384, 4), 256>>>(multi, agg_dw_w, msdw);
    pw_group_k<<<dim3(128, 48, 4), 128>>>(msdw, agg_pw_w, multi);

    // relu linear attention (fp16 io, fp32 accum)
    zero_kv_k<<<(BB * 32 * 72 + 255) / 256, 256>>>(kv);
    attn_kv_k<<<dim3(8, 32, 4), 256>>>(multi, kv);
    attn_apply_k<<<dim3(64, 32, 4), 256>>>(multi, kv, att);

    // attn_proj + bn1 + residual(ref fp32) -> attended (fp32)
    gemm1x1_tc<1, __half, float><<<dim3(128, 1, 4), 256>>>(
        att, 256, fr4 + FP, 128, bn1_g, bn1_b, bn1_m, bn1_v, ref, attended);

    // MBConv
    gemm1x1_tc<0, float, __half><<<dim3(128, 6, 4), 256>>>(
        attended, 128, fr4 + F1, 768, mb1_b, nullptr, nullptr, nullptr, nullptr, h1);
    dw3x3_k<<<dim3(16, 768, 4), 256>>>(h1, mb2_w, mb2_b, h2);
    gemm1x1_tc<1, __half, float><<<dim3(128, 1, 4), 256>>>(
        h2, 768, fr4 + F3, 128, bn2_g, bn2_b, bn2_m, bn2_v, attended, (float*)d_out);
}

// round 14
// speedup vs baseline: 2.2148x; 1.0094x over previous
#include <cuda_runtime.h>
#include <cuda_fp16.h>
#include <cstdint>
#include <cstddef>

#define HH 128
#define WW 128
#define HW 16384
#define BB 4

// ---------------- scratch (static device globals; no allocation) ----------------
__device__ __half   g_multi[(size_t)BB * 768 * HW];   // qkv (0..383) + ms (384..767), planar
__device__ __half   g_msdw[(size_t)BB * 384 * HW];    // depthwise 5x5 output, planar
__device__ uint32_t g_atti[(size_t)BB * 128 * HW];    // attention output, half2 pairs
__device__ float    g_attended[(size_t)BB * 128 * HW];// residual branch point (fp32)
__device__ __half   g_h1[(size_t)BB * 768 * HW];      // mb1 output, planar
__device__ uint32_t g_h2i[(size_t)BB * 384 * HW];     // mb2 output, half2 pairs
__device__ float    g_kv[(size_t)BB * 32 * 72];       // per-(b,g) 9x8 kv matrices
__device__ float    g_wT[768 * 1152];                 // fragment-packed fp16 weights (uint4 view)
__device__ uint32_t g_refi[(size_t)BB * 64 * HW];     // ref as half2 channel pairs
__device__ uint32_t g_othi[(size_t)BB * 64 * HW];     // oth as half2 channel pairs

// fragment-region offsets in uint4 units
#define FQ 0
#define FK 18432
#define FV 36864
#define FP 55296
#define F1 59392
#define F3 71680

// conv dynamic smem: Afrag [2][2304] uint4 + Ish [2][8*3*136] uint32
#define CONV_SMEM (2 * 2304 * 16 + 2 * 3264 * 4)

// ---------------- fp16 mma helpers ----------------
__device__ __forceinline__ uint32_t packh2(float a, float b) {
    __half2 h = __floats2half2_rn(a, b);
    return *(uint32_t*)&h;
}

__device__ __forceinline__ void mma_fp16(float& d0, float& d1, float& d2, float& d3,
                                         uint32_t a0, uint32_t a1, uint32_t a2, uint32_t a3,
                                         uint32_t b0, uint32_t b1) {
    asm volatile(
        "mma.sync.aligned.m16n8k16.row.col.f32.f16.f16.f32 "
        "{%0,%1,%2,%3},{%4,%5,%6,%7},{%8,%9},{%0,%1,%2,%3};"
        : "+f"(d0), "+f"(d1), "+f"(d2), "+f"(d3)
        : "r"(a0), "r"(a1), "r"(a2), "r"(a3), "r"(b0), "r"(b1));
}

__device__ __forceinline__ float hswish_f(float x) {
    return x * fminf(fmaxf(x + 3.f, 0.f), 6.f) * (1.f / 6.f);
}

// ---------------- prep: interleave ref/oth into half2 channel-pair planar ----------------
__global__ void prep_interleave(const float* __restrict__ ref, const float* __restrict__ oth,
                                uint32_t* __restrict__ refI, uint32_t* __restrict__ othI) {
    size_t i = (size_t)blockIdx.x * 256 + threadIdx.x;   // 0 .. BB*64*HW-1
    size_t px = i & (HW - 1);
    size_t rest = i >> 14;
    size_t p = rest & 63;
    size_t b = rest >> 6;
    size_t s0 = (b * 128 + 2 * p) * HW + px;
    refI[i] = packh2(ref[s0], ref[s0 + HW]);
    othI[i] = packh2(oth[s0], oth[s0 + HW]);
}

// ---------------- prep: 3 conv weight sets -> fp16 fragment-packed uint4 ----------------
__global__ void prep_conv_frag_h3(const float* __restrict__ wq, const float* __restrict__ wk,
                                  const float* __restrict__ wv, uint4* __restrict__ out) {
    int which = blockIdx.y;
    const float* w = (which == 0) ? wq : (which == 1) ? wk : wv;
    uint4* o = out + (size_t)which * 18432;
    int j = blockIdx.x * 256 + threadIdx.x;   // 0..18431
    int lane = j & 31, mi = (j >> 5) & 1, w2 = (j >> 6) & 1;
    int r3 = j >> 7;
    int rs = r3 % 9;
    int tmp = r3 / 9;
    int c016 = tmp & 7;
    int cb2 = tmp >> 3;
    int g = lane >> 2, t = lane & 3;
    int m = cb2 * 64 + w2 * 32 + mi * 16 + g;
    int k0 = c016 * 16 + 2 * t;
    uint4 u;
    u.x = packh2(w[((size_t)m * 128 + k0) * 9 + rs],       w[((size_t)m * 128 + k0 + 1) * 9 + rs]);
    u.y = packh2(w[((size_t)(m + 8) * 128 + k0) * 9 + rs], w[((size_t)(m + 8) * 128 + k0 + 1) * 9 + rs]);
    u.z = packh2(w[((size_t)m * 128 + k0 + 8) * 9 + rs],   w[((size_t)m * 128 + k0 + 9) * 9 + rs]);
    u.w = packh2(w[((size_t)(m + 8) * 128 + k0 + 8) * 9 + rs], w[((size_t)(m + 8) * 128 + k0 + 9) * 9 + rs]);
    o[j] = u;
}

// ---------------- prep: 1x1 weights -> fp16 fragment-packed uint4 ----------------
__global__ void prep_gemm_frag_h(const float* __restrict__ w, uint4* __restrict__ out,
                                 int Cin, int Cout) {
    int j = blockIdx.x * 256 + threadIdx.x;
    if (j >= (Cin * Cout) / 8) return;
    int lane = j & 31, mi = (j >> 5) & 1, w2 = (j >> 6) & 1;
    int rest = j >> 7;
    int nk = Cin >> 4;
    int k016 = rest % nk;
    int cb = rest / nk;
    int g = lane >> 2, t = lane & 3;
    int m = cb * 64 + w2 * 32 + mi * 16 + g;
    int k0 = k016 * 16 + 2 * t;
    uint4 u;
    u.x = packh2(w[(size_t)m * Cin + k0],       w[(size_t)m * Cin + k0 + 1]);
    u.y = packh2(w[(size_t)(m + 8) * Cin + k0], w[(size_t)(m + 8) * Cin + k0 + 1]);
    u.z = packh2(w[(size_t)m * Cin + k0 + 8],   w[(size_t)m * Cin + k0 + 9]);
    u.w = packh2(w[(size_t)(m + 8) * Cin + k0 + 8], w[(size_t)(m + 8) * Cin + k0 + 9]);
    out[j] = u;
}

// ---------------- fused 3x3 convs (q,k,v), M=128/block, 2-stage pipeline ----------------
__global__ void __launch_bounds__(256, 2)
conv3x3_tc(const uint32_t* __restrict__ refI, const uint32_t* __restrict__ othI,
           const uint4* __restrict__ wfragAll,
           const float* __restrict__ bq, const float* __restrict__ bk,
           const float* __restrict__ bv, __half* __restrict__ out) {
    extern __shared__ char smem_raw[];
    uint4* AfragB = (uint4*)smem_raw;                        // [2][2304]
    uint32_t* IshB = (uint32_t*)(smem_raw + 2 * 2304 * 16);  // [2][8*3*136]
    int tid = threadIdx.x;
    int lane = tid & 31, warp = tid >> 5;
    int g = lane >> 2, t = lane & 3;
    int w2 = warp >> 2;
    int wn = (warp & 3) * 32;
    int y = blockIdx.x;
    int cv = blockIdx.y;
    int b = blockIdx.z;
    const uint32_t* inI = (cv == 0) ? refI : othI;
    const uint4* wf = wfragAll + (size_t)cv * 18432;
    const float* bias = (cv == 0) ? bq : (cv == 1) ? bk : bv;
    int outOff = cv * 128;
    const uint32_t* inB = inI + (size_t)b * 64 * HW;
    float acc[4][4][4] = {};

    auto loadStage = [&](int c016, int buf) {
        uint4* A = AfragB + buf * 2304;
        uint32_t* I = IshB + buf * 3264;
        for (int j = tid; j < 1152; j += 256) {
            A[j] = wf[c016 * 1152 + j];
            A[j + 1152] = wf[9216 + c016 * 1152 + j];
        }
        const uint32_t* inP = inB + (size_t)(c016 * 8 + warp) * HW;
#pragma unroll
        for (int r = 0; r < 3; r++) {
            int yy = y - 1 + r;
            for (int col = lane; col < 130; col += 32) {
                int xx = col - 1;
                uint32_t v = 0u;
                if (xx >= 0 && xx < WW && yy >= 0 && yy < HH)
                    v = inP[yy * WW + xx];
                I[(warp * 3 + r) * 136 + col] = v;
            }
        }
    };

    loadStage(0, 0);
    for (int c016 = 0; c016 < 8; c016++) {
        __syncthreads();
        if (c016 < 7) loadStage(c016 + 1, (c016 + 1) & 1);
        const uint4* A = AfragB + (c016 & 1) * 2304;
        const uint32_t* I = IshB + (c016 & 1) * 3264;
#pragma unroll
        for (int r = 0; r < 3; r++) {
#pragma unroll
            for (int s = 0; s < 3; s++) {
                int rs = r * 3 + s;
                uint4 af[4];
#pragma unroll
                for (int mi2 = 0; mi2 < 4; mi2++)
                    af[mi2] = A[(mi2 >> 1) * 1152 +
                                ((rs * 2 + w2) * 2 + (mi2 & 1)) * 32 + lane];
#pragma unroll
                for (int ni = 0; ni < 4; ni++) {
                    uint32_t b0 = I[(t * 3 + r) * 136 + wn + ni * 8 + g + s];
                    uint32_t b1 = I[((t + 4) * 3 + r) * 136 + wn + ni * 8 + g + s];
#pragma unroll
                    for (int mi2 = 0; mi2 < 4; mi2++)
                        mma_fp16(acc[mi2][ni][0], acc[mi2][ni][1],
                                 acc[mi2][ni][2], acc[mi2][ni][3],
                                 af[mi2].x, af[mi2].y, af[mi2].z, af[mi2].w, b0, b1);
                }
            }
        }
    }
#pragma unroll
    for (int mi2 = 0; mi2 < 4; mi2++) {
        int co0 = (mi2 >> 1) * 64 + w2 * 32 + (mi2 & 1) * 16 + g;
        int co1 = co0 + 8;
        float bv0 = bias[co0], bv1 = bias[co1];
        __half* p0 = out + ((size_t)b * 768 + outOff + co0) * HW + y * WW;
        __half* p1 = out + ((size_t)b * 768 + outOff + co1) * HW + y * WW;
#pragma unroll
        for (int ni = 0; ni < 4; ni++) {
            int x0 = wn + ni * 8 + 2 * t;
            *(__half2*)&p0[x0] = __floats2half2_rn(acc[mi2][ni][0] + bv0, acc[mi2][ni][1] + bv0);
            *(__half2*)&p1[x0] = __floats2half2_rn(acc[mi2][ni][2] + bv1, acc[mi2][ni][3] + bv1);
        }
    }
}

// ---------------- 1x1 conv (GEMM), M=128/block, 2-stage pipeline ----------------
// INKIND: 0 = fp32 planar, 2 = half2 pair-interleaved.  TO: float or __half.
template <int MODE, int INKIND, typename TO>
__global__ void __launch_bounds__(256, 2)
gemm1x1_tc(const void* __restrict__ in, int Cin,
           const uint4* __restrict__ wfrag, int Cout,
           const float* __restrict__ p0, const float* __restrict__ p1,
           const float* __restrict__ p2, const float* __restrict__ p3,
           const float* __restrict__ res, TO* __restrict__ out) {
    __shared__ uint4 Af[2][256];
    __shared__ uint32_t Ish[2][8][136];
    int tid = threadIdx.x;
    int lane = tid & 31, warp = tid >> 5;
    int g = lane >> 2, t = lane & 3;
    int w2 = warp >> 2;
    int wn = (warp & 3) * 32;
    int nbase = blockIdx.x * 128;
    int cbBase = blockIdx.y * 2;
    int b = blockIdx.z;
    int nk = Cin >> 4;
    const float* inF = (const float*)in + (size_t)b * Cin * HW + nbase;
    const uint32_t* inP = (const uint32_t*)in + (size_t)b * (Cin / 2) * HW + nbase;
    float acc[4][4][4] = {};

    auto loadStage = [&](int k016, int buf) {
        int half = tid >> 7;
        int idx = tid & 127;
        Af[buf][tid] = wfrag[((size_t)(cbBase + half) * nk + k016) * 128 + idx];
        int k2 = tid >> 5, p2i = tid & 31;
        if constexpr (INKIND == 0) {
            int k0 = k016 * 16;
            const float* r0 = inF + (size_t)(k0 + 2 * k2) * HW + p2i * 4;
            float4 v0 = *(const float4*)r0;
            float4 v1 = *(const float4*)(r0 + HW);
            uint4 o;
            o.x = packh2(v0.x, v1.x);
            o.y = packh2(v0.y, v1.y);
            o.z = packh2(v0.z, v1.z);
            o.w = packh2(v0.w, v1.w);
            *(uint4*)&Ish[buf][k2][p2i * 4] = o;
        } else {
            const uint32_t* r0 = inP + (size_t)(k016 * 8 + k2) * HW + p2i * 4;
            *(uint4*)&Ish[buf][k2][p2i * 4] = *(const uint4*)r0;
        }
    };

    loadStage(0, 0);
    for (int k016 = 0; k016 < nk; k016++) {
        __syncthreads();
        if (k016 + 1 < nk) loadStage(k016 + 1, (k016 + 1) & 1);
        int buf = k016 & 1;
        uint4 af[4];
#pragma unroll
        for (int mi2 = 0; mi2 < 4; mi2++)
            af[mi2] = Af[buf][(mi2 >> 1) * 128 + (w2 * 2 + (mi2 & 1)) * 32 + lane];
#pragma unroll
        for (int ni = 0; ni < 4; ni++) {
            uint32_t b0 = Ish[buf][t][wn + ni * 8 + g];
            uint32_t b1 = Ish[buf][t + 4][wn + ni * 8 + g];
#pragma unroll
            for (int mi2 = 0; mi2 < 4; mi2++)
                mma_fp16(acc[mi2][ni][0], acc[mi2][ni][1], acc[mi2][ni][2], acc[mi2][ni][3],
                         af[mi2].x, af[mi2].y, af[mi2].z, af[mi2].w, b0, b1);
        }
    }
    // epilogue
#pragma unroll
    for (int mi2 = 0; mi2 < 4; mi2++) {
        int co0 = (cbBase + (mi2 >> 1)) * 64 + w2 * 32 + (mi2 & 1) * 16 + g;
        int co1 = co0 + 8;
        float b0v = 0.f, b1v = 0.f, sc0 = 0.f, sc1 = 0.f, sh0 = 0.f, sh1 = 0.f;
        if (MODE == 0) {
            b0v = p0[co0];
            b1v = p0[co1];
        } else {
            sc0 = p0[co0] * rsqrtf(p3[co0] + 1e-5f);
            sh0 = p1[co0] - p2[co0] * sc0;
            sc1 = p0[co1] * rsqrtf(p3[co1] + 1e-5f);
            sh1 = p1[co1] - p2[co1] * sc1;
        }
        size_t row0 = ((size_t)b * Cout + co0) * HW + nbase;
        size_t row1 = ((size_t)b * Cout + co1) * HW + nbase;
#pragma unroll
        for (int ni = 0; ni < 4; ni++) {
            int x0 = wn + ni * 8 + 2 * t;
            float v00 = acc[mi2][ni][0], v01 = acc[mi2][ni][1];
            float v10 = acc[mi2][ni][2], v11 = acc[mi2][ni][3];
            if (MODE == 0) {
                v00 = hswish_f(v00 + b0v);
                v01 = hswish_f(v01 + b0v);
                v10 = hswish_f(v10 + b1v);
                v11 = hswish_f(v11 + b1v);
            } else {
                float2 r0 = *(const float2*)&res[row0 + x0];
                float2 r1 = *(const float2*)&res[row1 + x0];
                v00 = v00 * sc0 + sh0 + r0.x;
                v01 = v01 * sc0 + sh0 + r0.y;
                v10 = v10 * sc1 + sh1 + r1.x;
                v11 = v11 * sc1 + sh1 + r1.y;
            }
            if constexpr (sizeof(TO) == 4) {
                *(float2*)&((float*)out)[row0 + x0] = make_float2(v00, v01);
                *(float2*)&((float*)out)[row1 + x0] = make_float2(v10, v11);
            } else {
                *(__half2*)&((__half*)out)[row0 + x0] = __floats2half2_rn(v00, v01);
                *(__half2*)&((__half*)out)[row1 + x0] = __floats2half2_rn(v10, v11);
            }
        }
    }
}

// ---------------- 5x5 depthwise, 8 rows per block (fp16 io) ----------------
__global__ void dw5x5_k(const __half* __restrict__ in, const float* __restrict__ wgt,
                        __half* __restrict__ out) {
    __shared__ float sh[12][136];
    int tid = threadIdx.x;
    int warp = tid >> 5, lane = tid & 31;
    int y0 = blockIdx.x * 8;
    int c = blockIdx.y;
    int b = blockIdx.z;
    const __half* inC = in + ((size_t)b * 768 + c) * HW;
    for (int rr = warp; rr < 12; rr += 8) {
        int yy = y0 - 2 + rr;
        for (int col = lane; col < 132; col += 32) {
            int xx = col - 2;
            float v = 0.f;
            if (yy >= 0 && yy < HH && xx >= 0 && xx < WW) v = __half2float(inC[yy * WW + xx]);
            sh[rr][col] = v;
        }
    }
    __syncthreads();
    float wreg[25];
#pragma unroll
    for (int i = 0; i < 25; i++) wreg[i] = wgt[c * 25 + i];
    __half* oC = out + ((size_t)b * 384 + c) * HW;
#pragma unroll
    for (int p = 0; p < 4; p++) {
        int px = tid + p * 256;
        int ry = px >> 7, x = px & 127;
        float a = 0.f;
#pragma unroll
        for (int r = 0; r < 5; r++)
#pragma unroll
            for (int s = 0; s < 5; s++)
                a += wreg[r * 5 + s] * sh[ry + r][x + s];
        oC[(y0 + ry) * WW + x] = __float2half(a);
    }
}

// ---------------- grouped 1x1, 8->8 per group, 48 groups (fp16 io) ----------------
__global__ void pw_group_k(const __half* __restrict__ in, const float* __restrict__ wgt,
                           __half* __restrict__ out) {
    __shared__ float wsh[64];
    int g = blockIdx.y;
    int b = blockIdx.z;
    if (threadIdx.x < 64) wsh[threadIdx.x] = wgt[g * 64 + threadIdx.x];
    __syncthreads();
    int n = blockIdx.x * 128 + threadIdx.x;
    const __half* ip = in + ((size_t)b * 384 + g * 8) * HW + n;
    float xi[8];
#pragma unroll
    for (int i = 0; i < 8; i++) xi[i] = __half2float(ip[(size_t)i * HW]);
    __half* op = out + ((size_t)b * 768 + 384 + g * 8) * HW + n;
#pragma unroll
    for (int o = 0; o < 8; o++) {
        float a = 0.f;
#pragma unroll
        for (int i = 0; i < 8; i++) a += wsh[o * 8 + i] * xi[i];
        op[(size_t)o * HW] = __float2half(a);
    }
}

// ---------------- zero kv accumulators ----------------
__global__ void zero_kv_k(float* __restrict__ kv) {
    int i = blockIdx.x * 256 + threadIdx.x;
    if (i < BB * 32 * 72) kv[i] = 0.f;
}

// ---------------- attention phase 1 (fp16 in) ----------------
__global__ void attn_kv_k(const __half* __restrict__ multi, float* __restrict__ kv) {
    int b = blockIdx.z, g = blockIdx.y;
    const __half* base = multi + ((size_t)b * 768 + g * 24) * HW;
    int n0 = blockIdx.x * 2048;
    float acc[72];
#pragma unroll
    for (int i = 0; i < 72; i++) acc[i] = 0.f;
    for (int n = n0 + threadIdx.x; n < n0 + 2048; n += 256) {
        float kq[8], vv[8];
#pragma unroll
        for (int j = 0; j < 8; j++) kq[j] = fmaxf(__half2float(base[(size_t)(8 + j) * HW + n]), 0.f);
#pragma unroll
        for (int e = 0; e < 8; e++) vv[e] = __half2float(base[(size_t)(16 + e) * HW + n]);
#pragma unroll
        for (int e = 0; e < 8; e++)
#pragma unroll
            for (int j = 0; j < 8; j++) acc[e * 8 + j] += vv[e] * kq[j];
#pragma unroll
        for (int j = 0; j < 8; j++) acc[64 + j] += kq[j];
    }
    __shared__ float red[72][8];
    int lane = threadIdx.x & 31, warp = threadIdx.x >> 5;
#pragma unroll
    for (int i = 0; i < 72; i++) {
        float v = acc[i];
        v += __shfl_down_sync(0xffffffffu, v, 16);
        v += __shfl_down_sync(0xffffffffu, v, 8);
        v += __shfl_down_sync(0xffffffffu, v, 4);
        v += __shfl_down_sync(0xffffffffu, v, 2);
        v += __shfl_down_sync(0xffffffffu, v, 1);
        if (lane == 0) red[i][warp] = v;
    }
    __syncthreads();
    if (threadIdx.x < 72) {
        float s = 0.f;
#pragma unroll
        for (int w = 0; w < 8; w++) s += red[threadIdx.x][w];
        atomicAdd(&kv[((size_t)b * 32 + g) * 72 + threadIdx.x], s);
    }
}

// ---------------- attention phase 2: writes half2-pair interleaved att ----------------
__global__ void attn_apply_k(const __half* __restrict__ multi, const float* __restrict__ kv,
                             uint32_t* __restrict__ attI) {
    int b = blockIdx.z, g = blockIdx.y;
    __shared__ float kvs[72];
    if (threadIdx.x < 72) kvs[threadIdx.x] = kv[((size_t)b * 32 + g) * 72 + threadIdx.x];
    __syncthreads();
    int n = blockIdx.x * 256 + threadIdx.x;
    const __half* base = multi + ((size_t)b * 768 + g * 24) * HW + n;
    float q[8];
#pragma unroll
    for (int j = 0; j < 8; j++) q[j] = fmaxf(__half2float(base[(size_t)j * HW]), 0.f);
    float denom = 0.f;
#pragma unroll
    for (int j = 0; j < 8; j++) denom += kvs[64 + j] * q[j];
    float inv = 1.f / (denom + 1e-15f);
    uint32_t* op = attI + ((size_t)b * 128 + g * 4) * HW + n;
#pragma unroll
    for (int e2 = 0; e2 < 4; e2++) {
        float s0 = 0.f, s1 = 0.f;
#pragma unroll
        for (int j = 0; j < 8; j++) {
            s0 += kvs[(2 * e2) * 8 + j] * q[j];
            s1 += kvs[(2 * e2 + 1) * 8 + j] * q[j];
        }
        op[(size_t)e2 * HW] = packh2(s0 * inv, s1 * inv);
    }
}

// ---------------- 3x3 dw + bias + hswish, channel PAIR per block, half2 out ----------------
__global__ void dw3x3_k(const __half* __restrict__ in, const float* __restrict__ wgt,
                        const float* __restrict__ bias, uint32_t* __restrict__ outI) {
    __shared__ float sh[2][10][136];
    int tid = threadIdx.x;
    int warp = tid >> 5, lane = tid & 31;
    int y0 = blockIdx.x * 8;
    int cp = blockIdx.y;                 // channel pair: channels 2cp, 2cp+1
    int b = blockIdx.z;
    const __half* inC = in + ((size_t)b * 768 + 2 * cp) * HW;
    for (int rr = warp; rr < 20; rr += 8) {
        int ch = rr / 10, row = rr % 10;
        int yy = y0 - 1 + row;
        const __half* ip = inC + (size_t)ch * HW;
        for (int col = lane; col < 130; col += 32) {
            int xx = col - 1;
            float v = 0.f;
            if (yy >= 0 && yy < HH && xx >= 0 && xx < WW) v = __half2float(ip[yy * WW + xx]);
            sh[ch][row][col] = v;
        }
    }
    __syncthreads();
    float w0[9], w1[9];
#pragma unroll
    for (int i = 0; i < 9; i++) {
        w0[i] = wgt[(2 * cp) * 9 + i];
        w1[i] = wgt[(2 * cp + 1) * 9 + i];
    }
    float bv0 = bias[2 * cp], bv1 = bias[2 * cp + 1];
    uint32_t* oC = outI + ((size_t)b * 384 + cp) * HW;
#pragma unroll
    for (int p = 0; p < 4; p++) {
        int px = tid + p * 256;
        int ry = px >> 7, x = px & 127;
        float a0 = bv0, a1 = bv1;
#pragma unroll
        for (int r = 0; r < 3; r++)
#pragma unroll
            for (int s = 0; s < 3; s++) {
                float i0 = sh[0][ry + r][x + s];
                float i1 = sh[1][ry + r][x + s];
                a0 += w0[r * 3 + s] * i0;
                a1 += w1[r * 3 + s] * i1;
            }
        oC[(y0 + ry) * WW + x] = packh2(hswish_f(a0), hswish_f(a1));
    }
}

// ---------------- launch ----------------
extern "C" void kernel_launch(void* const* d_in, const int* in_sizes, int n_in,
                              void* d_out, int out_size) {
    const float* ref = (const float*)d_in[0];
    const float* oth = (const float*)d_in[1];
    const float* wq = (const float*)d_in[2];
    const float* bq = (const float*)d_in[3];
    const float* wk = (const float*)d_in[4];
    const float* bk = (const float*)d_in[5];
    const float* wv = (const float*)d_in[6];
    const float* bv = (const float*)d_in[7];
    const float* agg_dw_w = (const float*)d_in[8];
    const float* agg_pw_w = (const float*)d_in[9];
    const float* attn_proj_w = (const float*)d_in[10];
    const float* bn1_g = (const float*)d_in[11];
    const float* bn1_b = (const float*)d_in[12];
    const float* bn1_m = (const float*)d_in[13];
    const float* bn1_v = (const float*)d_in[14];
    const float* mb1_w = (const float*)d_in[15];
    const float* mb1_b = (const float*)d_in[16];
    const float* mb2_w = (const float*)d_in[17];
    const float* mb2_b = (const float*)d_in[18];
    const float* mb3_w = (const float*)d_in[19];
    const float* bn2_g = (const float*)d_in[20];
    const float* bn2_b = (const float*)d_in[21];
    const float* bn2_m = (const float*)d_in[22];
    const float* bn2_v = (const float*)d_in[23];

    __half *multi, *msdw, *h1;
    uint32_t *atti, *h2i, *refi, *othi;
    float *attended, *kv, *wT;
    cudaGetSymbolAddress((void**)&multi, g_multi);
    cudaGetSymbolAddress((void**)&msdw, g_msdw);
    cudaGetSymbolAddress((void**)&atti, g_atti);
    cudaGetSymbolAddress((void**)&attended, g_attended);
    cudaGetSymbolAddress((void**)&h1, g_h1);
    cudaGetSymbolAddress((void**)&h2i, g_h2i);
    cudaGetSymbolAddress((void**)&kv, g_kv);
    cudaGetSymbolAddress((void**)&wT, g_wT);
    cudaGetSymbolAddress((void**)&refi, g_refi);
    cudaGetSymbolAddress((void**)&othi, g_othi);
    uint4* fr4 = (uint4*)wT;

    static bool attr_set = false;
    if (!attr_set) {
        cudaFuncSetAttribute(conv3x3_tc, cudaFuncAttributeMaxDynamicSharedMemorySize,
                             CONV_SMEM);
        attr_set = true;
    }

    // prep: interleave inputs + weight fragment packing
    prep_interleave<<<BB * 64 * HW / 256, 256>>>(ref, oth, refi, othi);
    prep_conv_frag_h3<<<dim3(72, 3), 256>>>(wq, wk, wv, fr4 + FQ);
    prep_gemm_frag_h<<<16, 256>>>(attn_proj_w, fr4 + FP, 256, 128);
    prep_gemm_frag_h<<<48, 256>>>(mb1_w, fr4 + F1, 128, 768);
    prep_gemm_frag_h<<<48, 256>>>(mb3_w, fr4 + F3, 768, 128);

    // fused q,k,v 3x3 convs (M=128/block, pipelined) -> multi channels 0/128/256
    conv3x3_tc<<<dim3(128, 3, 4), 256, CONV_SMEM>>>(refi, othi, fr4 + FQ, bq, bk, bv, multi);

    // aggregation: 5x5 dw (8 rows/block) then grouped 1x1 -> multi channels 384..767
    dw5x5_k<<<dim3(16, 384, 4), 256>>>(multi, agg_dw_w, msdw);
    pw_group_k<<<dim3(128, 48, 4), 128>>>(msdw, agg_pw_w, multi);

    // relu linear attention (fp16 io, fp32 accum)
    zero_kv_k<<<(BB * 32 * 72 + 255) / 256, 256>>>(kv);
    attn_kv_k<<<dim3(8, 32, 4), 256>>>(multi, kv);
    attn_apply_k<<<dim3(64, 32, 4), 256>>>(multi, kv, atti);

    // attn_proj + bn1 + residual(ref fp32) -> attended (fp32)
    gemm1x1_tc<1, 2, float><<<dim3(128, 1, 4), 256>>>(
        atti, 256, fr4 + FP, 128, bn1_g, bn1_b, bn1_m, bn1_v, ref, attended);

    // MBConv
    gemm1x1_tc<0, 0, __half><<<dim3(128, 6, 4), 256>>>(
        attended, 128, fr4 + F1, 768, mb1_b, nullptr, nullptr, nullptr, nullptr, h1);
    dw3x3_k<<<dim3(16, 384, 4), 256>>>(h1, mb2_w, mb2_b, h2i);
    gemm1x1_tc<1, 2, float><<<dim3(128, 1, 4), 256>>>(
        h2i, 768, fr4 + F3, 128, bn2_g, bn2_b, bn2_m, bn2_v, attended, (float*)d_out);
}

// round 15
// speedup vs baseline: 2.2910x; 1.0344x over previous
#include <cuda_runtime.h>
#include <cuda_fp16.h>
#include <cstdint>
#include <cstddef>

#define HH 128
#define WW 128
#define HW 16384
#define BB 4

// ---------------- scratch (static device globals; no allocation) ----------------
__device__ __half   g_multi[(size_t)BB * 768 * HW];   // qkv (0..383) + ms (384..767), planar
__device__ __half   g_msdw[(size_t)BB * 384 * HW];    // depthwise 5x5 output, planar
__device__ uint32_t g_atti[(size_t)BB * 128 * HW];    // attention output, half2 pairs
__device__ float    g_attended[(size_t)BB * 128 * HW];// residual branch point (fp32)
__device__ __half   g_h1[(size_t)BB * 768 * HW];      // mb1 output, planar
__device__ uint32_t g_h2i[(size_t)BB * 384 * HW];     // mb2 output, half2 pairs
__device__ float    g_kv[(size_t)BB * 32 * 72];       // per-(b,g) 9x8 kv matrices
__device__ float    g_wT[768 * 1152];                 // fragment-packed fp16 weights (uint4 view)
__device__ uint32_t g_refi[(size_t)BB * 64 * HW];     // ref as half2 channel pairs
__device__ uint32_t g_othi[(size_t)BB * 64 * HW];     // oth as half2 channel pairs

// fragment-region offsets in uint4 units
#define FQ 0
#define FK 18432
#define FV 36864
#define FP 55296
#define F1 59392
#define F3 71680

// conv dynamic smem: Afrag [2][2304] uint4 + Ish [2][8*3*136] uint32
#define CONV_SMEM (2 * 2304 * 16 + 2 * 3264 * 4)

// ---------------- fp16 mma helpers ----------------
__device__ __forceinline__ uint32_t packh2(float a, float b) {
    __half2 h = __floats2half2_rn(a, b);
    return *(uint32_t*)&h;
}

__device__ __forceinline__ void mma_fp16(float& d0, float& d1, float& d2, float& d3,
                                         uint32_t a0, uint32_t a1, uint32_t a2, uint32_t a3,
                                         uint32_t b0, uint32_t b1) {
    asm volatile(
        "mma.sync.aligned.m16n8k16.row.col.f32.f16.f16.f32 "
        "{%0,%1,%2,%3},{%4,%5,%6,%7},{%8,%9},{%0,%1,%2,%3};"
        : "+f"(d0), "+f"(d1), "+f"(d2), "+f"(d3)
        : "r"(a0), "r"(a1), "r"(a2), "r"(a3), "r"(b0), "r"(b1));
}

__device__ __forceinline__ float hswish_f(float x) {
    return x * fminf(fmaxf(x + 3.f, 0.f), 6.f) * (1.f / 6.f);
}

// ---------------- prep: interleave ref/oth into half2 channel-pair planar ----------------
__global__ void prep_interleave(const float* __restrict__ ref, const float* __restrict__ oth,
                                uint32_t* __restrict__ refI, uint32_t* __restrict__ othI) {
    size_t i = (size_t)blockIdx.x * 256 + threadIdx.x;
    size_t px = i & (HW - 1);
    size_t rest = i >> 14;
    size_t p = rest & 63;
    size_t b = rest >> 6;
    size_t s0 = (b * 128 + 2 * p) * HW + px;
    refI[i] = packh2(ref[s0], ref[s0 + HW]);
    othI[i] = packh2(oth[s0], oth[s0 + HW]);
}

// ---------------- prep: 3 conv weight sets -> fp16 fragment-packed uint4 ----------------
__global__ void prep_conv_frag_h3(const float* __restrict__ wq, const float* __restrict__ wk,
                                  const float* __restrict__ wv, uint4* __restrict__ out) {
    int which = blockIdx.y;
    const float* w = (which == 0) ? wq : (which == 1) ? wk : wv;
    uint4* o = out + (size_t)which * 18432;
    int j = blockIdx.x * 256 + threadIdx.x;
    int lane = j & 31, mi = (j >> 5) & 1, w2 = (j >> 6) & 1;
    int r3 = j >> 7;
    int rs = r3 % 9;
    int tmp = r3 / 9;
    int c016 = tmp & 7;
    int cb2 = tmp >> 3;
    int g = lane >> 2, t = lane & 3;
    int m = cb2 * 64 + w2 * 32 + mi * 16 + g;
    int k0 = c016 * 16 + 2 * t;
    uint4 u;
    u.x = packh2(w[((size_t)m * 128 + k0) * 9 + rs],       w[((size_t)m * 128 + k0 + 1) * 9 + rs]);
    u.y = packh2(w[((size_t)(m + 8) * 128 + k0) * 9 + rs], w[((size_t)(m + 8) * 128 + k0 + 1) * 9 + rs]);
    u.z = packh2(w[((size_t)m * 128 + k0 + 8) * 9 + rs],   w[((size_t)m * 128 + k0 + 9) * 9 + rs]);
    u.w = packh2(w[((size_t)(m + 8) * 128 + k0 + 8) * 9 + rs], w[((size_t)(m + 8) * 128 + k0 + 9) * 9 + rs]);
    o[j] = u;
}

// ---------------- prep: 1x1 weights -> fp16 fragment-packed uint4 ----------------
__global__ void prep_gemm_frag_h(const float* __restrict__ w, uint4* __restrict__ out,
                                 int Cin, int Cout) {
    int j = blockIdx.x * 256 + threadIdx.x;
    if (j >= (Cin * Cout) / 8) return;
    int lane = j & 31, mi = (j >> 5) & 1, w2 = (j >> 6) & 1;
    int rest = j >> 7;
    int nk = Cin >> 4;
    int k016 = rest % nk;
    int cb = rest / nk;
    int g = lane >> 2, t = lane & 3;
    int m = cb * 64 + w2 * 32 + mi * 16 + g;
    int k0 = k016 * 16 + 2 * t;
    uint4 u;
    u.x = packh2(w[(size_t)m * Cin + k0],       w[(size_t)m * Cin + k0 + 1]);
    u.y = packh2(w[(size_t)(m + 8) * Cin + k0], w[(size_t)(m + 8) * Cin + k0 + 1]);
    u.z = packh2(w[(size_t)m * Cin + k0 + 8],   w[(size_t)m * Cin + k0 + 9]);
    u.w = packh2(w[(size_t)(m + 8) * Cin + k0 + 8], w[(size_t)(m + 8) * Cin + k0 + 9]);
    out[j] = u;
}

// ---------------- fused 3x3 convs (q,k,v), M=128/block, 2-stage pipeline ----------------
__global__ void __launch_bounds__(256, 2)
conv3x3_tc(const uint32_t* __restrict__ refI, const uint32_t* __restrict__ othI,
           const uint4* __restrict__ wfragAll,
           const float* __restrict__ bq, const float* __restrict__ bk,
           const float* __restrict__ bv, __half* __restrict__ out) {
    extern __shared__ char smem_raw[];
    uint4* AfragB = (uint4*)smem_raw;                        // [2][2304]
    uint32_t* IshB = (uint32_t*)(smem_raw + 2 * 2304 * 16);  // [2][8*3*136]
    int tid = threadIdx.x;
    int lane = tid & 31, warp = tid >> 5;
    int g = lane >> 2, t = lane & 3;
    int w2 = warp >> 2;
    int wn = (warp & 3) * 32;
    int y = blockIdx.x;
    int cv = blockIdx.y;
    int b = blockIdx.z;
    const uint32_t* inI = (cv == 0) ? refI : othI;
    const uint4* wf = wfragAll + (size_t)cv * 18432;
    const float* bias = (cv == 0) ? bq : (cv == 1) ? bk : bv;
    int outOff = cv * 128;
    const uint32_t* inB = inI + (size_t)b * 64 * HW;
    float acc[4][4][4] = {};

    auto loadStage = [&](int c016, int buf) {
        uint4* A = AfragB + buf * 2304;
        uint32_t* I = IshB + buf * 3264;
        for (int j = tid; j < 1152; j += 256) {
            A[j] = wf[c016 * 1152 + j];
            A[j + 1152] = wf[9216 + c016 * 1152 + j];
        }
        const uint32_t* inP = inB + (size_t)(c016 * 8 + warp) * HW;
#pragma unroll
        for (int r = 0; r < 3; r++) {
            int yy = y - 1 + r;
            for (int col = lane; col < 130; col += 32) {
                int xx = col - 1;
                uint32_t v = 0u;
                if (xx >= 0 && xx < WW && yy >= 0 && yy < HH)
                    v = inP[yy * WW + xx];
                I[(warp * 3 + r) * 136 + col] = v;
            }
        }
    };

    loadStage(0, 0);
    for (int c016 = 0; c016 < 8; c016++) {
        __syncthreads();
        if (c016 < 7) loadStage(c016 + 1, (c016 + 1) & 1);
        const uint4* A = AfragB + (c016 & 1) * 2304;
        const uint32_t* I = IshB + (c016 & 1) * 3264;
#pragma unroll
        for (int r = 0; r < 3; r++) {
#pragma unroll
            for (int s = 0; s < 3; s++) {
                int rs = r * 3 + s;
                uint4 af[4];
#pragma unroll
                for (int mi2 = 0; mi2 < 4; mi2++)
                    af[mi2] = A[(mi2 >> 1) * 1152 +
                                ((rs * 2 + w2) * 2 + (mi2 & 1)) * 32 + lane];
#pragma unroll
                for (int ni = 0; ni < 4; ni++) {
                    uint32_t b0 = I[(t * 3 + r) * 136 + wn + ni * 8 + g + s];
                    uint32_t b1 = I[((t + 4) * 3 + r) * 136 + wn + ni * 8 + g + s];
#pragma unroll
                    for (int mi2 = 0; mi2 < 4; mi2++)
                        mma_fp16(acc[mi2][ni][0], acc[mi2][ni][1],
                                 acc[mi2][ni][2], acc[mi2][ni][3],
                                 af[mi2].x, af[mi2].y, af[mi2].z, af[mi2].w, b0, b1);
                }
            }
        }
    }
#pragma unroll
    for (int mi2 = 0; mi2 < 4; mi2++) {
        int co0 = (mi2 >> 1) * 64 + w2 * 32 + (mi2 & 1) * 16 + g;
        int co1 = co0 + 8;
        float bv0 = bias[co0], bv1 = bias[co1];
        __half* p0 = out + ((size_t)b * 768 + outOff + co0) * HW + y * WW;
        __half* p1 = out + ((size_t)b * 768 + outOff + co1) * HW + y * WW;
#pragma unroll
        for (int ni = 0; ni < 4; ni++) {
            int x0 = wn + ni * 8 + 2 * t;
            *(__half2*)&p0[x0] = __floats2half2_rn(acc[mi2][ni][0] + bv0, acc[mi2][ni][1] + bv0);
            *(__half2*)&p1[x0] = __floats2half2_rn(acc[mi2][ni][2] + bv1, acc[mi2][ni][3] + bv1);
        }
    }
}

// ---------------- 1x1 conv (GEMM), M=128/block, 2-stage pipeline ----------------
// INKIND: 0 = fp32 planar, 2 = half2 pair-interleaved.  TO: float or __half.
template <int MODE, int INKIND, typename TO>
__global__ void __launch_bounds__(256, 2)
gemm1x1_tc(const void* __restrict__ in, int Cin,
           const uint4* __restrict__ wfrag, int Cout,
           const float* __restrict__ p0, const float* __restrict__ p1,
           const float* __restrict__ p2, const float* __restrict__ p3,
           const float* __restrict__ res, TO* __restrict__ out) {
    __shared__ uint4 Af[2][256];
    __shared__ uint32_t Ish[2][8][136];
    int tid = threadIdx.x;
    int lane = tid & 31, warp = tid >> 5;
    int g = lane >> 2, t = lane & 3;
    int w2 = warp >> 2;
    int wn = (warp & 3) * 32;
    int nbase = blockIdx.x * 128;
    int cbBase = blockIdx.y * 2;
    int b = blockIdx.z;
    int nk = Cin >> 4;
    const float* inF = (const float*)in + (size_t)b * Cin * HW + nbase;
    const uint32_t* inP = (const uint32_t*)in + (size_t)b * (Cin / 2) * HW + nbase;
    float acc[4][4][4] = {};

    auto loadStage = [&](int k016, int buf) {
        int half = tid >> 7;
        int idx = tid & 127;
        Af[buf][tid] = wfrag[((size_t)(cbBase + half) * nk + k016) * 128 + idx];
        int k2 = tid >> 5, p2i = tid & 31;
        if constexpr (INKIND == 0) {
            int k0 = k016 * 16;
            const float* r0 = inF + (size_t)(k0 + 2 * k2) * HW + p2i * 4;
            float4 v0 = *(const float4*)r0;
            float4 v1 = *(const float4*)(r0 + HW);
            uint4 o;
            o.x = packh2(v0.x, v1.x);
            o.y = packh2(v0.y, v1.y);
            o.z = packh2(v0.z, v1.z);
            o.w = packh2(v0.w, v1.w);
            *(uint4*)&Ish[buf][k2][p2i * 4] = o;
        } else {
            const uint32_t* r0 = inP + (size_t)(k016 * 8 + k2) * HW + p2i * 4;
            *(uint4*)&Ish[buf][k2][p2i * 4] = *(const uint4*)r0;
        }
    };

    loadStage(0, 0);
    for (int k016 = 0; k016 < nk; k016++) {
        __syncthreads();
        if (k016 + 1 < nk) loadStage(k016 + 1, (k016 + 1) & 1);
        int buf = k016 & 1;
        uint4 af[4];
#pragma unroll
        for (int mi2 = 0; mi2 < 4; mi2++)
            af[mi2] = Af[buf][(mi2 >> 1) * 128 + (w2 * 2 + (mi2 & 1)) * 32 + lane];
#pragma unroll
        for (int ni = 0; ni < 4; ni++) {
            uint32_t b0 = Ish[buf][t][wn + ni * 8 + g];
            uint32_t b1 = Ish[buf][t + 4][wn + ni * 8 + g];
#pragma unroll
            for (int mi2 = 0; mi2 < 4; mi2++)
                mma_fp16(acc[mi2][ni][0], acc[mi2][ni][1], acc[mi2][ni][2], acc[mi2][ni][3],
                         af[mi2].x, af[mi2].y, af[mi2].z, af[mi2].w, b0, b1);
        }
    }
    // epilogue
#pragma unroll
    for (int mi2 = 0; mi2 < 4; mi2++) {
        int co0 = (cbBase + (mi2 >> 1)) * 64 + w2 * 32 + (mi2 & 1) * 16 + g;
        int co1 = co0 + 8;
        float b0v = 0.f, b1v = 0.f, sc0 = 0.f, sc1 = 0.f, sh0 = 0.f, sh1 = 0.f;
        if (MODE == 0) {
            b0v = p0[co0];
            b1v = p0[co1];
        } else {
            sc0 = p0[co0] * rsqrtf(p3[co0] + 1e-5f);
            sh0 = p1[co0] - p2[co0] * sc0;
            sc1 = p0[co1] * rsqrtf(p3[co1] + 1e-5f);
            sh1 = p1[co1] - p2[co1] * sc1;
        }
        size_t row0 = ((size_t)b * Cout + co0) * HW + nbase;
        size_t row1 = ((size_t)b * Cout + co1) * HW + nbase;
#pragma unroll
        for (int ni = 0; ni < 4; ni++) {
            int x0 = wn + ni * 8 + 2 * t;
            float v00 = acc[mi2][ni][0], v01 = acc[mi2][ni][1];
            float v10 = acc[mi2][ni][2], v11 = acc[mi2][ni][3];
            if (MODE == 0) {
                v00 = hswish_f(v00 + b0v);
                v01 = hswish_f(v01 + b0v);
                v10 = hswish_f(v10 + b1v);
                v11 = hswish_f(v11 + b1v);
            } else {
                float2 r0 = *(const float2*)&res[row0 + x0];
                float2 r1 = *(const float2*)&res[row1 + x0];
                v00 = v00 * sc0 + sh0 + r0.x;
                v01 = v01 * sc0 + sh0 + r0.y;
                v10 = v10 * sc1 + sh1 + r1.x;
                v11 = v11 * sc1 + sh1 + r1.y;
            }
            if constexpr (sizeof(TO) == 4) {
                *(float2*)&((float*)out)[row0 + x0] = make_float2(v00, v01);
                *(float2*)&((float*)out)[row1 + x0] = make_float2(v10, v11);
            } else {
                *(__half2*)&((__half*)out)[row0 + x0] = __floats2half2_rn(v00, v01);
                *(__half2*)&((__half*)out)[row1 + x0] = __floats2half2_rn(v10, v11);
            }
        }
    }
}

// ---------------- 5x5 depthwise, 8 rows per block (fp16 io) ----------------
__global__ void dw5x5_k(const __half* __restrict__ in, const float* __restrict__ wgt,
                        __half* __restrict__ out) {
    __shared__ float sh[12][136];
    int tid = threadIdx.x;
    int warp = tid >> 5, lane = tid & 31;
    int y0 = blockIdx.x * 8;
    int c = blockIdx.y;
    int b = blockIdx.z;
    const __half* inC = in + ((size_t)b * 768 + c) * HW;
    for (int rr = warp; rr < 12; rr += 8) {
        int yy = y0 - 2 + rr;
        for (int col = lane; col < 132; col += 32) {
            int xx = col - 2;
            float v = 0.f;
            if (yy >= 0 && yy < HH && xx >= 0 && xx < WW) v = __half2float(inC[yy * WW + xx]);
            sh[rr][col] = v;
        }
    }
    __syncthreads();
    float wreg[25];
#pragma unroll
    for (int i = 0; i < 25; i++) wreg[i] = wgt[c * 25 + i];
    __half* oC = out + ((size_t)b * 384 + c) * HW;
#pragma unroll
    for (int p = 0; p < 4; p++) {
        int px = tid + p * 256;
        int ry = px >> 7, x = px & 127;
        float a = 0.f;
#pragma unroll
        for (int r = 0; r < 5; r++)
#pragma unroll
            for (int s = 0; s < 5; s++)
                a += wreg[r * 5 + s] * sh[ry + r][x + s];
        oC[(y0 + ry) * WW + x] = __float2half(a);
    }
}

// ---------------- grouped 1x1, 8->8 per group, 2 pixels/thread (half2 io) ----------------
__global__ void pw_group_k(const uint32_t* __restrict__ in, const float* __restrict__ wgt,
                           uint32_t* __restrict__ out) {
    __shared__ float wsh[64];
    int g = blockIdx.y;
    int b = blockIdx.z;
    if (threadIdx.x < 64) wsh[threadIdx.x] = wgt[g * 64 + threadIdx.x];
    __syncthreads();
    int n2 = blockIdx.x * 256 + threadIdx.x;    // half2 index over HW/2
    const uint32_t* ip = in + ((size_t)b * 384 + g * 8) * (HW / 2) + n2;
    float2 xi[8];
#pragma unroll
    for (int i = 0; i < 8; i++) {
        __half2 h = *(const __half2*)&ip[(size_t)i * (HW / 2)];
        xi[i] = __half22float2(h);
    }
    uint32_t* op = out + ((size_t)b * 768 + 384 + g * 8) * (HW / 2) + n2;
#pragma unroll
    for (int o = 0; o < 8; o++) {
        float a0 = 0.f, a1 = 0.f;
#pragma unroll
        for (int i = 0; i < 8; i++) {
            a0 += wsh[o * 8 + i] * xi[i].x;
            a1 += wsh[o * 8 + i] * xi[i].y;
        }
        op[(size_t)o * (HW / 2)] = packh2(a0, a1);
    }
}

// ---------------- zero kv accumulators ----------------
__global__ void zero_kv_k(float* __restrict__ kv) {
    int i = blockIdx.x * 256 + threadIdx.x;
    if (i < BB * 32 * 72) kv[i] = 0.f;
}

// ---------------- attention phase 1: half2 loads, grid.x=2 (amortized tail) ----------------
__global__ void attn_kv_k(const __half* __restrict__ multi, float* __restrict__ kv) {
    int b = blockIdx.z, g = blockIdx.y;
    const __half* base = multi + ((size_t)b * 768 + g * 24) * HW;
    int n0 = blockIdx.x * 8192;
    float acc[72];
#pragma unroll
    for (int i = 0; i < 72; i++) acc[i] = 0.f;
    for (int n = n0 + 2 * threadIdx.x; n < n0 + 8192; n += 512) {
        float2 kq[8], vv[8];
#pragma unroll
        for (int j = 0; j < 8; j++) {
            __half2 h = *(const __half2*)&base[(size_t)(8 + j) * HW + n];
            float2 f = __half22float2(h);
            kq[j].x = fmaxf(f.x, 0.f);
            kq[j].y = fmaxf(f.y, 0.f);
        }
#pragma unroll
        for (int e = 0; e < 8; e++) {
            __half2 h = *(const __half2*)&base[(size_t)(16 + e) * HW + n];
            vv[e] = __half22float2(h);
        }
#pragma unroll
        for (int e = 0; e < 8; e++)
#pragma unroll
            for (int j = 0; j < 8; j++)
                acc[e * 8 + j] += vv[e].x * kq[j].x + vv[e].y * kq[j].y;
#pragma unroll
        for (int j = 0; j < 8; j++) acc[64 + j] += kq[j].x + kq[j].y;
    }
    __shared__ float red[72][8];
    int lane = threadIdx.x & 31, warp = threadIdx.x >> 5;
#pragma unroll
    for (int i = 0; i < 72; i++) {
        float v = acc[i];
        v += __shfl_down_sync(0xffffffffu, v, 16);
        v += __shfl_down_sync(0xffffffffu, v, 8);
        v += __shfl_down_sync(0xffffffffu, v, 4);
        v += __shfl_down_sync(0xffffffffu, v, 2);
        v += __shfl_down_sync(0xffffffffu, v, 1);
        if (lane == 0) red[i][warp] = v;
    }
    __syncthreads();
    if (threadIdx.x < 72) {
        float s = 0.f;
#pragma unroll
        for (int w = 0; w < 8; w++) s += red[threadIdx.x][w];
        atomicAdd(&kv[((size_t)b * 32 + g) * 72 + threadIdx.x], s);
    }
}

// ---------------- attention phase 2: 2 pixels/thread, half2-pair out ----------------
__global__ void attn_apply_k(const __half* __restrict__ multi, const float* __restrict__ kv,
                             uint32_t* __restrict__ attI) {
    int b = blockIdx.z, g = blockIdx.y;
    __shared__ float kvs[72];
    if (threadIdx.x < 72) kvs[threadIdx.x] = kv[((size_t)b * 32 + g) * 72 + threadIdx.x];
    __syncthreads();
    int n = (blockIdx.x * 256 + threadIdx.x) * 2;
    const __half* base = multi + ((size_t)b * 768 + g * 24) * HW + n;
    float2 q[8];
#pragma unroll
    for (int j = 0; j < 8; j++) {
        __half2 h = *(const __half2*)&base[(size_t)j * HW];
        float2 f = __half22float2(h);
        q[j].x = fmaxf(f.x, 0.f);
        q[j].y = fmaxf(f.y, 0.f);
    }
    float d0 = 0.f, d1 = 0.f;
#pragma unroll
    for (int j = 0; j < 8; j++) {
        d0 += kvs[64 + j] * q[j].x;
        d1 += kvs[64 + j] * q[j].y;
    }
    float inv0 = 1.f / (d0 + 1e-15f);
    float inv1 = 1.f / (d1 + 1e-15f);
    uint32_t* op = attI + ((size_t)b * 128 + g * 4) * HW + n;
#pragma unroll
    for (int e2 = 0; e2 < 4; e2++) {
        float sa0 = 0.f, sb0 = 0.f, sa1 = 0.f, sb1 = 0.f;
#pragma unroll
        for (int j = 0; j < 8; j++) {
            float ka = kvs[(2 * e2) * 8 + j], kb = kvs[(2 * e2 + 1) * 8 + j];
            sa0 += ka * q[j].x;
            sb0 += kb * q[j].x;
            sa1 += ka * q[j].y;
            sb1 += kb * q[j].y;
        }
        uint2 o;
        o.x = packh2(sa0 * inv0, sb0 * inv0);
        o.y = packh2(sa1 * inv1, sb1 * inv1);
        *(uint2*)&op[(size_t)e2 * HW] = o;
    }
}

// ---------------- 3x3 dw + bias + hswish, channel PAIR per block, half2 out ----------------
__global__ void dw3x3_k(const __half* __restrict__ in, const float* __restrict__ wgt,
                        const float* __restrict__ bias, uint32_t* __restrict__ outI) {
    __shared__ float sh[2][10][136];
    int tid = threadIdx.x;
    int warp = tid >> 5, lane = tid & 31;
    int y0 = blockIdx.x * 8;
    int cp = blockIdx.y;
    int b = blockIdx.z;
    const __half* inC = in + ((size_t)b * 768 + 2 * cp) * HW;
    for (int rr = warp; rr < 20; rr += 8) {
        int ch = rr / 10, row = rr % 10;
        int yy = y0 - 1 + row;
        const __half* ip = inC + (size_t)ch * HW;
        for (int col = lane; col < 130; col += 32) {
            int xx = col - 1;
            float v = 0.f;
            if (yy >= 0 && yy < HH && xx >= 0 && xx < WW) v = __half2float(ip[yy * WW + xx]);
            sh[ch][row][col] = v;
        }
    }
    __syncthreads();
    float w0[9], w1[9];
#pragma unroll
    for (int i = 0; i < 9; i++) {
        w0[i] = wgt[(2 * cp) * 9 + i];
        w1[i] = wgt[(2 * cp + 1) * 9 + i];
    }
    float bv0 = bias[2 * cp], bv1 = bias[2 * cp + 1];
    uint32_t* oC = outI + ((size_t)b * 384 + cp) * HW;
#pragma unroll
    for (int p = 0; p < 4; p++) {
        int px = tid + p * 256;
        int ry = px >> 7, x = px & 127;
        float a0 = bv0, a1 = bv1;
#pragma unroll
        for (int r = 0; r < 3; r++)
#pragma unroll
            for (int s = 0; s < 3; s++) {
                a0 += w0[r * 3 + s] * sh[0][ry + r][x + s];
                a1 += w1[r * 3 + s] * sh[1][ry + r][x + s];
            }
        oC[(y0 + ry) * WW + x] = packh2(hswish_f(a0), hswish_f(a1));
    }
}

// ---------------- launch ----------------
extern "C" void kernel_launch(void* const* d_in, const int* in_sizes, int n_in,
                              void* d_out, int out_size) {
    const float* ref = (const float*)d_in[0];
    const float* oth = (const float*)d_in[1];
    const float* wq = (const float*)d_in[2];
    const float* bq = (const float*)d_in[3];
    const float* wk = (const float*)d_in[4];
    const float* bk = (const float*)d_in[5];
    const float* wv = (const float*)d_in[6];
    const float* bv = (const float*)d_in[7];
    const float* agg_dw_w = (const float*)d_in[8];
    const float* agg_pw_w = (const float*)d_in[9];
    const float* attn_proj_w = (const float*)d_in[10];
    const float* bn1_g = (const float*)d_in[11];
    const float* bn1_b = (const float*)d_in[12];
    const float* bn1_m = (const float*)d_in[13];
    const float* bn1_v = (const float*)d_in[14];
    const float* mb1_w = (const float*)d_in[15];
    const float* mb1_b = (const float*)d_in[16];
    const float* mb2_w = (const float*)d_in[17];
    const float* mb2_b = (const float*)d_in[18];
    const float* mb3_w = (const float*)d_in[19];
    const float* bn2_g = (const float*)d_in[20];
    const float* bn2_b = (const float*)d_in[21];
    const float* bn2_m = (const float*)d_in[22];
    const float* bn2_v = (const float*)d_in[23];

    __half *multi, *msdw, *h1;
    uint32_t *atti, *h2i, *refi, *othi;
    float *attended, *kv, *wT;
    cudaGetSymbolAddress((void**)&multi, g_multi);
    cudaGetSymbolAddress((void**)&msdw, g_msdw);
    cudaGetSymbolAddress((void**)&atti, g_atti);
    cudaGetSymbolAddress((void**)&attended, g_attended);
    cudaGetSymbolAddress((void**)&h1, g_h1);
    cudaGetSymbolAddress((void**)&h2i, g_h2i);
    cudaGetSymbolAddress((void**)&kv, g_kv);
    cudaGetSymbolAddress((void**)&wT, g_wT);
    cudaGetSymbolAddress((void**)&refi, g_refi);
    cudaGetSymbolAddress((void**)&othi, g_othi);
    uint4* fr4 = (uint4*)wT;

    static bool attr_set = false;
    if (!attr_set) {
        cudaFuncSetAttribute(conv3x3_tc, cudaFuncAttributeMaxDynamicSharedMemorySize,
                             CONV_SMEM);
        attr_set = true;
    }

    // prep: interleave inputs + weight fragment packing
    prep_interleave<<<BB * 64 * HW / 256, 256>>>(ref, oth, refi, othi);
    prep_conv_frag_h3<<<dim3(72, 3), 256>>>(wq, wk, wv, fr4 + FQ);
    prep_gemm_frag_h<<<16, 256>>>(attn_proj_w, fr4 + FP, 256, 128);
    prep_gemm_frag_h<<<48, 256>>>(mb1_w, fr4 + F1, 128, 768);
    prep_gemm_frag_h<<<48, 256>>>(mb3_w, fr4 + F3, 768, 128);

    // fused q,k,v 3x3 convs (M=128/block, pipelined) -> multi channels 0/128/256
    conv3x3_tc<<<dim3(128, 3, 4), 256, CONV_SMEM>>>(refi, othi, fr4 + FQ, bq, bk, bv, multi);

    // aggregation: 5x5 dw (8 rows/block) then grouped 1x1 -> multi channels 384..767
    dw5x5_k<<<dim3(16, 384, 4), 256>>>(multi, agg_dw_w, msdw);
    pw_group_k<<<dim3(32, 48, 4), 256>>>((const uint32_t*)msdw, agg_pw_w, (uint32_t*)multi);

    // relu linear attention (fp16 io, fp32 accum)
    zero_kv_k<<<(BB * 32 * 72 + 255) / 256, 256>>>(kv);
    attn_kv_k<<<dim3(2, 32, 4), 256>>>(multi, kv);
    attn_apply_k<<<dim3(32, 32, 4), 256>>>(multi, kv, atti);

    // attn_proj + bn1 + residual(ref fp32) -> attended (fp32)
    gemm1x1_tc<1, 2, float><<<dim3(128, 1, 4), 256>>>(
        atti, 256, fr4 + FP, 128, bn1_g, bn1_b, bn1_m, bn1_v, ref, attended);

    // MBConv
    gemm1x1_tc<0, 0, __half><<<dim3(128, 6, 4), 256>>>(
        attended, 128, fr4 + F1, 768, mb1_b, nullptr, nullptr, nullptr, nullptr, h1);
    dw3x3_k<<<dim3(16, 384, 4), 256>>>(h1, mb2_w, mb2_b, h2i);
    gemm1x1_tc<1, 2, float><<<dim3(128, 1, 4), 256>>>(
        h2i, 768, fr4 + F3, 128, bn2_g, bn2_b, bn2_m, bn2_v, attended, (float*)d_out);
}